// round 1
// baseline (speedup 1.0000x reference)
#include <cuda_runtime.h>
#include <cuda_bf16.h>
#include <math.h>

// ---------------------------------------------------------------------------
// Problem constants
// ---------------------------------------------------------------------------
#define Bc    2
#define Sc    2048
#define HIDc  4096
#define Hc    32
#define KVc   8
#define Dc    128
#define Wc    512
#define BSc   (Bc * Sc)          // 4096
#define QKVF  ((Hc + 2 * KVc) * Dc)  // 6144

// ---------------------------------------------------------------------------
// Scratch (static device globals -- no allocation allowed)
// ---------------------------------------------------------------------------
__device__ float g_qkv[(size_t)BSc * QKVF];      // packed qkv projection
__device__ float g_q  [(size_t)BSc * Hc * Dc];   // roped Q
__device__ float g_k  [(size_t)BSc * KVc * Dc];  // smoothed+roped K
__device__ float g_v  [(size_t)BSc * KVc * Dc];  // smoothed V
__device__ float g_attn[(size_t)BSc * Hc * Dc];  // attention output

// ---------------------------------------------------------------------------
// f32x2 packed FMA helpers (Blackwell FFMA2 path; ~2x fp32 throughput)
// ---------------------------------------------------------------------------
__device__ __forceinline__ unsigned long long fma2(unsigned long long a,
                                                   unsigned long long b,
                                                   unsigned long long c) {
    unsigned long long d;
    asm("fma.rn.f32x2 %0, %1, %2, %3;" : "=l"(d) : "l"(a), "l"(b), "l"(c));
    return d;
}
__device__ __forceinline__ float2 unpack2(unsigned long long v) {
    float2 r;
    asm("mov.b64 {%0, %1}, %2;" : "=f"(r.x), "=f"(r.y) : "l"(v));
    return r;
}

// ---------------------------------------------------------------------------
// SGEMM: C[M,N] = A[M,K] * B[K,N], all row-major, M%128==0, N%128==0, K%16==0
// 128x128 block tile, 16 K-slice, 256 threads, 8x8 micro tile, FFMA2 inner.
// A is stored to shared as duplicated float2 (a,a) so the packed multiplier
// needs no per-iteration duplication movs.
// ---------------------------------------------------------------------------
#define BM 128
#define BN 128
#define BK 16

__global__ __launch_bounds__(256, 2)
void sgemm_f32x2(const float* __restrict__ A, const float* __restrict__ B,
                 float* __restrict__ C, int M, int N, int K)
{
    __shared__ float2 As[BK][BM + 2];   // duplicated pairs
    __shared__ float  Bs[BK][BN];

    const int tid = threadIdx.x;
    const int bm = blockIdx.y, bn = blockIdx.x;
    const int tx = tid & 15, ty = tid >> 4;

    // A tile load mapping: 128 rows x 16 cols = 512 float4; 2 per thread
    const int ar0 = tid >> 2;           // row of first float4
    const int ac0 = (tid & 3) * 4;      // col of first float4
    // B tile load mapping: 16 rows x 128 cols = 512 float4; 2 per thread
    const int br0 = tid >> 5;
    const int bc0 = (tid & 31) * 4;

    const float* Aptr = A + (size_t)(bm * BM) * K;
    const float* Bptr = B + (size_t)(bn * BN);

    float4 a0, a1, b0, b1;

    // prefetch tile 0
    a0 = *(const float4*)(Aptr + (size_t)ar0 * K + ac0);
    a1 = *(const float4*)(Aptr + (size_t)(ar0 + 64) * K + ac0);
    b0 = *(const float4*)(Bptr + (size_t)br0 * N + bc0);
    b1 = *(const float4*)(Bptr + (size_t)(br0 + 8) * N + bc0);

    unsigned long long acc[8][4];
#pragma unroll
    for (int i = 0; i < 8; i++)
#pragma unroll
        for (int p = 0; p < 4; p++) acc[i][p] = 0ull;

    // store tile 0
    As[ac0 + 0][ar0]      = make_float2(a0.x, a0.x);
    As[ac0 + 1][ar0]      = make_float2(a0.y, a0.y);
    As[ac0 + 2][ar0]      = make_float2(a0.z, a0.z);
    As[ac0 + 3][ar0]      = make_float2(a0.w, a0.w);
    As[ac0 + 0][ar0 + 64] = make_float2(a1.x, a1.x);
    As[ac0 + 1][ar0 + 64] = make_float2(a1.y, a1.y);
    As[ac0 + 2][ar0 + 64] = make_float2(a1.z, a1.z);
    As[ac0 + 3][ar0 + 64] = make_float2(a1.w, a1.w);
    *(float4*)&Bs[br0][bc0]     = b0;
    *(float4*)&Bs[br0 + 8][bc0] = b1;
    __syncthreads();

    const int a_off = ty * 8;
    const int b_off = tx * 8;

    for (int k0 = BK; k0 <= K - BK; k0 += BK) {
        // prefetch next tile into registers
        a0 = *(const float4*)(Aptr + (size_t)ar0 * K + k0 + ac0);
        a1 = *(const float4*)(Aptr + (size_t)(ar0 + 64) * K + k0 + ac0);
        b0 = *(const float4*)(Bptr + (size_t)(k0 + br0) * N + bc0);
        b1 = *(const float4*)(Bptr + (size_t)(k0 + br0 + 8) * N + bc0);

        // compute on current shared tile
#pragma unroll
        for (int k = 0; k < BK; k++) {
            unsigned long long ar[8];
#pragma unroll
            for (int i = 0; i < 8; i++)
                ar[i] = *(const unsigned long long*)&As[k][a_off + i];
            ulonglong2 bA = *(const ulonglong2*)&Bs[k][b_off];
            ulonglong2 bB = *(const ulonglong2*)&Bs[k][b_off + 4];
#pragma unroll
            for (int i = 0; i < 8; i++) {
                acc[i][0] = fma2(ar[i], bA.x, acc[i][0]);
                acc[i][1] = fma2(ar[i], bA.y, acc[i][1]);
                acc[i][2] = fma2(ar[i], bB.x, acc[i][2]);
                acc[i][3] = fma2(ar[i], bB.y, acc[i][3]);
            }
        }
        __syncthreads();

        As[ac0 + 0][ar0]      = make_float2(a0.x, a0.x);
        As[ac0 + 1][ar0]      = make_float2(a0.y, a0.y);
        As[ac0 + 2][ar0]      = make_float2(a0.z, a0.z);
        As[ac0 + 3][ar0]      = make_float2(a0.w, a0.w);
        As[ac0 + 0][ar0 + 64] = make_float2(a1.x, a1.x);
        As[ac0 + 1][ar0 + 64] = make_float2(a1.y, a1.y);
        As[ac0 + 2][ar0 + 64] = make_float2(a1.z, a1.z);
        As[ac0 + 3][ar0 + 64] = make_float2(a1.w, a1.w);
        *(float4*)&Bs[br0][bc0]     = b0;
        *(float4*)&Bs[br0 + 8][bc0] = b1;
        __syncthreads();
    }

    // last tile compute
#pragma unroll
    for (int k = 0; k < BK; k++) {
        unsigned long long ar[8];
#pragma unroll
        for (int i = 0; i < 8; i++)
            ar[i] = *(const unsigned long long*)&As[k][a_off + i];
        ulonglong2 bA = *(const ulonglong2*)&Bs[k][b_off];
        ulonglong2 bB = *(const ulonglong2*)&Bs[k][b_off + 4];
#pragma unroll
        for (int i = 0; i < 8; i++) {
            acc[i][0] = fma2(ar[i], bA.x, acc[i][0]);
            acc[i][1] = fma2(ar[i], bA.y, acc[i][1]);
            acc[i][2] = fma2(ar[i], bB.x, acc[i][2]);
            acc[i][3] = fma2(ar[i], bB.y, acc[i][3]);
        }
    }

    // write back
    const int crow = bm * BM + ty * 8;
    const int ccol = bn * BN + tx * 8;
#pragma unroll
    for (int i = 0; i < 8; i++) {
        float* cp = C + (size_t)(crow + i) * N + ccol;
        float2 v0 = unpack2(acc[i][0]);
        float2 v1 = unpack2(acc[i][1]);
        float2 v2 = unpack2(acc[i][2]);
        float2 v3 = unpack2(acc[i][3]);
        float4 w0 = make_float4(v0.x, v0.y, v1.x, v1.y);
        float4 w1 = make_float4(v2.x, v2.y, v3.x, v3.y);
        *(float4*)(cp)     = w0;
        *(float4*)(cp + 4) = w1;
    }
}

// ---------------------------------------------------------------------------
// RoPE for Q (reads qkv, writes g_q)
// ---------------------------------------------------------------------------
__global__ void rope_q_kernel(const float* __restrict__ qkv,
                              const int* __restrict__ positions,
                              float* __restrict__ Qg)
{
    int idx = blockIdx.x * blockDim.x + threadIdx.x;   // BS*H*64
    int i  = idx & 63;
    int h  = (idx >> 6) & 31;
    int bs = idx >> 11;
    if (bs >= BSc) return;

    const float* src = qkv + (size_t)bs * QKVF + h * Dc;
    float x1 = src[i], x2 = src[i + 64];
    float pos = (float)positions[bs];
    float inv = 1.0f / powf(10000.0f, (float)i * (1.0f / 64.0f));
    float ang = pos * inv;
    float sn, cs;
    sincosf(ang, &sn, &cs);
    float* dst = Qg + (size_t)bs * (Hc * Dc) + h * Dc;
    dst[i]      = x1 * cs - x2 * sn;
    dst[i + 64] = x2 * cs + x1 * sn;
}

// ---------------------------------------------------------------------------
// Smooth conv + RoPE for K (reads qkv, writes g_k)
// ---------------------------------------------------------------------------
__global__ void smooth_rope_k_kernel(const float* __restrict__ qkv,
                                     const int* __restrict__ positions,
                                     const float* __restrict__ conv_k,
                                     float* __restrict__ Kg)
{
    int idx = blockIdx.x * blockDim.x + threadIdx.x;   // BS*KV*64
    int i  = idx & 63;
    int kv = (idx >> 6) & 7;
    int bs = idx >> 9;
    if (bs >= BSc) return;
    int s = bs & (Sc - 1);

    const float* src = qkv + (size_t)bs * QKVF + Hc * Dc + kv * Dc;
    float c1 = src[i], c2 = src[i + 64];
    float p1 = 0.f, p2 = 0.f;
    if (s > 0) {
        const float* ps = src - QKVF;
        p1 = ps[i]; p2 = ps[i + 64];
    }
    float f0 = conv_k[kv], f1 = conv_k[KVc + kv];
    float x1 = c1 * f1 + p1 * f0;
    float x2 = c2 * f1 + p2 * f0;

    float pos = (float)positions[bs];
    float inv = 1.0f / powf(10000.0f, (float)i * (1.0f / 64.0f));
    float ang = pos * inv;
    float sn, cs;
    sincosf(ang, &sn, &cs);
    float* dst = Kg + ((size_t)bs * KVc + kv) * Dc;
    dst[i]      = x1 * cs - x2 * sn;
    dst[i + 64] = x2 * cs + x1 * sn;
}

// ---------------------------------------------------------------------------
// Smooth conv for V (reads qkv, writes g_v)
// ---------------------------------------------------------------------------
__global__ void smooth_v_kernel(const float* __restrict__ qkv,
                                const float* __restrict__ conv_v,
                                float* __restrict__ Vg)
{
    int idx = blockIdx.x * blockDim.x + threadIdx.x;   // BS*KV*128
    int d  = idx & 127;
    int kv = (idx >> 7) & 7;
    int bs = idx >> 10;
    if (bs >= BSc) return;
    int s = bs & (Sc - 1);

    const float* src = qkv + (size_t)bs * QKVF + (Hc + KVc) * Dc + kv * Dc;
    float c = src[d];
    float p = (s > 0) ? src[d - QKVF] : 0.f;
    float f0 = conv_v[kv], f1 = conv_v[KVc + kv];
    Vg[((size_t)bs * KVc + kv) * Dc + d] = c * f1 + p * f0;
}

// ---------------------------------------------------------------------------
// Windowed flash attention. One CTA per (b, h, 64-query tile). 256 threads.
// K tiles of 64 keys; online softmax; window = 512, causal.
// ---------------------------------------------------------------------------
#define QS_STRIDE 132
#define KT_STRIDE 68
#define SS_STRIDE 65
#define ATTN_SMEM_FLOATS (64*QS_STRIDE + 128*KT_STRIDE + 64*128 + 64*SS_STRIDE + 64*3 + 256)
#define ATTN_SMEM_BYTES  (ATTN_SMEM_FLOATS * 4)

__global__ __launch_bounds__(256)
void attn_kernel(const float* __restrict__ Qg, const float* __restrict__ Kg,
                 const float* __restrict__ Vg, float* __restrict__ Og)
{
    extern __shared__ float sm[];
    float* Qs   = sm;                        // 64 x 132
    float* Kt   = Qs + 64 * QS_STRIDE;       // 128 x 68 (transposed)
    float* Vs   = Kt + 128 * KT_STRIDE;      // 64 x 128
    float* Ss   = Vs + 64 * 128;             // 64 x 65
    float* mrow = Ss + 64 * SS_STRIDE;       // 64
    float* lrow = mrow + 64;                 // 64
    float* frow = lrow + 64;                 // 64
    float* red  = frow + 64;                 // 64 x 4

    const int tid = threadIdx.x;
    const int qt = blockIdx.x, h = blockIdx.y, b = blockIdx.z;
    const int q0 = qt * 64;
    const int kvh = h >> 2;                  // H/KV = 4

    // load Q tile
    for (int idx = tid; idx < 64 * 128; idx += 256) {
        int r = idx >> 7, d = idx & 127;
        Qs[r * QS_STRIDE + d] =
            Qg[(((size_t)(b * Sc + q0 + r)) * Hc + h) * Dc + d];
    }
    if (tid < 64) { mrow[tid] = -1e30f; lrow[tid] = 0.f; }

    const int pr = tid & 63;                 // PV row
    const int pc = (tid >> 6) * 32;          // PV col segment
    float o[32];
#pragma unroll
    for (int j = 0; j < 32; j++) o[j] = 0.f;

    const int tx = tid & 15, ty = tid >> 4;
    const int r0 = ty * 4, c0 = tx * 4;
    const float scale = 0.08838834764831845f;   // 1/sqrt(128)

    int kt_lo = qt - 8; if (kt_lo < 0) kt_lo = 0;
    __syncthreads();

    for (int kt = kt_lo; kt <= qt; kt++) {
        const int k0 = kt * 64;
        for (int idx = tid; idx < 64 * 128; idx += 256) {
            int c = idx >> 7, d = idx & 127;
            size_t base = (((size_t)(b * Sc + k0 + c)) * KVc + kvh) * Dc + d;
            Kt[d * KT_STRIDE + c] = Kg[base];
            Vs[c * 128 + d]       = Vg[base];
        }
        __syncthreads();

        // ---- scores: 4x4 micro tile per thread ----
        float sc[4][4];
#pragma unroll
        for (int i = 0; i < 4; i++)
#pragma unroll
            for (int j = 0; j < 4; j++) sc[i][j] = 0.f;

        for (int d = 0; d < 128; d++) {
            float4 kv4 = *(const float4*)&Kt[d * KT_STRIDE + c0];
#pragma unroll
            for (int i = 0; i < 4; i++) {
                float qv = Qs[(r0 + i) * QS_STRIDE + d];
                sc[i][0] += qv * kv4.x;
                sc[i][1] += qv * kv4.y;
                sc[i][2] += qv * kv4.z;
                sc[i][3] += qv * kv4.w;
            }
        }
#pragma unroll
        for (int i = 0; i < 4; i++) {
            int qi = q0 + r0 + i;
#pragma unroll
            for (int j = 0; j < 4; j++) {
                int ki = k0 + c0 + j;
                bool ok = (ki <= qi) && (qi - ki < Wc);
                Ss[(r0 + i) * SS_STRIDE + c0 + j] = ok ? sc[i][j] * scale : -1e30f;
            }
        }
        __syncthreads();

        // ---- row max (partial) ----
        {
            int rr = tid >> 2, seg = (tid & 3) * 16;
            float mx = -1e30f;
#pragma unroll
            for (int j = 0; j < 16; j++)
                mx = fmaxf(mx, Ss[rr * SS_STRIDE + seg + j]);
            red[(tid >> 2) * 4 + (tid & 3)] = mx;
        }
        __syncthreads();
        if (tid < 64) {
            float tm = fmaxf(fmaxf(red[tid * 4], red[tid * 4 + 1]),
                             fmaxf(red[tid * 4 + 2], red[tid * 4 + 3]));
            float mo = mrow[tid];
            float mn = fmaxf(mo, tm);
            mrow[tid] = mn;
            frow[tid] = __expf(mo - mn);
        }
        __syncthreads();

        // ---- exp + partial sums ----
        {
            int rr = tid >> 2, seg = (tid & 3) * 16;
            float mn = mrow[rr];
            float s = 0.f;
#pragma unroll
            for (int j = 0; j < 16; j++) {
                float vv = Ss[rr * SS_STRIDE + seg + j];
                float p = (vv > -1e29f) ? __expf(vv - mn) : 0.f;
                Ss[rr * SS_STRIDE + seg + j] = p;
                s += p;
            }
            red[(tid >> 2) * 4 + (tid & 3)] = s;
        }
        __syncthreads();
        if (tid < 64) {
            lrow[tid] = lrow[tid] * frow[tid] +
                        red[tid * 4] + red[tid * 4 + 1] +
                        red[tid * 4 + 2] + red[tid * 4 + 3];
        }

        // ---- PV accumulate (concurrent with lrow update; no shared conflict) ----
        {
            float f = frow[pr];
#pragma unroll
            for (int j = 0; j < 32; j++) o[j] *= f;
            for (int k = 0; k < 64; k++) {
                float p = Ss[pr * SS_STRIDE + k];
                const float4* vp = (const float4*)&Vs[k * 128 + pc];
#pragma unroll
                for (int j4 = 0; j4 < 8; j4++) {
                    float4 vv = vp[j4];
                    o[j4 * 4 + 0] += p * vv.x;
                    o[j4 * 4 + 1] += p * vv.y;
                    o[j4 * 4 + 2] += p * vv.z;
                    o[j4 * 4 + 3] += p * vv.w;
                }
            }
        }
        __syncthreads();
    }

    float linv = 1.0f / lrow[pr];
    size_t ob = ((size_t)(b * Sc + q0 + pr)) * (Hc * Dc) + h * Dc + pc;
#pragma unroll
    for (int j4 = 0; j4 < 8; j4++) {
        float4 w = make_float4(o[j4 * 4 + 0] * linv, o[j4 * 4 + 1] * linv,
                               o[j4 * 4 + 2] * linv, o[j4 * 4 + 3] * linv);
        *(float4*)&Og[ob + j4 * 4] = w;
    }
}

// ---------------------------------------------------------------------------
// Launch
// ---------------------------------------------------------------------------
extern "C" void kernel_launch(void* const* d_in, const int* in_sizes, int n_in,
                              void* d_out, int out_size)
{
    const float* hidden    = (const float*)d_in[0];
    const int*   positions = (const int*)d_in[1];
    const float* w_pack    = (const float*)d_in[2];
    const float* w_o       = (const float*)d_in[3];
    const float* conv_k    = (const float*)d_in[4];
    const float* conv_v    = (const float*)d_in[5];
    float* out = (float*)d_out;

    float *qkv, *q, *k, *v, *attn;
    cudaGetSymbolAddress((void**)&qkv,  g_qkv);
    cudaGetSymbolAddress((void**)&q,    g_q);
    cudaGetSymbolAddress((void**)&k,    g_k);
    cudaGetSymbolAddress((void**)&v,    g_v);
    cudaGetSymbolAddress((void**)&attn, g_attn);

    // 1) QKV projection: [4096,4096] x [4096,6144]
    dim3 g1(QKVF / BN, BSc / BM);
    sgemm_f32x2<<<g1, 256>>>(hidden, w_pack, qkv, BSc, QKVF, HIDc);

    // 2) elementwise prep
    rope_q_kernel<<<(BSc * Hc * 64) / 256, 256>>>(qkv, positions, q);
    smooth_rope_k_kernel<<<(BSc * KVc * 64) / 256, 256>>>(qkv, positions, conv_k, k);
    smooth_v_kernel<<<(BSc * KVc * 128) / 256, 256>>>(qkv, conv_v, v);

    // 3) windowed attention
    cudaFuncSetAttribute(attn_kernel,
                         cudaFuncAttributeMaxDynamicSharedMemorySize,
                         ATTN_SMEM_BYTES);
    attn_kernel<<<dim3(Sc / 64, Hc, Bc), 256, ATTN_SMEM_BYTES>>>(q, k, v, attn);

    // 4) output projection: [4096,4096] x [4096,4096]
    dim3 g2(HIDc / BN, BSc / BM);
    sgemm_f32x2<<<g2, 256>>>(attn, w_o, out, BSc, HIDc, HIDc);
}

// round 3
// speedup vs baseline: 2.1218x; 2.1218x over previous
#include <cuda_runtime.h>
#include <cuda_bf16.h>
#include <math.h>
#include <stdint.h>

// ---------------------------------------------------------------------------
// Problem constants
// ---------------------------------------------------------------------------
#define Bc    2
#define Sc    2048
#define HIDc  4096
#define Hc    32
#define KVc   8
#define Dc    128
#define Wc    512
#define BSc   (Bc * Sc)              // 4096
#define QKVF  ((Hc + 2 * KVc) * Dc)  // 6144

// ---------------------------------------------------------------------------
// Scratch (static device globals -- no allocation allowed)
// ---------------------------------------------------------------------------
__device__ float g_qkv[(size_t)BSc * QKVF];
__device__ float g_q  [(size_t)BSc * Hc * Dc];
__device__ float g_k  [(size_t)BSc * KVc * Dc];
__device__ float g_v  [(size_t)BSc * KVc * Dc];
__device__ float g_attn[(size_t)BSc * Hc * Dc];

// bf16 split operands for tensor-core GEMMs
__device__ __nv_bfloat16 g_ah[(size_t)BSc * HIDc];     // A hi  [M,K]
__device__ __nv_bfloat16 g_al[(size_t)BSc * HIDc];     // A lo  [M,K]
__device__ __nv_bfloat16 g_bh[(size_t)QKVF * HIDc];    // B^T hi [N,K]
__device__ __nv_bfloat16 g_bl[(size_t)QKVF * HIDc];    // B^T lo [N,K]

// ---------------------------------------------------------------------------
// Helpers
// ---------------------------------------------------------------------------
__device__ __forceinline__ uint32_t smem_u32(const void* p) {
    uint32_t a;
    asm("{ .reg .u64 t; cvta.to.shared.u64 t, %1; cvt.u32.u64 %0, t; }"
        : "=r"(a) : "l"(p));
    return a;
}
__device__ __forceinline__ void cp16(uint32_t smem, const void* gmem) {
    asm volatile("cp.async.cg.shared.global [%0], [%1], 16;"
                 :: "r"(smem), "l"(gmem));
}
#define CP_COMMIT() asm volatile("cp.async.commit_group;" ::: "memory")
#define CP_WAIT0()  asm volatile("cp.async.wait_group 0;" ::: "memory")

__device__ __forceinline__ uint32_t lds32(uint32_t addr) {
    uint32_t v;
    asm("ld.shared.b32 %0, [%1];" : "=r"(v) : "r"(addr));
    return v;
}

// bf16 HMMA m16n8k16 (sm_80 baseline; tensor pipe on sm_103)
__device__ __forceinline__ void mma16816(float* d, const uint32_t* a,
                                         const uint32_t* b) {
    asm volatile(
        "mma.sync.aligned.m16n8k16.row.col.f32.bf16.bf16.f32 "
        "{%0,%1,%2,%3}, {%4,%5,%6,%7}, {%8,%9}, {%0,%1,%2,%3};"
        : "+f"(d[0]), "+f"(d[1]), "+f"(d[2]), "+f"(d[3])
        : "r"(a[0]), "r"(a[1]), "r"(a[2]), "r"(a[3]),
          "r"(b[0]), "r"(b[1]));
}

// ---------------------------------------------------------------------------
// Split-precision HMMA GEMM:  C[M,N] = A[M,K] * B[K,N]
// Ah/Al bf16 [M,K] row-major; BhT/BlT bf16 [N,K] row-major. C fp32.
// CTA: 128x128 tile, BK=32, 8 warps (each 32x64), cp.async double buffer.
// ---------------------------------------------------------------------------
#define GBK   32
#define SROW  40                          // smem row stride in bf16 (80 B)
#define MATB  (128 * SROW * 2)            // 10240 B per matrix tile
#define STAGEB (4 * MATB)                 // 40960 B (Ah,Al,Bh,Bl)
#define GEMM_SMEM (2 * STAGEB)            // 81920 B

__global__ __launch_bounds__(256)
void gemm_mma(const __nv_bfloat16* __restrict__ Ah,
              const __nv_bfloat16* __restrict__ Al,
              const __nv_bfloat16* __restrict__ Bh,
              const __nv_bfloat16* __restrict__ Bl,
              float* __restrict__ C, int M, int N, int K)
{
    extern __shared__ char sm[];
    const uint32_t sb = smem_u32(sm);
    const int tid  = threadIdx.x;
    const int wid  = tid >> 5;
    const int lane = tid & 31;
    const int wm = wid & 3;                // warp row (0..3): 32 rows each
    const int wn = wid >> 2;               // warp col (0..1): 64 cols each
    const int g  = lane >> 2;              // group id (row within 8)
    const int tg = lane & 3;               // thread in group

    const int m0 = blockIdx.y * 128;
    const int n0 = blockIdx.x * 128;

    // ---- stage loader: 4 matrices x 128 rows x 64B each via cp.async ----
    auto load_stage = [&](int k0, int st) {
        const uint32_t base = sb + st * STAGEB;
#pragma unroll
        for (int mat = 0; mat < 4; mat++) {
            const __nv_bfloat16* src =
                (mat == 0) ? Ah : (mat == 1) ? Al : (mat == 2) ? Bh : Bl;
            const int row0 = (mat < 2) ? m0 : n0;
#pragma unroll
            for (int hh = 0; hh < 2; hh++) {
                int unit = tid + hh * 256;       // 512 units = 128 rows x 4
                int r = unit >> 2, u = unit & 3;
                const void* gp = src + (size_t)(row0 + r) * K + k0 + u * 8;
                cp16(base + mat * MATB + r * (SROW * 2) + u * 16, gp);
            }
        }
    };

    float acc[2][8][4];
#pragma unroll
    for (int mt = 0; mt < 2; mt++)
#pragma unroll
        for (int nt = 0; nt < 8; nt++)
#pragma unroll
            for (int j = 0; j < 4; j++) acc[mt][nt][j] = 0.f;

    const int NIT = K / GBK;
    load_stage(0, 0);
    CP_COMMIT();

    for (int it = 0; it < NIT; it++) {
        CP_WAIT0();
        __syncthreads();
        const int st = it & 1;
        if (it + 1 < NIT) {
            load_stage((it + 1) * GBK, st ^ 1);
            CP_COMMIT();
        }

        const uint32_t ahb = sb + st * STAGEB;
        const uint32_t alb = ahb + MATB;
        const uint32_t bhb = ahb + 2 * MATB;
        const uint32_t blb = ahb + 3 * MATB;

#pragma unroll
        for (int ks = 0; ks < 2; ks++) {
            const int c0 = ks * 16 + tg * 2;
            uint32_t ah[2][4], al[2][4];
#pragma unroll
            for (int mt = 0; mt < 2; mt++) {
                const int r0 = wm * 32 + mt * 16 + g;
                const uint32_t o00 = (uint32_t)((r0 * SROW + c0) * 2);
                const uint32_t o10 = (uint32_t)(((r0 + 8) * SROW + c0) * 2);
                ah[mt][0] = lds32(ahb + o00);
                ah[mt][1] = lds32(ahb + o10);
                ah[mt][2] = lds32(ahb + o00 + 16);
                ah[mt][3] = lds32(ahb + o10 + 16);
                al[mt][0] = lds32(alb + o00);
                al[mt][1] = lds32(alb + o10);
                al[mt][2] = lds32(alb + o00 + 16);
                al[mt][3] = lds32(alb + o10 + 16);
            }
#pragma unroll
            for (int nt = 0; nt < 8; nt++) {
                const int r0 = wn * 64 + nt * 8 + g;
                const uint32_t bo = (uint32_t)((r0 * SROW + c0) * 2);
                uint32_t bh2[2], bl2[2];
                bh2[0] = lds32(bhb + bo);
                bh2[1] = lds32(bhb + bo + 16);
                bl2[0] = lds32(blb + bo);
                bl2[1] = lds32(blb + bo + 16);
#pragma unroll
                for (int mt = 0; mt < 2; mt++) {
                    mma16816(acc[mt][nt], ah[mt], bh2);
                    mma16816(acc[mt][nt], ah[mt], bl2);
                    mma16816(acc[mt][nt], al[mt], bh2);
                }
            }
        }
    }

    // ---- epilogue: direct fp32 stores ----
#pragma unroll
    for (int mt = 0; mt < 2; mt++) {
        const int r0 = m0 + wm * 32 + mt * 16 + g;
#pragma unroll
        for (int nt = 0; nt < 8; nt++) {
            const int cc = n0 + wn * 64 + nt * 8 + tg * 2;
            float2 w0 = make_float2(acc[mt][nt][0], acc[mt][nt][1]);
            float2 w1 = make_float2(acc[mt][nt][2], acc[mt][nt][3]);
            *(float2*)(C + (size_t)r0 * N + cc)       = w0;
            *(float2*)(C + (size_t)(r0 + 8) * N + cc) = w1;
        }
    }
}

// ---------------------------------------------------------------------------
// Split fp32 -> (hi, lo) bf16, elementwise (A operands), vectorized x4
// ---------------------------------------------------------------------------
__global__ void split_a_kernel(const float* __restrict__ X,
                               __nv_bfloat16* __restrict__ Xh,
                               __nv_bfloat16* __restrict__ Xl, int n4)
{
    int i = blockIdx.x * blockDim.x + threadIdx.x;
    if (i >= n4) return;
    float4 v = ((const float4*)X)[i];
    __nv_bfloat16 h0 = __float2bfloat16(v.x);
    __nv_bfloat16 h1 = __float2bfloat16(v.y);
    __nv_bfloat16 h2 = __float2bfloat16(v.z);
    __nv_bfloat16 h3 = __float2bfloat16(v.w);
    __nv_bfloat162 hh0(h0, h1), hh1(h2, h3);
    __nv_bfloat162 ll0(__float2bfloat16(v.x - __bfloat162float(h0)),
                       __float2bfloat16(v.y - __bfloat162float(h1)));
    __nv_bfloat162 ll1(__float2bfloat16(v.z - __bfloat162float(h2)),
                       __float2bfloat16(v.w - __bfloat162float(h3)));
    ((__nv_bfloat162*)Xh)[i * 2 + 0] = hh0;
    ((__nv_bfloat162*)Xh)[i * 2 + 1] = hh1;
    ((__nv_bfloat162*)Xl)[i * 2 + 0] = ll0;
    ((__nv_bfloat162*)Xl)[i * 2 + 1] = ll1;
}

// ---------------------------------------------------------------------------
// Split + transpose: B fp32 [K,N] -> BhT/BlT bf16 [N,K]
// ---------------------------------------------------------------------------
__global__ void split_bt_kernel(const float* __restrict__ B,
                                __nv_bfloat16* __restrict__ BhT,
                                __nv_bfloat16* __restrict__ BlT, int K, int N)
{
    __shared__ float th[32][33];
    __shared__ float tl[32][33];
    const int tx = threadIdx.x, ty = threadIdx.y;
    const int n0 = blockIdx.x * 32, k0 = blockIdx.y * 32;
#pragma unroll
    for (int i = 0; i < 4; i++) {
        int k = ty + i * 8;
        float v = B[(size_t)(k0 + k) * N + n0 + tx];
        float hi = __bfloat162float(__float2bfloat16(v));
        th[k][tx] = hi;
        tl[k][tx] = v - hi;
    }
    __syncthreads();
#pragma unroll
    for (int i = 0; i < 4; i++) {
        int n = ty + i * 8;
        BhT[(size_t)(n0 + n) * K + k0 + tx] = __float2bfloat16(th[tx][n]);
        BlT[(size_t)(n0 + n) * K + k0 + tx] = __float2bfloat16(tl[tx][n]);
    }
}

// ---------------------------------------------------------------------------
// RoPE for Q
// ---------------------------------------------------------------------------
__global__ void rope_q_kernel(const float* __restrict__ qkv,
                              const int* __restrict__ positions,
                              float* __restrict__ Qg)
{
    int idx = blockIdx.x * blockDim.x + threadIdx.x;
    int i  = idx & 63;
    int h  = (idx >> 6) & 31;
    int bs = idx >> 11;
    if (bs >= BSc) return;

    const float* src = qkv + (size_t)bs * QKVF + h * Dc;
    float x1 = src[i], x2 = src[i + 64];
    float pos = (float)positions[bs];
    float inv = 1.0f / powf(10000.0f, (float)i * (1.0f / 64.0f));
    float ang = pos * inv;
    float sn, cs;
    sincosf(ang, &sn, &cs);
    float* dst = Qg + (size_t)bs * (Hc * Dc) + h * Dc;
    dst[i]      = x1 * cs - x2 * sn;
    dst[i + 64] = x2 * cs + x1 * sn;
}

// ---------------------------------------------------------------------------
// Smooth conv + RoPE for K
// ---------------------------------------------------------------------------
__global__ void smooth_rope_k_kernel(const float* __restrict__ qkv,
                                     const int* __restrict__ positions,
                                     const float* __restrict__ conv_k,
                                     float* __restrict__ Kg)
{
    int idx = blockIdx.x * blockDim.x + threadIdx.x;
    int i  = idx & 63;
    int kv = (idx >> 6) & 7;
    int bs = idx >> 9;
    if (bs >= BSc) return;
    int s = bs & (Sc - 1);

    const float* src = qkv + (size_t)bs * QKVF + Hc * Dc + kv * Dc;
    float c1 = src[i], c2 = src[i + 64];
    float p1 = 0.f, p2 = 0.f;
    if (s > 0) {
        const float* ps = src - QKVF;
        p1 = ps[i]; p2 = ps[i + 64];
    }
    float f0 = conv_k[kv], f1 = conv_k[KVc + kv];
    float x1 = c1 * f1 + p1 * f0;
    float x2 = c2 * f1 + p2 * f0;

    float pos = (float)positions[bs];
    float inv = 1.0f / powf(10000.0f, (float)i * (1.0f / 64.0f));
    float ang = pos * inv;
    float sn, cs;
    sincosf(ang, &sn, &cs);
    float* dst = Kg + ((size_t)bs * KVc + kv) * Dc;
    dst[i]      = x1 * cs - x2 * sn;
    dst[i + 64] = x2 * cs + x1 * sn;
}

// ---------------------------------------------------------------------------
// Smooth conv for V
// ---------------------------------------------------------------------------
__global__ void smooth_v_kernel(const float* __restrict__ qkv,
                                const float* __restrict__ conv_v,
                                float* __restrict__ Vg)
{
    int idx = blockIdx.x * blockDim.x + threadIdx.x;
    int d  = idx & 127;
    int kv = (idx >> 7) & 7;
    int bs = idx >> 10;
    if (bs >= BSc) return;
    int s = bs & (Sc - 1);

    const float* src = qkv + (size_t)bs * QKVF + (Hc + KVc) * Dc + kv * Dc;
    float c = src[d];
    float p = (s > 0) ? src[d - QKVF] : 0.f;
    float f0 = conv_v[kv], f1 = conv_v[KVc + kv];
    Vg[((size_t)bs * KVc + kv) * Dc + d] = c * f1 + p * f0;
}

// ---------------------------------------------------------------------------
// Windowed flash attention (fp32 CUDA-core; unchanged from R1 passing code)
// ---------------------------------------------------------------------------
#define QS_STRIDE 132
#define KT_STRIDE 68
#define SS_STRIDE 65
#define ATTN_SMEM_FLOATS (64*QS_STRIDE + 128*KT_STRIDE + 64*128 + 64*SS_STRIDE + 64*3 + 256)
#define ATTN_SMEM_BYTES  (ATTN_SMEM_FLOATS * 4)

__global__ __launch_bounds__(256)
void attn_kernel(const float* __restrict__ Qg, const float* __restrict__ Kg,
                 const float* __restrict__ Vg, float* __restrict__ Og)
{
    extern __shared__ float smf[];
    float* Qs   = smf;
    float* Kt   = Qs + 64 * QS_STRIDE;
    float* Vs   = Kt + 128 * KT_STRIDE;
    float* Ss   = Vs + 64 * 128;
    float* mrow = Ss + 64 * SS_STRIDE;
    float* lrow = mrow + 64;
    float* frow = lrow + 64;
    float* red  = frow + 64;

    const int tid = threadIdx.x;
    const int qt = blockIdx.x, h = blockIdx.y, b = blockIdx.z;
    const int q0 = qt * 64;
    const int kvh = h >> 2;

    for (int idx = tid; idx < 64 * 128; idx += 256) {
        int r = idx >> 7, d = idx & 127;
        Qs[r * QS_STRIDE + d] =
            Qg[(((size_t)(b * Sc + q0 + r)) * Hc + h) * Dc + d];
    }
    if (tid < 64) { mrow[tid] = -1e30f; lrow[tid] = 0.f; }

    const int pr = tid & 63;
    const int pc = (tid >> 6) * 32;
    float o[32];
#pragma unroll
    for (int j = 0; j < 32; j++) o[j] = 0.f;

    const int tx = tid & 15, ty = tid >> 4;
    const int r0 = ty * 4, c0 = tx * 4;
    const float scale = 0.08838834764831845f;

    int kt_lo = qt - 8; if (kt_lo < 0) kt_lo = 0;
    __syncthreads();

    for (int kt = kt_lo; kt <= qt; kt++) {
        const int k0 = kt * 64;
        for (int idx = tid; idx < 64 * 128; idx += 256) {
            int c = idx >> 7, d = idx & 127;
            size_t base = (((size_t)(b * Sc + k0 + c)) * KVc + kvh) * Dc + d;
            Kt[d * KT_STRIDE + c] = Kg[base];
            Vs[c * 128 + d]       = Vg[base];
        }
        __syncthreads();

        float sc[4][4];
#pragma unroll
        for (int i = 0; i < 4; i++)
#pragma unroll
            for (int j = 0; j < 4; j++) sc[i][j] = 0.f;

        for (int d = 0; d < 128; d++) {
            float4 kv4 = *(const float4*)&Kt[d * KT_STRIDE + c0];
#pragma unroll
            for (int i = 0; i < 4; i++) {
                float qv = Qs[(r0 + i) * QS_STRIDE + d];
                sc[i][0] += qv * kv4.x;
                sc[i][1] += qv * kv4.y;
                sc[i][2] += qv * kv4.z;
                sc[i][3] += qv * kv4.w;
            }
        }
#pragma unroll
        for (int i = 0; i < 4; i++) {
            int qi = q0 + r0 + i;
#pragma unroll
            for (int j = 0; j < 4; j++) {
                int ki = k0 + c0 + j;
                bool ok = (ki <= qi) && (qi - ki < Wc);
                Ss[(r0 + i) * SS_STRIDE + c0 + j] = ok ? sc[i][j] * scale : -1e30f;
            }
        }
        __syncthreads();

        {
            int rr = tid >> 2, seg = (tid & 3) * 16;
            float mx = -1e30f;
#pragma unroll
            for (int j = 0; j < 16; j++)
                mx = fmaxf(mx, Ss[rr * SS_STRIDE + seg + j]);
            red[(tid >> 2) * 4 + (tid & 3)] = mx;
        }
        __syncthreads();
        if (tid < 64) {
            float tm = fmaxf(fmaxf(red[tid * 4], red[tid * 4 + 1]),
                             fmaxf(red[tid * 4 + 2], red[tid * 4 + 3]));
            float mo = mrow[tid];
            float mn = fmaxf(mo, tm);
            mrow[tid] = mn;
            frow[tid] = __expf(mo - mn);
        }
        __syncthreads();

        {
            int rr = tid >> 2, seg = (tid & 3) * 16;
            float mn = mrow[rr];
            float s = 0.f;
#pragma unroll
            for (int j = 0; j < 16; j++) {
                float vv = Ss[rr * SS_STRIDE + seg + j];
                float p = (vv > -1e29f) ? __expf(vv - mn) : 0.f;
                Ss[rr * SS_STRIDE + seg + j] = p;
                s += p;
            }
            red[(tid >> 2) * 4 + (tid & 3)] = s;
        }
        __syncthreads();
        if (tid < 64) {
            lrow[tid] = lrow[tid] * frow[tid] +
                        red[tid * 4] + red[tid * 4 + 1] +
                        red[tid * 4 + 2] + red[tid * 4 + 3];
        }

        {
            float f = frow[pr];
#pragma unroll
            for (int j = 0; j < 32; j++) o[j] *= f;
            for (int k = 0; k < 64; k++) {
                float p = Ss[pr * SS_STRIDE + k];
                const float4* vp = (const float4*)&Vs[k * 128 + pc];
#pragma unroll
                for (int j4 = 0; j4 < 8; j4++) {
                    float4 vv = vp[j4];
                    o[j4 * 4 + 0] += p * vv.x;
                    o[j4 * 4 + 1] += p * vv.y;
                    o[j4 * 4 + 2] += p * vv.z;
                    o[j4 * 4 + 3] += p * vv.w;
                }
            }
        }
        __syncthreads();
    }

    float linv = 1.0f / lrow[pr];
    size_t ob = ((size_t)(b * Sc + q0 + pr)) * (Hc * Dc) + h * Dc + pc;
#pragma unroll
    for (int j4 = 0; j4 < 8; j4++) {
        float4 w = make_float4(o[j4 * 4 + 0] * linv, o[j4 * 4 + 1] * linv,
                               o[j4 * 4 + 2] * linv, o[j4 * 4 + 3] * linv);
        *(float4*)&Og[ob + j4 * 4] = w;
    }
}

// ---------------------------------------------------------------------------
// Launch
// ---------------------------------------------------------------------------
extern "C" void kernel_launch(void* const* d_in, const int* in_sizes, int n_in,
                              void* d_out, int out_size)
{
    const float* hidden    = (const float*)d_in[0];
    const int*   positions = (const int*)d_in[1];
    const float* w_pack    = (const float*)d_in[2];
    const float* w_o       = (const float*)d_in[3];
    const float* conv_k    = (const float*)d_in[4];
    const float* conv_v    = (const float*)d_in[5];
    float* out = (float*)d_out;

    float *qkv, *q, *k, *v, *attn;
    __nv_bfloat16 *ah, *al, *bh, *bl;
    cudaGetSymbolAddress((void**)&qkv,  g_qkv);
    cudaGetSymbolAddress((void**)&q,    g_q);
    cudaGetSymbolAddress((void**)&k,    g_k);
    cudaGetSymbolAddress((void**)&v,    g_v);
    cudaGetSymbolAddress((void**)&attn, g_attn);
    cudaGetSymbolAddress((void**)&ah,   g_ah);
    cudaGetSymbolAddress((void**)&al,   g_al);
    cudaGetSymbolAddress((void**)&bh,   g_bh);
    cudaGetSymbolAddress((void**)&bl,   g_bl);

    cudaFuncSetAttribute(gemm_mma, cudaFuncAttributeMaxDynamicSharedMemorySize,
                         GEMM_SMEM);
    cudaFuncSetAttribute(attn_kernel, cudaFuncAttributeMaxDynamicSharedMemorySize,
                         ATTN_SMEM_BYTES);

    // ---- GEMM 1: qkv = hidden[4096,4096] @ w_pack[4096,6144] ----
    {
        int n4 = BSc * HIDc / 4;
        split_a_kernel<<<(n4 + 255) / 256, 256>>>(hidden, ah, al, n4);
        split_bt_kernel<<<dim3(QKVF / 32, HIDc / 32), dim3(32, 8)>>>(w_pack, bh, bl, HIDc, QKVF);
        dim3 g1(QKVF / 128, BSc / 128);
        gemm_mma<<<g1, 256, GEMM_SMEM>>>(ah, al, bh, bl, qkv, BSc, QKVF, HIDc);
    }

    // ---- elementwise prep ----
    rope_q_kernel<<<(BSc * Hc * 64) / 256, 256>>>(qkv, positions, q);
    smooth_rope_k_kernel<<<(BSc * KVc * 64) / 256, 256>>>(qkv, positions, conv_k, k);
    smooth_v_kernel<<<(BSc * KVc * 128) / 256, 256>>>(qkv, conv_v, v);

    // ---- windowed attention ----
    attn_kernel<<<dim3(Sc / 64, Hc, Bc), 256, ATTN_SMEM_BYTES>>>(q, k, v, attn);

    // ---- GEMM 2: out = attn[4096,4096] @ w_o[4096,4096] ----
    {
        int n4 = BSc * HIDc / 4;
        split_a_kernel<<<(n4 + 255) / 256, 256>>>(attn, ah, al, n4);
        split_bt_kernel<<<dim3(HIDc / 32, HIDc / 32), dim3(32, 8)>>>(w_o, bh, bl, HIDc, HIDc);
        dim3 g2(HIDc / 128, BSc / 128);
        gemm_mma<<<g2, 256, GEMM_SMEM>>>(ah, al, bh, bl, out, BSc, HIDc, HIDc);
    }
}

// round 4
// speedup vs baseline: 2.5013x; 1.1789x over previous
#include <cuda_runtime.h>
#include <cuda_bf16.h>
#include <math.h>
#include <stdint.h>

// ---------------------------------------------------------------------------
// Problem constants
// ---------------------------------------------------------------------------
#define Bc    2
#define Sc    2048
#define HIDc  4096
#define Hc    32
#define KVc   8
#define Dc    128
#define Wc    512
#define BSc   (Bc * Sc)              // 4096
#define QKVF  ((Hc + 2 * KVc) * Dc)  // 6144

// ---------------------------------------------------------------------------
// Scratch (static device globals -- no allocation allowed)
// ---------------------------------------------------------------------------
__device__ float g_qkv[(size_t)BSc * QKVF];

__device__ __nv_bfloat16 g_qh[(size_t)BSc * Hc * Dc];   // roped Q hi
__device__ __nv_bfloat16 g_ql[(size_t)BSc * Hc * Dc];   // roped Q lo
__device__ __nv_bfloat16 g_kh[(size_t)BSc * KVc * Dc];  // smoothed+roped K hi
__device__ __nv_bfloat16 g_kl[(size_t)BSc * KVc * Dc];  // smoothed+roped K lo
__device__ __nv_bfloat16 g_vth[(size_t)Bc * KVc * Dc * Sc]; // V^T hi  [b][kv][d][s]
__device__ __nv_bfloat16 g_vtl[(size_t)Bc * KVc * Dc * Sc]; // V^T lo

__device__ __nv_bfloat16 g_ah[(size_t)BSc * HIDc];      // GEMM A hi [M,K]
__device__ __nv_bfloat16 g_al[(size_t)BSc * HIDc];      // GEMM A lo
__device__ __nv_bfloat16 g_bh[(size_t)QKVF * HIDc];     // GEMM B^T hi [N,K]
__device__ __nv_bfloat16 g_bl[(size_t)QKVF * HIDc];     // GEMM B^T lo

// ---------------------------------------------------------------------------
// Helpers
// ---------------------------------------------------------------------------
__device__ __forceinline__ uint32_t smem_u32(const void* p) {
    uint32_t a;
    asm("{ .reg .u64 t; cvta.to.shared.u64 t, %1; cvt.u32.u64 %0, t; }"
        : "=r"(a) : "l"(p));
    return a;
}
__device__ __forceinline__ void cp16(uint32_t smem, const void* gmem) {
    asm volatile("cp.async.cg.shared.global [%0], [%1], 16;"
                 :: "r"(smem), "l"(gmem));
}
#define CP_COMMIT() asm volatile("cp.async.commit_group;" ::: "memory")
#define CP_WAIT0()  asm volatile("cp.async.wait_group 0;" ::: "memory")

__device__ __forceinline__ uint32_t lds32(uint32_t addr) {
    uint32_t v;
    asm("ld.shared.b32 %0, [%1];" : "=r"(v) : "r"(addr));
    return v;
}
__device__ __forceinline__ void sts32(uint32_t addr, uint32_t v) {
    asm volatile("st.shared.b32 [%0], %1;" :: "r"(addr), "r"(v));
}

// bf16 HMMA m16n8k16 (sm_80 baseline; tensor pipe on sm_103)
__device__ __forceinline__ void mma16816(float* d, const uint32_t* a,
                                         const uint32_t* b) {
    asm volatile(
        "mma.sync.aligned.m16n8k16.row.col.f32.bf16.bf16.f32 "
        "{%0,%1,%2,%3}, {%4,%5,%6,%7}, {%8,%9}, {%0,%1,%2,%3};"
        : "+f"(d[0]), "+f"(d[1]), "+f"(d[2]), "+f"(d[3])
        : "r"(a[0]), "r"(a[1]), "r"(a[2]), "r"(a[3]),
          "r"(b[0]), "r"(b[1]));
}

__device__ __forceinline__ uint32_t pack_hi2(float x, float y) {
    __nv_bfloat162 h(__float2bfloat16(x), __float2bfloat16(y));
    return *(uint32_t*)&h;
}
__device__ __forceinline__ uint32_t pack_lo2(float x, float y) {
    float hx = __bfloat162float(__float2bfloat16(x));
    float hy = __bfloat162float(__float2bfloat16(y));
    __nv_bfloat162 l(__float2bfloat16(x - hx), __float2bfloat16(y - hy));
    return *(uint32_t*)&l;
}

// ---------------------------------------------------------------------------
// Split-precision HMMA GEMM (unchanged from R3 passing version)
// ---------------------------------------------------------------------------
#define GBK   32
#define SROW  40
#define MATB  (128 * SROW * 2)
#define STAGEB (4 * MATB)
#define GEMM_SMEM (2 * STAGEB)

__global__ __launch_bounds__(256)
void gemm_mma(const __nv_bfloat16* __restrict__ Ah,
              const __nv_bfloat16* __restrict__ Al,
              const __nv_bfloat16* __restrict__ Bh,
              const __nv_bfloat16* __restrict__ Bl,
              float* __restrict__ C, int M, int N, int K)
{
    extern __shared__ char sm[];
    const uint32_t sb = smem_u32(sm);
    const int tid  = threadIdx.x;
    const int wid  = tid >> 5;
    const int lane = tid & 31;
    const int wm = wid & 3;
    const int wn = wid >> 2;
    const int g  = lane >> 2;
    const int tg = lane & 3;

    const int m0 = blockIdx.y * 128;
    const int n0 = blockIdx.x * 128;

    auto load_stage = [&](int k0, int st) {
        const uint32_t base = sb + st * STAGEB;
#pragma unroll
        for (int mat = 0; mat < 4; mat++) {
            const __nv_bfloat16* src =
                (mat == 0) ? Ah : (mat == 1) ? Al : (mat == 2) ? Bh : Bl;
            const int row0 = (mat < 2) ? m0 : n0;
#pragma unroll
            for (int hh = 0; hh < 2; hh++) {
                int unit = tid + hh * 256;
                int r = unit >> 2, u = unit & 3;
                const void* gp = src + (size_t)(row0 + r) * K + k0 + u * 8;
                cp16(base + mat * MATB + r * (SROW * 2) + u * 16, gp);
            }
        }
    };

    float acc[2][8][4];
#pragma unroll
    for (int mt = 0; mt < 2; mt++)
#pragma unroll
        for (int nt = 0; nt < 8; nt++)
#pragma unroll
            for (int j = 0; j < 4; j++) acc[mt][nt][j] = 0.f;

    const int NIT = K / GBK;
    load_stage(0, 0);
    CP_COMMIT();

    for (int it = 0; it < NIT; it++) {
        CP_WAIT0();
        __syncthreads();
        const int st = it & 1;
        if (it + 1 < NIT) {
            load_stage((it + 1) * GBK, st ^ 1);
            CP_COMMIT();
        }

        const uint32_t ahb = sb + st * STAGEB;
        const uint32_t alb = ahb + MATB;
        const uint32_t bhb = ahb + 2 * MATB;
        const uint32_t blb = ahb + 3 * MATB;

#pragma unroll
        for (int ks = 0; ks < 2; ks++) {
            const int c0 = ks * 16 + tg * 2;
            uint32_t ah[2][4], al[2][4];
#pragma unroll
            for (int mt = 0; mt < 2; mt++) {
                const int r0 = wm * 32 + mt * 16 + g;
                const uint32_t o00 = (uint32_t)((r0 * SROW + c0) * 2);
                const uint32_t o10 = (uint32_t)(((r0 + 8) * SROW + c0) * 2);
                ah[mt][0] = lds32(ahb + o00);
                ah[mt][1] = lds32(ahb + o10);
                ah[mt][2] = lds32(ahb + o00 + 16);
                ah[mt][3] = lds32(ahb + o10 + 16);
                al[mt][0] = lds32(alb + o00);
                al[mt][1] = lds32(alb + o10);
                al[mt][2] = lds32(alb + o00 + 16);
                al[mt][3] = lds32(alb + o10 + 16);
            }
#pragma unroll
            for (int nt = 0; nt < 8; nt++) {
                const int r0 = wn * 64 + nt * 8 + g;
                const uint32_t bo = (uint32_t)((r0 * SROW + c0) * 2);
                uint32_t bh2[2], bl2[2];
                bh2[0] = lds32(bhb + bo);
                bh2[1] = lds32(bhb + bo + 16);
                bl2[0] = lds32(blb + bo);
                bl2[1] = lds32(blb + bo + 16);
#pragma unroll
                for (int mt = 0; mt < 2; mt++) {
                    mma16816(acc[mt][nt], ah[mt], bh2);
                    mma16816(acc[mt][nt], ah[mt], bl2);
                    mma16816(acc[mt][nt], al[mt], bh2);
                }
            }
        }
    }

#pragma unroll
    for (int mt = 0; mt < 2; mt++) {
        const int r0 = m0 + wm * 32 + mt * 16 + g;
#pragma unroll
        for (int nt = 0; nt < 8; nt++) {
            const int cc = n0 + wn * 64 + nt * 8 + tg * 2;
            float2 w0 = make_float2(acc[mt][nt][0], acc[mt][nt][1]);
            float2 w1 = make_float2(acc[mt][nt][2], acc[mt][nt][3]);
            *(float2*)(C + (size_t)r0 * N + cc)       = w0;
            *(float2*)(C + (size_t)(r0 + 8) * N + cc) = w1;
        }
    }
}

// ---------------------------------------------------------------------------
// Split fp32 -> (hi, lo) bf16 (A operand prep for GEMM1)
// ---------------------------------------------------------------------------
__global__ void split_a_kernel(const float* __restrict__ X,
                               __nv_bfloat16* __restrict__ Xh,
                               __nv_bfloat16* __restrict__ Xl, int n4)
{
    int i = blockIdx.x * blockDim.x + threadIdx.x;
    if (i >= n4) return;
    float4 v = ((const float4*)X)[i];
    ((uint32_t*)Xh)[i * 2 + 0] = pack_hi2(v.x, v.y);
    ((uint32_t*)Xh)[i * 2 + 1] = pack_hi2(v.z, v.w);
    ((uint32_t*)Xl)[i * 2 + 0] = pack_lo2(v.x, v.y);
    ((uint32_t*)Xl)[i * 2 + 1] = pack_lo2(v.z, v.w);
}

// ---------------------------------------------------------------------------
// Split + transpose: B fp32 [K,N] -> BhT/BlT bf16 [N,K]
// ---------------------------------------------------------------------------
__global__ void split_bt_kernel(const float* __restrict__ B,
                                __nv_bfloat16* __restrict__ BhT,
                                __nv_bfloat16* __restrict__ BlT, int K, int N)
{
    __shared__ float th[32][33];
    __shared__ float tl[32][33];
    const int tx = threadIdx.x, ty = threadIdx.y;
    const int n0 = blockIdx.x * 32, k0 = blockIdx.y * 32;
#pragma unroll
    for (int i = 0; i < 4; i++) {
        int k = ty + i * 8;
        float v = B[(size_t)(k0 + k) * N + n0 + tx];
        float hi = __bfloat162float(__float2bfloat16(v));
        th[k][tx] = hi;
        tl[k][tx] = v - hi;
    }
    __syncthreads();
#pragma unroll
    for (int i = 0; i < 4; i++) {
        int n = ty + i * 8;
        BhT[(size_t)(n0 + n) * K + k0 + tx] = __float2bfloat16(th[tx][n]);
        BlT[(size_t)(n0 + n) * K + k0 + tx] = __float2bfloat16(tl[tx][n]);
    }
}

// ---------------------------------------------------------------------------
// RoPE for Q -> split bf16 [bs][h][d]
// ---------------------------------------------------------------------------
__global__ void rope_q_kernel(const float* __restrict__ qkv,
                              const int* __restrict__ positions,
                              __nv_bfloat16* __restrict__ Qh,
                              __nv_bfloat16* __restrict__ Ql)
{
    int idx = blockIdx.x * blockDim.x + threadIdx.x;
    int i  = idx & 63;
    int h  = (idx >> 6) & 31;
    int bs = idx >> 11;
    if (bs >= BSc) return;

    const float* src = qkv + (size_t)bs * QKVF + h * Dc;
    float x1 = src[i], x2 = src[i + 64];
    float pos = (float)positions[bs];
    float inv = 1.0f / powf(10000.0f, (float)i * (1.0f / 64.0f));
    float ang = pos * inv;
    float sn, cs;
    sincosf(ang, &sn, &cs);
    float y1 = x1 * cs - x2 * sn;
    float y2 = x2 * cs + x1 * sn;

    size_t o = (size_t)bs * (Hc * Dc) + h * Dc;
    __nv_bfloat16 h1 = __float2bfloat16(y1);
    __nv_bfloat16 h2 = __float2bfloat16(y2);
    Qh[o + i]      = h1;
    Qh[o + i + 64] = h2;
    Ql[o + i]      = __float2bfloat16(y1 - __bfloat162float(h1));
    Ql[o + i + 64] = __float2bfloat16(y2 - __bfloat162float(h2));
}

// ---------------------------------------------------------------------------
// Smooth conv + RoPE for K -> split bf16 [bs][kv][d]
// ---------------------------------------------------------------------------
__global__ void smooth_rope_k_kernel(const float* __restrict__ qkv,
                                     const int* __restrict__ positions,
                                     const float* __restrict__ conv_k,
                                     __nv_bfloat16* __restrict__ Kh,
                                     __nv_bfloat16* __restrict__ Kl)
{
    int idx = blockIdx.x * blockDim.x + threadIdx.x;
    int i  = idx & 63;
    int kv = (idx >> 6) & 7;
    int bs = idx >> 9;
    if (bs >= BSc) return;
    int s = bs & (Sc - 1);

    const float* src = qkv + (size_t)bs * QKVF + Hc * Dc + kv * Dc;
    float c1 = src[i], c2 = src[i + 64];
    float p1 = 0.f, p2 = 0.f;
    if (s > 0) {
        const float* ps = src - QKVF;
        p1 = ps[i]; p2 = ps[i + 64];
    }
    float f0 = conv_k[kv], f1 = conv_k[KVc + kv];
    float x1 = c1 * f1 + p1 * f0;
    float x2 = c2 * f1 + p2 * f0;

    float pos = (float)positions[bs];
    float inv = 1.0f / powf(10000.0f, (float)i * (1.0f / 64.0f));
    float ang = pos * inv;
    float sn, cs;
    sincosf(ang, &sn, &cs);
    float y1 = x1 * cs - x2 * sn;
    float y2 = x2 * cs + x1 * sn;

    size_t o = ((size_t)bs * KVc + kv) * Dc;
    __nv_bfloat16 h1 = __float2bfloat16(y1);
    __nv_bfloat16 h2 = __float2bfloat16(y2);
    Kh[o + i]      = h1;
    Kh[o + i + 64] = h2;
    Kl[o + i]      = __float2bfloat16(y1 - __bfloat162float(h1));
    Kl[o + i + 64] = __float2bfloat16(y2 - __bfloat162float(h2));
}

// ---------------------------------------------------------------------------
// Smooth conv for V + transpose -> split bf16 Vt [b][kv][d][s]
// grid: (s-tile 64, d-tile 4, b*kv 16), block (32,8)
// ---------------------------------------------------------------------------
__global__ void smooth_v_t_kernel(const float* __restrict__ qkv,
                                  const float* __restrict__ conv_v,
                                  __nv_bfloat16* __restrict__ Vth,
                                  __nv_bfloat16* __restrict__ Vtl)
{
    __shared__ float t[32][33];
    const int tx = threadIdx.x, ty = threadIdx.y;
    const int s0 = blockIdx.x * 32;
    const int d0 = blockIdx.y * 32;
    const int b  = blockIdx.z >> 3;
    const int kv = blockIdx.z & 7;

    const float f0 = conv_v[kv], f1 = conv_v[KVc + kv];
    const size_t voff = (size_t)(Hc + KVc) * Dc + kv * Dc + d0;

#pragma unroll
    for (int i = 0; i < 4; i++) {
        int sl = ty + i * 8;
        int s = s0 + sl;
        const float* src = qkv + (size_t)(b * Sc + s) * QKVF + voff;
        float cur = src[tx];
        float prv = (s > 0) ? src[tx - QKVF] : 0.f;
        t[sl][tx] = cur * f1 + prv * f0;
    }
    __syncthreads();
#pragma unroll
    for (int i = 0; i < 4; i++) {
        int dl = ty + i * 8;
        float v = t[tx][dl];
        __nv_bfloat16 hi = __float2bfloat16(v);
        size_t o = (((size_t)(b * KVc + kv)) * Dc + d0 + dl) * Sc + s0 + tx;
        Vth[o] = hi;
        Vtl[o] = __float2bfloat16(v - __bfloat162float(hi));
    }
}

// ---------------------------------------------------------------------------
// Windowed flash attention on HMMA with split-bf16 operands.
// CTA = (qt 64 queries, head, batch), 256 threads = 8 warps.
// Warp grid for scores: 4 (M) x 2 (N of 64). For PV: 4 (M) x 2 (N of 128).
// Writes split-bf16 output directly into GEMM2's A buffers.
// ---------------------------------------------------------------------------
#define RQK  272                 // Q/K smem row stride bytes (128 bf16 + 8 pad)
#define RPV  144                 // P/Vt smem row stride bytes (64 bf16 + 8 pad)
#define SSW  66                  // Ss fp32 row stride in floats

#define QH_OFF  0
#define QL_OFF  (QH_OFF + 64 * RQK)
#define KH_OFF  (QL_OFF + 64 * RQK)
#define KL_OFF  (KH_OFF + 64 * RQK)
#define VTH_OFF (KL_OFF + 64 * RQK)
#define VTL_OFF (VTH_OFF + 128 * RPV)
#define SS_OFF  (VTL_OFF + 128 * RPV)
#define PH_OFF  (SS_OFF + 64 * SSW * 4)
#define PL_OFF  (PH_OFF + 64 * RPV)
#define MROW_OFF (PL_OFF + 64 * RPV)
#define LROW_OFF (MROW_OFF + 256)
#define FROW_OFF (LROW_OFF + 256)
#define RED_OFF  (FROW_OFF + 256)
#define ATTN_SMEM (RED_OFF + 1024)

__global__ __launch_bounds__(256)
void attn_mma(const __nv_bfloat16* __restrict__ Qh, const __nv_bfloat16* __restrict__ Ql,
              const __nv_bfloat16* __restrict__ Kh, const __nv_bfloat16* __restrict__ Kl,
              const __nv_bfloat16* __restrict__ Vth, const __nv_bfloat16* __restrict__ Vtl,
              __nv_bfloat16* __restrict__ Oh, __nv_bfloat16* __restrict__ Ol)
{
    extern __shared__ char sm[];
    const uint32_t sb = smem_u32(sm);
    float* Ss   = (float*)(sm + SS_OFF);
    float* mrow = (float*)(sm + MROW_OFF);
    float* lrow = (float*)(sm + LROW_OFF);
    float* frow = (float*)(sm + FROW_OFF);
    float* red  = (float*)(sm + RED_OFF);

    const int tid  = threadIdx.x;
    const int wid  = tid >> 5;
    const int lane = tid & 31;
    const int g  = lane >> 2;
    const int tg = lane & 3;
    const int wm = wid & 3;          // 16-row block
    const int wn = wid >> 2;         // score col half / PV col half

    const int qt = blockIdx.x, h = blockIdx.y, b = blockIdx.z;
    const int q0 = qt * 64;
    const int kvh = h >> 2;
    const float scale = 0.08838834764831845f;

    // ---- load Q tile (hi/lo) ----
    {
        const uint32_t* qhp = (const uint32_t*)Qh +
            (((size_t)(b * Sc + q0) * Hc + h) * Dc >> 1);
        const uint32_t* qlp = (const uint32_t*)Ql +
            (((size_t)(b * Sc + q0) * Hc + h) * Dc >> 1);
        for (int idx = tid; idx < 64 * 64; idx += 256) {
            int r = idx >> 6, w = idx & 63;
            uint32_t so = (uint32_t)(r * RQK + w * 4);
            sts32(sb + QH_OFF + so, qhp[(size_t)r * (Hc * Dc / 2) + w]);
            sts32(sb + QL_OFF + so, qlp[(size_t)r * (Hc * Dc / 2) + w]);
        }
    }
    if (tid < 64) { mrow[tid] = -1e30f; lrow[tid] = 0.f; }

    float oacc[8][4];
#pragma unroll
    for (int nt = 0; nt < 8; nt++)
#pragma unroll
        for (int j = 0; j < 4; j++) oacc[nt][j] = 0.f;

    int kt_lo = qt - 8; if (kt_lo < 0) kt_lo = 0;
    __syncthreads();

    for (int kt = kt_lo; kt <= qt; kt++) {
        const int k0 = kt * 64;

        // ---- load K (hi/lo) and Vt (hi/lo) tiles ----
        {
            const uint32_t* khp = (const uint32_t*)Kh +
                (((size_t)(b * Sc + k0) * KVc + kvh) * Dc >> 1);
            const uint32_t* klp = (const uint32_t*)Kl +
                (((size_t)(b * Sc + k0) * KVc + kvh) * Dc >> 1);
            for (int idx = tid; idx < 64 * 64; idx += 256) {
                int r = idx >> 6, w = idx & 63;
                uint32_t so = (uint32_t)(r * RQK + w * 4);
                sts32(sb + KH_OFF + so, khp[(size_t)r * (KVc * Dc / 2) + w]);
                sts32(sb + KL_OFF + so, klp[(size_t)r * (KVc * Dc / 2) + w]);
            }
            const uint32_t* vhp = (const uint32_t*)Vth +
                ((((size_t)(b * KVc + kvh)) * Dc * Sc + k0) >> 1);
            const uint32_t* vlp = (const uint32_t*)Vtl +
                ((((size_t)(b * KVc + kvh)) * Dc * Sc + k0) >> 1);
            for (int idx = tid; idx < 128 * 32; idx += 256) {
                int d = idx >> 5, w = idx & 31;
                uint32_t so = (uint32_t)(d * RPV + w * 4);
                sts32(sb + VTH_OFF + so, vhp[(size_t)d * (Sc / 2) + w]);
                sts32(sb + VTL_OFF + so, vlp[(size_t)d * (Sc / 2) + w]);
            }
        }
        __syncthreads();

        // ---- scores: warp computes 16x32 via 3-term split MMA ----
        float sacc[4][4];
#pragma unroll
        for (int nt = 0; nt < 4; nt++)
#pragma unroll
            for (int j = 0; j < 4; j++) sacc[nt][j] = 0.f;

#pragma unroll
        for (int ks = 0; ks < 8; ks++) {
            uint32_t aqh[4], aql[4];
            const uint32_t o0 = (uint32_t)((wm * 16 + g) * RQK + ks * 32 + tg * 4);
            aqh[0] = lds32(sb + QH_OFF + o0);
            aqh[1] = lds32(sb + QH_OFF + o0 + 8 * RQK);
            aqh[2] = lds32(sb + QH_OFF + o0 + 16);
            aqh[3] = lds32(sb + QH_OFF + o0 + 8 * RQK + 16);
            aql[0] = lds32(sb + QL_OFF + o0);
            aql[1] = lds32(sb + QL_OFF + o0 + 8 * RQK);
            aql[2] = lds32(sb + QL_OFF + o0 + 16);
            aql[3] = lds32(sb + QL_OFF + o0 + 8 * RQK + 16);
#pragma unroll
            for (int nt = 0; nt < 4; nt++) {
                const uint32_t bo = (uint32_t)((wn * 32 + nt * 8 + g) * RQK + ks * 32 + tg * 4);
                uint32_t bh2[2], bl2[2];
                bh2[0] = lds32(sb + KH_OFF + bo);
                bh2[1] = lds32(sb + KH_OFF + bo + 16);
                bl2[0] = lds32(sb + KL_OFF + bo);
                bl2[1] = lds32(sb + KL_OFF + bo + 16);
                mma16816(sacc[nt], aqh, bh2);
                mma16816(sacc[nt], aqh, bl2);
                mma16816(sacc[nt], aql, bh2);
            }
        }

        // ---- mask + scale -> Ss ----
        {
            const int qi0 = q0 + wm * 16 + g;
            const int qi1 = qi0 + 8;
            const int r0 = wm * 16 + g;
#pragma unroll
            for (int nt = 0; nt < 4; nt++) {
                const int c = wn * 32 + nt * 8 + tg * 2;
                const int ki0 = k0 + c, ki1 = ki0 + 1;
                bool m00 = (ki0 <= qi0) && (qi0 - ki0 < Wc);
                bool m01 = (ki1 <= qi0) && (qi0 - ki1 < Wc);
                bool m10 = (ki0 <= qi1) && (qi1 - ki0 < Wc);
                bool m11 = (ki1 <= qi1) && (qi1 - ki1 < Wc);
                Ss[r0 * SSW + c]           = m00 ? sacc[nt][0] * scale : -1e30f;
                Ss[r0 * SSW + c + 1]       = m01 ? sacc[nt][1] * scale : -1e30f;
                Ss[(r0 + 8) * SSW + c]     = m10 ? sacc[nt][2] * scale : -1e30f;
                Ss[(r0 + 8) * SSW + c + 1] = m11 ? sacc[nt][3] * scale : -1e30f;
            }
        }
        __syncthreads();

        // ---- row max (partial, 4 threads/row) ----
        {
            int rr = tid >> 2, seg = (tid & 3) * 16;
            float mx = -1e30f;
#pragma unroll
            for (int j = 0; j < 16; j++)
                mx = fmaxf(mx, Ss[rr * SSW + seg + j]);
            red[rr * 4 + (tid & 3)] = mx;
        }
        __syncthreads();
        if (tid < 64) {
            float tm = fmaxf(fmaxf(red[tid * 4], red[tid * 4 + 1]),
                             fmaxf(red[tid * 4 + 2], red[tid * 4 + 3]));
            float mo = mrow[tid];
            float mn = fmaxf(mo, tm);
            mrow[tid] = mn;
            frow[tid] = __expf(mo - mn);
        }
        __syncthreads();

        // ---- exp + partial sums; rescale O fragments ----
        {
            float f0 = frow[wm * 16 + g];
            float f1 = frow[wm * 16 + g + 8];
#pragma unroll
            for (int nt = 0; nt < 8; nt++) {
                oacc[nt][0] *= f0; oacc[nt][1] *= f0;
                oacc[nt][2] *= f1; oacc[nt][3] *= f1;
            }
            int rr = tid >> 2, seg = (tid & 3) * 16;
            float mn = mrow[rr];
            float s = 0.f;
#pragma unroll
            for (int j = 0; j < 16; j++) {
                float vv = Ss[rr * SSW + seg + j];
                float p = (vv > -1e29f) ? __expf(vv - mn) : 0.f;
                Ss[rr * SSW + seg + j] = p;
                s += p;
            }
            red[rr * 4 + (tid & 3)] = s;
        }
        __syncthreads();

        // ---- lrow update + build split-bf16 P ----
        if (tid < 64) {
            lrow[tid] = lrow[tid] * frow[tid] +
                        red[tid * 4] + red[tid * 4 + 1] +
                        red[tid * 4 + 2] + red[tid * 4 + 3];
        }
        for (int idx = tid; idx < 2048; idx += 256) {
            int r = idx >> 5, c2 = (idx & 31) * 2;
            float2 p = *(float2*)&Ss[r * SSW + c2];
            uint32_t so = (uint32_t)(r * RPV + c2 * 2);
            sts32(sb + PH_OFF + so, pack_hi2(p.x, p.y));
            sts32(sb + PL_OFF + so, pack_lo2(p.x, p.y));
        }
        __syncthreads();

        // ---- PV: warp computes 16x64 via 3-term split MMA ----
#pragma unroll
        for (int ks = 0; ks < 4; ks++) {
            uint32_t aph[4], apl[4];
            const uint32_t o0 = (uint32_t)((wm * 16 + g) * RPV + ks * 32 + tg * 4);
            aph[0] = lds32(sb + PH_OFF + o0);
            aph[1] = lds32(sb + PH_OFF + o0 + 8 * RPV);
            aph[2] = lds32(sb + PH_OFF + o0 + 16);
            aph[3] = lds32(sb + PH_OFF + o0 + 8 * RPV + 16);
            apl[0] = lds32(sb + PL_OFF + o0);
            apl[1] = lds32(sb + PL_OFF + o0 + 8 * RPV);
            apl[2] = lds32(sb + PL_OFF + o0 + 16);
            apl[3] = lds32(sb + PL_OFF + o0 + 8 * RPV + 16);
#pragma unroll
            for (int nt = 0; nt < 8; nt++) {
                const uint32_t bo = (uint32_t)((wn * 64 + nt * 8 + g) * RPV + ks * 32 + tg * 4);
                uint32_t bv[2], bw[2];
                bv[0] = lds32(sb + VTH_OFF + bo);
                bv[1] = lds32(sb + VTH_OFF + bo + 16);
                bw[0] = lds32(sb + VTL_OFF + bo);
                bw[1] = lds32(sb + VTL_OFF + bo + 16);
                mma16816(oacc[nt], aph, bv);
                mma16816(oacc[nt], aph, bw);
                mma16816(oacc[nt], apl, bv);
            }
        }
        __syncthreads();
    }

    // ---- epilogue: normalize, split, write GEMM2 A operand ----
    {
        const int r0 = wm * 16 + g;
        float linv0 = 1.0f / lrow[r0];
        float linv1 = 1.0f / lrow[r0 + 8];
        const size_t tok0 = (size_t)(b * Sc + q0 + r0);
        const size_t tok1 = tok0 + 8;
#pragma unroll
        for (int nt = 0; nt < 8; nt++) {
            const int col = h * Dc + wn * 64 + nt * 8 + tg * 2;
            float v00 = oacc[nt][0] * linv0, v01 = oacc[nt][1] * linv0;
            float v10 = oacc[nt][2] * linv1, v11 = oacc[nt][3] * linv1;
            ((uint32_t*)Oh)[(tok0 * HIDc + col) >> 1] = pack_hi2(v00, v01);
            ((uint32_t*)Ol)[(tok0 * HIDc + col) >> 1] = pack_lo2(v00, v01);
            ((uint32_t*)Oh)[(tok1 * HIDc + col) >> 1] = pack_hi2(v10, v11);
            ((uint32_t*)Ol)[(tok1 * HIDc + col) >> 1] = pack_lo2(v10, v11);
        }
    }
}

// ---------------------------------------------------------------------------
// Launch
// ---------------------------------------------------------------------------
extern "C" void kernel_launch(void* const* d_in, const int* in_sizes, int n_in,
                              void* d_out, int out_size)
{
    const float* hidden    = (const float*)d_in[0];
    const int*   positions = (const int*)d_in[1];
    const float* w_pack    = (const float*)d_in[2];
    const float* w_o       = (const float*)d_in[3];
    const float* conv_k    = (const float*)d_in[4];
    const float* conv_v    = (const float*)d_in[5];
    float* out = (float*)d_out;

    float* qkv;
    __nv_bfloat16 *qh, *ql, *kh, *kl, *vth, *vtl, *ah, *al, *bh, *bl;
    cudaGetSymbolAddress((void**)&qkv, g_qkv);
    cudaGetSymbolAddress((void**)&qh,  g_qh);
    cudaGetSymbolAddress((void**)&ql,  g_ql);
    cudaGetSymbolAddress((void**)&kh,  g_kh);
    cudaGetSymbolAddress((void**)&kl,  g_kl);
    cudaGetSymbolAddress((void**)&vth, g_vth);
    cudaGetSymbolAddress((void**)&vtl, g_vtl);
    cudaGetSymbolAddress((void**)&ah,  g_ah);
    cudaGetSymbolAddress((void**)&al,  g_al);
    cudaGetSymbolAddress((void**)&bh,  g_bh);
    cudaGetSymbolAddress((void**)&bl,  g_bl);

    cudaFuncSetAttribute(gemm_mma, cudaFuncAttributeMaxDynamicSharedMemorySize,
                         GEMM_SMEM);
    cudaFuncSetAttribute(attn_mma, cudaFuncAttributeMaxDynamicSharedMemorySize,
                         ATTN_SMEM);

    // ---- GEMM 1: qkv = hidden @ w_pack ----
    {
        int n4 = BSc * HIDc / 4;
        split_a_kernel<<<(n4 + 255) / 256, 256>>>(hidden, ah, al, n4);
        split_bt_kernel<<<dim3(QKVF / 32, HIDc / 32), dim3(32, 8)>>>(w_pack, bh, bl, HIDc, QKVF);
        dim3 g1(QKVF / 128, BSc / 128);
        gemm_mma<<<g1, 256, GEMM_SMEM>>>(ah, al, bh, bl, qkv, BSc, QKVF, HIDc);
    }

    // ---- elementwise prep (emit split bf16 operands) ----
    rope_q_kernel<<<(BSc * Hc * 64) / 256, 256>>>(qkv, positions, qh, ql);
    smooth_rope_k_kernel<<<(BSc * KVc * 64) / 256, 256>>>(qkv, positions, conv_k, kh, kl);
    smooth_v_t_kernel<<<dim3(Sc / 32, Dc / 32, Bc * KVc), dim3(32, 8)>>>(qkv, conv_v, vth, vtl);

    // prep GEMM2 weights early (independent of attention)
    split_bt_kernel<<<dim3(HIDc / 32, HIDc / 32), dim3(32, 8)>>>(w_o, bh, bl, HIDc, HIDc);

    // ---- windowed attention on tensor cores; writes split A for GEMM2 ----
    attn_mma<<<dim3(Sc / 64, Hc, Bc), 256, ATTN_SMEM>>>(qh, ql, kh, kl, vth, vtl, ah, al);

    // ---- GEMM 2: out = attn @ w_o ----
    {
        dim3 g2(HIDc / 128, BSc / 128);
        gemm_mma<<<g2, 256, GEMM_SMEM>>>(ah, al, bh, bl, out, BSc, HIDc, HIDc);
    }
}

// round 5
// speedup vs baseline: 2.7744x; 1.1092x over previous
#include <cuda_runtime.h>
#include <cuda_bf16.h>
#include <math.h>
#include <stdint.h>

// ---------------------------------------------------------------------------
// Problem constants
// ---------------------------------------------------------------------------
#define Bc    2
#define Sc    2048
#define HIDc  4096
#define Hc    32
#define KVc   8
#define Dc    128
#define Wc    512
#define BSc   (Bc * Sc)              // 4096
#define QKVF  ((Hc + 2 * KVc) * Dc)  // 6144

// ---------------------------------------------------------------------------
// Scratch (static device globals -- no allocation allowed)
// ---------------------------------------------------------------------------
__device__ float g_qkv[(size_t)BSc * QKVF];

__device__ __nv_bfloat16 g_qh[(size_t)BSc * Hc * Dc];
__device__ __nv_bfloat16 g_ql[(size_t)BSc * Hc * Dc];
__device__ __nv_bfloat16 g_kh[(size_t)BSc * KVc * Dc];
__device__ __nv_bfloat16 g_kl[(size_t)BSc * KVc * Dc];
__device__ __nv_bfloat16 g_vth[(size_t)Bc * KVc * Dc * Sc]; // V^T [b][kv][d][s]
__device__ __nv_bfloat16 g_vtl[(size_t)Bc * KVc * Dc * Sc];

__device__ __nv_bfloat16 g_ah[(size_t)BSc * HIDc];
__device__ __nv_bfloat16 g_al[(size_t)BSc * HIDc];
__device__ __nv_bfloat16 g_bh[(size_t)QKVF * HIDc];
__device__ __nv_bfloat16 g_bl[(size_t)QKVF * HIDc];

// ---------------------------------------------------------------------------
// Helpers
// ---------------------------------------------------------------------------
__device__ __forceinline__ uint32_t smem_u32(const void* p) {
    uint32_t a;
    asm("{ .reg .u64 t; cvta.to.shared.u64 t, %1; cvt.u32.u64 %0, t; }"
        : "=r"(a) : "l"(p));
    return a;
}
__device__ __forceinline__ void cp16(uint32_t smem, const void* gmem) {
    asm volatile("cp.async.cg.shared.global [%0], [%1], 16;"
                 :: "r"(smem), "l"(gmem));
}
#define CP_COMMIT() asm volatile("cp.async.commit_group;" ::: "memory")
#define CP_WAIT0()  asm volatile("cp.async.wait_group 0;" ::: "memory")

__device__ __forceinline__ uint32_t lds32(uint32_t addr) {
    uint32_t v;
    asm("ld.shared.b32 %0, [%1];" : "=r"(v) : "r"(addr));
    return v;
}
__device__ __forceinline__ void sts32(uint32_t addr, uint32_t v) {
    asm volatile("st.shared.b32 [%0], %1;" :: "r"(addr), "r"(v));
}

// bf16 HMMA m16n8k16
__device__ __forceinline__ void mma16816(float* d, const uint32_t* a,
                                         const uint32_t* b) {
    asm volatile(
        "mma.sync.aligned.m16n8k16.row.col.f32.bf16.bf16.f32 "
        "{%0,%1,%2,%3}, {%4,%5,%6,%7}, {%8,%9}, {%0,%1,%2,%3};"
        : "+f"(d[0]), "+f"(d[1]), "+f"(d[2]), "+f"(d[3])
        : "r"(a[0]), "r"(a[1]), "r"(a[2]), "r"(a[3]),
          "r"(b[0]), "r"(b[1]));
}

__device__ __forceinline__ uint32_t pack_hi2(float x, float y) {
    __nv_bfloat162 h(__float2bfloat16(x), __float2bfloat16(y));
    return *(uint32_t*)&h;
}
__device__ __forceinline__ uint32_t pack_lo2(float x, float y) {
    float hx = __bfloat162float(__float2bfloat16(x));
    float hy = __bfloat162float(__float2bfloat16(y));
    __nv_bfloat162 l(__float2bfloat16(x - hx), __float2bfloat16(y - hy));
    return *(uint32_t*)&l;
}

// ---------------------------------------------------------------------------
// Split-precision HMMA GEMM (unchanged from R3/R4 passing version)
// ---------------------------------------------------------------------------
#define GBK   32
#define SROW  40
#define MATB  (128 * SROW * 2)
#define STAGEB (4 * MATB)
#define GEMM_SMEM (2 * STAGEB)

__global__ __launch_bounds__(256)
void gemm_mma(const __nv_bfloat16* __restrict__ Ah,
              const __nv_bfloat16* __restrict__ Al,
              const __nv_bfloat16* __restrict__ Bh,
              const __nv_bfloat16* __restrict__ Bl,
              float* __restrict__ C, int M, int N, int K)
{
    extern __shared__ char sm[];
    const uint32_t sb = smem_u32(sm);
    const int tid  = threadIdx.x;
    const int wid  = tid >> 5;
    const int lane = tid & 31;
    const int wm = wid & 3;
    const int wn = wid >> 2;
    const int g  = lane >> 2;
    const int tg = lane & 3;

    const int m0 = blockIdx.y * 128;
    const int n0 = blockIdx.x * 128;

    auto load_stage = [&](int k0, int st) {
        const uint32_t base = sb + st * STAGEB;
#pragma unroll
        for (int mat = 0; mat < 4; mat++) {
            const __nv_bfloat16* src =
                (mat == 0) ? Ah : (mat == 1) ? Al : (mat == 2) ? Bh : Bl;
            const int row0 = (mat < 2) ? m0 : n0;
#pragma unroll
            for (int hh = 0; hh < 2; hh++) {
                int unit = tid + hh * 256;
                int r = unit >> 2, u = unit & 3;
                const void* gp = src + (size_t)(row0 + r) * K + k0 + u * 8;
                cp16(base + mat * MATB + r * (SROW * 2) + u * 16, gp);
            }
        }
    };

    float acc[2][8][4];
#pragma unroll
    for (int mt = 0; mt < 2; mt++)
#pragma unroll
        for (int nt = 0; nt < 8; nt++)
#pragma unroll
            for (int j = 0; j < 4; j++) acc[mt][nt][j] = 0.f;

    const int NIT = K / GBK;
    load_stage(0, 0);
    CP_COMMIT();

    for (int it = 0; it < NIT; it++) {
        CP_WAIT0();
        __syncthreads();
        const int st = it & 1;
        if (it + 1 < NIT) {
            load_stage((it + 1) * GBK, st ^ 1);
            CP_COMMIT();
        }

        const uint32_t ahb = sb + st * STAGEB;
        const uint32_t alb = ahb + MATB;
        const uint32_t bhb = ahb + 2 * MATB;
        const uint32_t blb = ahb + 3 * MATB;

#pragma unroll
        for (int ks = 0; ks < 2; ks++) {
            const int c0 = ks * 16 + tg * 2;
            uint32_t ah[2][4], al[2][4];
#pragma unroll
            for (int mt = 0; mt < 2; mt++) {
                const int r0 = wm * 32 + mt * 16 + g;
                const uint32_t o00 = (uint32_t)((r0 * SROW + c0) * 2);
                const uint32_t o10 = (uint32_t)(((r0 + 8) * SROW + c0) * 2);
                ah[mt][0] = lds32(ahb + o00);
                ah[mt][1] = lds32(ahb + o10);
                ah[mt][2] = lds32(ahb + o00 + 16);
                ah[mt][3] = lds32(ahb + o10 + 16);
                al[mt][0] = lds32(alb + o00);
                al[mt][1] = lds32(alb + o10);
                al[mt][2] = lds32(alb + o00 + 16);
                al[mt][3] = lds32(alb + o10 + 16);
            }
#pragma unroll
            for (int nt = 0; nt < 8; nt++) {
                const int r0 = wn * 64 + nt * 8 + g;
                const uint32_t bo = (uint32_t)((r0 * SROW + c0) * 2);
                uint32_t bh2[2], bl2[2];
                bh2[0] = lds32(bhb + bo);
                bh2[1] = lds32(bhb + bo + 16);
                bl2[0] = lds32(blb + bo);
                bl2[1] = lds32(blb + bo + 16);
#pragma unroll
                for (int mt = 0; mt < 2; mt++) {
                    mma16816(acc[mt][nt], ah[mt], bh2);
                    mma16816(acc[mt][nt], ah[mt], bl2);
                    mma16816(acc[mt][nt], al[mt], bh2);
                }
            }
        }
    }

#pragma unroll
    for (int mt = 0; mt < 2; mt++) {
        const int r0 = m0 + wm * 32 + mt * 16 + g;
#pragma unroll
        for (int nt = 0; nt < 8; nt++) {
            const int cc = n0 + wn * 64 + nt * 8 + tg * 2;
            float2 w0 = make_float2(acc[mt][nt][0], acc[mt][nt][1]);
            float2 w1 = make_float2(acc[mt][nt][2], acc[mt][nt][3]);
            *(float2*)(C + (size_t)r0 * N + cc)       = w0;
            *(float2*)(C + (size_t)(r0 + 8) * N + cc) = w1;
        }
    }
}

// ---------------------------------------------------------------------------
// Split fp32 -> (hi, lo) bf16 (A operand prep for GEMM1)
// ---------------------------------------------------------------------------
__global__ void split_a_kernel(const float* __restrict__ X,
                               __nv_bfloat16* __restrict__ Xh,
                               __nv_bfloat16* __restrict__ Xl, int n4)
{
    int i = blockIdx.x * blockDim.x + threadIdx.x;
    if (i >= n4) return;
    float4 v = ((const float4*)X)[i];
    ((uint32_t*)Xh)[i * 2 + 0] = pack_hi2(v.x, v.y);
    ((uint32_t*)Xh)[i * 2 + 1] = pack_hi2(v.z, v.w);
    ((uint32_t*)Xl)[i * 2 + 0] = pack_lo2(v.x, v.y);
    ((uint32_t*)Xl)[i * 2 + 1] = pack_lo2(v.z, v.w);
}

// ---------------------------------------------------------------------------
// Split + transpose: B fp32 [K,N] -> BhT/BlT bf16 [N,K]
// ---------------------------------------------------------------------------
__global__ void split_bt_kernel(const float* __restrict__ B,
                                __nv_bfloat16* __restrict__ BhT,
                                __nv_bfloat16* __restrict__ BlT, int K, int N)
{
    __shared__ float th[32][33];
    __shared__ float tl[32][33];
    const int tx = threadIdx.x, ty = threadIdx.y;
    const int n0 = blockIdx.x * 32, k0 = blockIdx.y * 32;
#pragma unroll
    for (int i = 0; i < 4; i++) {
        int k = ty + i * 8;
        float v = B[(size_t)(k0 + k) * N + n0 + tx];
        float hi = __bfloat162float(__float2bfloat16(v));
        th[k][tx] = hi;
        tl[k][tx] = v - hi;
    }
    __syncthreads();
#pragma unroll
    for (int i = 0; i < 4; i++) {
        int n = ty + i * 8;
        BhT[(size_t)(n0 + n) * K + k0 + tx] = __float2bfloat16(th[tx][n]);
        BlT[(size_t)(n0 + n) * K + k0 + tx] = __float2bfloat16(tl[tx][n]);
    }
}

// ---------------------------------------------------------------------------
// RoPE for Q -> split bf16
// ---------------------------------------------------------------------------
__global__ void rope_q_kernel(const float* __restrict__ qkv,
                              const int* __restrict__ positions,
                              __nv_bfloat16* __restrict__ Qh,
                              __nv_bfloat16* __restrict__ Ql)
{
    int idx = blockIdx.x * blockDim.x + threadIdx.x;
    int i  = idx & 63;
    int h  = (idx >> 6) & 31;
    int bs = idx >> 11;
    if (bs >= BSc) return;

    const float* src = qkv + (size_t)bs * QKVF + h * Dc;
    float x1 = src[i], x2 = src[i + 64];
    float pos = (float)positions[bs];
    float inv = 1.0f / powf(10000.0f, (float)i * (1.0f / 64.0f));
    float ang = pos * inv;
    float sn, cs;
    sincosf(ang, &sn, &cs);
    float y1 = x1 * cs - x2 * sn;
    float y2 = x2 * cs + x1 * sn;

    size_t o = (size_t)bs * (Hc * Dc) + h * Dc;
    __nv_bfloat16 h1 = __float2bfloat16(y1);
    __nv_bfloat16 h2 = __float2bfloat16(y2);
    Qh[o + i]      = h1;
    Qh[o + i + 64] = h2;
    Ql[o + i]      = __float2bfloat16(y1 - __bfloat162float(h1));
    Ql[o + i + 64] = __float2bfloat16(y2 - __bfloat162float(h2));
}

// ---------------------------------------------------------------------------
// Smooth conv + RoPE for K -> split bf16
// ---------------------------------------------------------------------------
__global__ void smooth_rope_k_kernel(const float* __restrict__ qkv,
                                     const int* __restrict__ positions,
                                     const float* __restrict__ conv_k,
                                     __nv_bfloat16* __restrict__ Kh,
                                     __nv_bfloat16* __restrict__ Kl)
{
    int idx = blockIdx.x * blockDim.x + threadIdx.x;
    int i  = idx & 63;
    int kv = (idx >> 6) & 7;
    int bs = idx >> 9;
    if (bs >= BSc) return;
    int s = bs & (Sc - 1);

    const float* src = qkv + (size_t)bs * QKVF + Hc * Dc + kv * Dc;
    float c1 = src[i], c2 = src[i + 64];
    float p1 = 0.f, p2 = 0.f;
    if (s > 0) {
        const float* ps = src - QKVF;
        p1 = ps[i]; p2 = ps[i + 64];
    }
    float f0 = conv_k[kv], f1 = conv_k[KVc + kv];
    float x1 = c1 * f1 + p1 * f0;
    float x2 = c2 * f1 + p2 * f0;

    float pos = (float)positions[bs];
    float inv = 1.0f / powf(10000.0f, (float)i * (1.0f / 64.0f));
    float ang = pos * inv;
    float sn, cs;
    sincosf(ang, &sn, &cs);
    float y1 = x1 * cs - x2 * sn;
    float y2 = x2 * cs + x1 * sn;

    size_t o = ((size_t)bs * KVc + kv) * Dc;
    __nv_bfloat16 h1 = __float2bfloat16(y1);
    __nv_bfloat16 h2 = __float2bfloat16(y2);
    Kh[o + i]      = h1;
    Kh[o + i + 64] = h2;
    Kl[o + i]      = __float2bfloat16(y1 - __bfloat162float(h1));
    Kl[o + i + 64] = __float2bfloat16(y2 - __bfloat162float(h2));
}

// ---------------------------------------------------------------------------
// Smooth conv for V + transpose -> split bf16 Vt [b][kv][d][s]
// ---------------------------------------------------------------------------
__global__ void smooth_v_t_kernel(const float* __restrict__ qkv,
                                  const float* __restrict__ conv_v,
                                  __nv_bfloat16* __restrict__ Vth,
                                  __nv_bfloat16* __restrict__ Vtl)
{
    __shared__ float t[32][33];
    const int tx = threadIdx.x, ty = threadIdx.y;
    const int s0 = blockIdx.x * 32;
    const int d0 = blockIdx.y * 32;
    const int b  = blockIdx.z >> 3;
    const int kv = blockIdx.z & 7;

    const float f0 = conv_v[kv], f1 = conv_v[KVc + kv];
    const size_t voff = (size_t)(Hc + KVc) * Dc + kv * Dc + d0;

#pragma unroll
    for (int i = 0; i < 4; i++) {
        int sl = ty + i * 8;
        int s = s0 + sl;
        const float* src = qkv + (size_t)(b * Sc + s) * QKVF + voff;
        float cur = src[tx];
        float prv = (s > 0) ? src[tx - QKVF] : 0.f;
        t[sl][tx] = cur * f1 + prv * f0;
    }
    __syncthreads();
#pragma unroll
    for (int i = 0; i < 4; i++) {
        int dl = ty + i * 8;
        float v = t[tx][dl];
        __nv_bfloat16 hi = __float2bfloat16(v);
        size_t o = (((size_t)(b * KVc + kv)) * Dc + d0 + dl) * Sc + s0 + tx;
        Vth[o] = hi;
        Vtl[o] = __float2bfloat16(v - __bfloat162float(hi));
    }
}

// ---------------------------------------------------------------------------
// Register-resident windowed flash attention on HMMA.
// CTA = 128 queries x (head, batch). 8 warps; warp w owns rows [16w, 16w+16).
// Each warp computes full 64-key score rows -> softmax in registers ->
// P fragments reused directly as PV A-operand (no smem round trip).
// K/V tiles double-buffered via cp.async. Output -> split bf16 GEMM2 A.
// ---------------------------------------------------------------------------
#define RQK  272                 // Q/K smem row stride bytes (128 bf16 + pad)
#define RPV  144                 // Vt smem row stride bytes  (64 bf16 + pad)

#define A_QH   0
#define A_QL   (A_QH + 128 * RQK)                   // 34816
#define A_ST0  (A_QL + 128 * RQK)                   // 69632
#define KV_STAGE (2 * 64 * RQK + 2 * 128 * RPV)     // 71680
// within stage: KH(64*RQK) KL(64*RQK) VH(128*RPV) VL(128*RPV)
#define ST_KH  0
#define ST_KL  (64 * RQK)
#define ST_VH  (2 * 64 * RQK)
#define ST_VL  (2 * 64 * RQK + 128 * RPV)
#define ATTN_SMEM (A_ST0 + 2 * KV_STAGE)            // 212992

__global__ __launch_bounds__(256)
void attn_mma(const __nv_bfloat16* __restrict__ Qh, const __nv_bfloat16* __restrict__ Ql,
              const __nv_bfloat16* __restrict__ Kh, const __nv_bfloat16* __restrict__ Kl,
              const __nv_bfloat16* __restrict__ Vth, const __nv_bfloat16* __restrict__ Vtl,
              __nv_bfloat16* __restrict__ Oh, __nv_bfloat16* __restrict__ Ol)
{
    extern __shared__ char sm[];
    const uint32_t sb = smem_u32(sm);

    const int tid  = threadIdx.x;
    const int w    = tid >> 5;
    const int lane = tid & 31;
    const int g  = lane >> 2;
    const int tg = lane & 3;

    const int qt = blockIdx.x, h = blockIdx.y, b = blockIdx.z;
    const int q0 = qt * 128;
    const int kvh = h >> 2;
    const float scale = 0.08838834764831845f;

    // ---- load Q tile (128 rows x 128 bf16, hi/lo) via cp.async ----
    {
        const size_t qbase = ((size_t)(b * Sc + q0) * Hc + h) * Dc;
#pragma unroll
        for (int hh = 0; hh < 8; hh++) {
            int idx = tid + hh * 256;         // 2048 units
            int r = idx >> 4, u = idx & 15;
            const size_t go = qbase + (size_t)r * (Hc * Dc) + u * 8;
            cp16(sb + A_QH + r * RQK + u * 16, Qh + go);
            cp16(sb + A_QL + r * RQK + u * 16, Ql + go);
        }
    }

    // K/V tile loader into stage st
    const size_t kbase = ((size_t)b * Sc * KVc + kvh) * Dc;   // + s*KVc*Dc
    const size_t vbase = ((size_t)(b * KVc + kvh)) * Dc * Sc; // + d*Sc + s
    auto load_kv = [&](int kt, int st) {
        const int k0 = kt * 64;
        const uint32_t stb = sb + A_ST0 + st * KV_STAGE;
#pragma unroll
        for (int hh = 0; hh < 4; hh++) {
            int idx = tid + hh * 256;         // 1024 units (64 rows x 16)
            int r = idx >> 4, u = idx & 15;
            const size_t go = kbase + (size_t)(k0 + r) * (KVc * Dc) + u * 8;
            cp16(stb + ST_KH + r * RQK + u * 16, Kh + go);
            cp16(stb + ST_KL + r * RQK + u * 16, Kl + go);
        }
#pragma unroll
        for (int hh = 0; hh < 4; hh++) {
            int idx = tid + hh * 256;         // 1024 units (128 rows x 8)
            int d = idx >> 3, u = idx & 7;
            const size_t go = vbase + (size_t)d * Sc + k0 + u * 8;
            cp16(stb + ST_VH + d * RPV + u * 16, Vth + go);
            cp16(stb + ST_VL + d * RPV + u * 16, Vtl + go);
        }
    };

    // per-thread softmax state (rows g and g+8 of this warp's 16-row block)
    float m0 = -1e30f, m1 = -1e30f, l0 = 0.f, l1 = 0.f;
    float oacc[16][4];
#pragma unroll
    for (int nt = 0; nt < 16; nt++)
#pragma unroll
        for (int j = 0; j < 4; j++) oacc[nt][j] = 0.f;

    const int qw_lo = q0 + w * 16;        // warp's min query row
    const int qw_hi = qw_lo + 15;         // warp's max query row
    const int qi0 = qw_lo + g;            // this thread's rows
    const int qi1 = qi0 + 8;

    int kt_lo = 2 * qt - 8; if (kt_lo < 0) kt_lo = 0;
    const int kt_hi = 2 * qt + 1;

    load_kv(kt_lo, 0);
    CP_COMMIT();

    for (int kt = kt_lo; kt <= kt_hi; kt++) {
        const int st = (kt - kt_lo) & 1;
        const int k0 = kt * 64;
        CP_WAIT0();
        __syncthreads();
        if (kt < kt_hi) {
            load_kv(kt + 1, st ^ 1);
            CP_COMMIT();
        }

        // per-warp tile skip (outside causal window for all 16 rows)
        if (k0 > qw_hi) continue;                 // all keys in future
        if (k0 + 575 <= qw_lo) continue;          // all keys before window

        const uint32_t stb = sb + A_ST0 + st * KV_STAGE;
        const uint32_t khb = stb + ST_KH;
        const uint32_t klb = stb + ST_KL;
        const uint32_t vhb = stb + ST_VH;
        const uint32_t vlb = stb + ST_VL;

        // ---- scores: 16 rows x 64 keys, 3-term split HMMA ----
        float sacc[8][4];
#pragma unroll
        for (int nt = 0; nt < 8; nt++)
#pragma unroll
            for (int j = 0; j < 4; j++) sacc[nt][j] = 0.f;

#pragma unroll
        for (int ks = 0; ks < 8; ks++) {
            uint32_t aqh[4], aql[4];
            const uint32_t o0 = (uint32_t)((w * 16 + g) * RQK + ks * 32 + tg * 4);
            aqh[0] = lds32(sb + A_QH + o0);
            aqh[1] = lds32(sb + A_QH + o0 + 8 * RQK);
            aqh[2] = lds32(sb + A_QH + o0 + 16);
            aqh[3] = lds32(sb + A_QH + o0 + 8 * RQK + 16);
            aql[0] = lds32(sb + A_QL + o0);
            aql[1] = lds32(sb + A_QL + o0 + 8 * RQK);
            aql[2] = lds32(sb + A_QL + o0 + 16);
            aql[3] = lds32(sb + A_QL + o0 + 8 * RQK + 16);
#pragma unroll
            for (int nt = 0; nt < 8; nt++) {
                const uint32_t bo = (uint32_t)((nt * 8 + g) * RQK + ks * 32 + tg * 4);
                uint32_t bh2[2], bl2[2];
                bh2[0] = lds32(khb + bo);
                bh2[1] = lds32(khb + bo + 16);
                bl2[0] = lds32(klb + bo);
                bl2[1] = lds32(klb + bo + 16);
                mma16816(sacc[nt], aqh, bh2);
                mma16816(sacc[nt], aqh, bl2);
                mma16816(sacc[nt], aql, bh2);
            }
        }

        // ---- scale + mask in registers ----
        const bool fully_valid = (k0 + 63 <= qw_lo) && (k0 >= qw_hi - (Wc - 1));
        if (fully_valid) {
#pragma unroll
            for (int nt = 0; nt < 8; nt++)
#pragma unroll
                for (int j = 0; j < 4; j++) sacc[nt][j] *= scale;
        } else {
#pragma unroll
            for (int nt = 0; nt < 8; nt++) {
                const int ki0 = k0 + nt * 8 + tg * 2, ki1 = ki0 + 1;
                bool m00 = (ki0 <= qi0) && (qi0 - ki0 < Wc);
                bool m01 = (ki1 <= qi0) && (qi0 - ki1 < Wc);
                bool m10 = (ki0 <= qi1) && (qi1 - ki0 < Wc);
                bool m11 = (ki1 <= qi1) && (qi1 - ki1 < Wc);
                sacc[nt][0] = m00 ? sacc[nt][0] * scale : -1e30f;
                sacc[nt][1] = m01 ? sacc[nt][1] * scale : -1e30f;
                sacc[nt][2] = m10 ? sacc[nt][2] * scale : -1e30f;
                sacc[nt][3] = m11 ? sacc[nt][3] * scale : -1e30f;
            }
        }

        // ---- row max via shfl within 4-thread groups ----
        float mx0 = -1e30f, mx1 = -1e30f;
#pragma unroll
        for (int nt = 0; nt < 8; nt++) {
            mx0 = fmaxf(mx0, fmaxf(sacc[nt][0], sacc[nt][1]));
            mx1 = fmaxf(mx1, fmaxf(sacc[nt][2], sacc[nt][3]));
        }
        mx0 = fmaxf(mx0, __shfl_xor_sync(0xffffffffu, mx0, 1));
        mx0 = fmaxf(mx0, __shfl_xor_sync(0xffffffffu, mx0, 2));
        mx1 = fmaxf(mx1, __shfl_xor_sync(0xffffffffu, mx1, 1));
        mx1 = fmaxf(mx1, __shfl_xor_sync(0xffffffffu, mx1, 2));

        const float mn0 = fmaxf(m0, mx0);
        const float mn1 = fmaxf(m1, mx1);
        const float f0 = __expf(m0 - mn0);
        const float f1 = __expf(m1 - mn1);
        m0 = mn0; m1 = mn1;

        // ---- exp + row sums (register fragments) ----
        float s0 = 0.f, s1 = 0.f;
#pragma unroll
        for (int nt = 0; nt < 8; nt++) {
            float p0 = (sacc[nt][0] > -1e29f) ? __expf(sacc[nt][0] - mn0) : 0.f;
            float p1 = (sacc[nt][1] > -1e29f) ? __expf(sacc[nt][1] - mn0) : 0.f;
            float p2 = (sacc[nt][2] > -1e29f) ? __expf(sacc[nt][2] - mn1) : 0.f;
            float p3 = (sacc[nt][3] > -1e29f) ? __expf(sacc[nt][3] - mn1) : 0.f;
            sacc[nt][0] = p0; sacc[nt][1] = p1; sacc[nt][2] = p2; sacc[nt][3] = p3;
            s0 += p0 + p1; s1 += p2 + p3;
        }
        s0 += __shfl_xor_sync(0xffffffffu, s0, 1);
        s0 += __shfl_xor_sync(0xffffffffu, s0, 2);
        s1 += __shfl_xor_sync(0xffffffffu, s1, 1);
        s1 += __shfl_xor_sync(0xffffffffu, s1, 2);
        l0 = l0 * f0 + s0;
        l1 = l1 * f1 + s1;

        // ---- rescale O fragments ----
#pragma unroll
        for (int nt = 0; nt < 16; nt++) {
            oacc[nt][0] *= f0; oacc[nt][1] *= f0;
            oacc[nt][2] *= f1; oacc[nt][3] *= f1;
        }

        // ---- PV: P fragments straight from score accumulators ----
#pragma unroll
        for (int ks = 0; ks < 4; ks++) {
            uint32_t aph[4], apl[4];
            aph[0] = pack_hi2(sacc[2 * ks][0],     sacc[2 * ks][1]);
            aph[1] = pack_hi2(sacc[2 * ks][2],     sacc[2 * ks][3]);
            aph[2] = pack_hi2(sacc[2 * ks + 1][0], sacc[2 * ks + 1][1]);
            aph[3] = pack_hi2(sacc[2 * ks + 1][2], sacc[2 * ks + 1][3]);
            apl[0] = pack_lo2(sacc[2 * ks][0],     sacc[2 * ks][1]);
            apl[1] = pack_lo2(sacc[2 * ks][2],     sacc[2 * ks][3]);
            apl[2] = pack_lo2(sacc[2 * ks + 1][0], sacc[2 * ks + 1][1]);
            apl[3] = pack_lo2(sacc[2 * ks + 1][2], sacc[2 * ks + 1][3]);
#pragma unroll
            for (int nt = 0; nt < 16; nt++) {
                const uint32_t bo = (uint32_t)((nt * 8 + g) * RPV + ks * 32 + tg * 4);
                uint32_t bv[2], bw[2];
                bv[0] = lds32(vhb + bo);
                bv[1] = lds32(vhb + bo + 16);
                bw[0] = lds32(vlb + bo);
                bw[1] = lds32(vlb + bo + 16);
                mma16816(oacc[nt], aph, bv);
                mma16816(oacc[nt], aph, bw);
                mma16816(oacc[nt], apl, bv);
            }
        }
    }

    // ---- epilogue: normalize, split, write GEMM2 A operand ----
    {
        const float linv0 = 1.0f / l0;
        const float linv1 = 1.0f / l1;
        const size_t tok0 = (size_t)(b * Sc + qw_lo + g);
        const size_t tok1 = tok0 + 8;
#pragma unroll
        for (int nt = 0; nt < 16; nt++) {
            const int col = h * Dc + nt * 8 + tg * 2;
            float v00 = oacc[nt][0] * linv0, v01 = oacc[nt][1] * linv0;
            float v10 = oacc[nt][2] * linv1, v11 = oacc[nt][3] * linv1;
            ((uint32_t*)Oh)[(tok0 * HIDc + col) >> 1] = pack_hi2(v00, v01);
            ((uint32_t*)Ol)[(tok0 * HIDc + col) >> 1] = pack_lo2(v00, v01);
            ((uint32_t*)Oh)[(tok1 * HIDc + col) >> 1] = pack_hi2(v10, v11);
            ((uint32_t*)Ol)[(tok1 * HIDc + col) >> 1] = pack_lo2(v10, v11);
        }
    }
}

// ---------------------------------------------------------------------------
// Launch
// ---------------------------------------------------------------------------
extern "C" void kernel_launch(void* const* d_in, const int* in_sizes, int n_in,
                              void* d_out, int out_size)
{
    const float* hidden    = (const float*)d_in[0];
    const int*   positions = (const int*)d_in[1];
    const float* w_pack    = (const float*)d_in[2];
    const float* w_o       = (const float*)d_in[3];
    const float* conv_k    = (const float*)d_in[4];
    const float* conv_v    = (const float*)d_in[5];
    float* out = (float*)d_out;

    float* qkv;
    __nv_bfloat16 *qh, *ql, *kh, *kl, *vth, *vtl, *ah, *al, *bh, *bl;
    cudaGetSymbolAddress((void**)&qkv, g_qkv);
    cudaGetSymbolAddress((void**)&qh,  g_qh);
    cudaGetSymbolAddress((void**)&ql,  g_ql);
    cudaGetSymbolAddress((void**)&kh,  g_kh);
    cudaGetSymbolAddress((void**)&kl,  g_kl);
    cudaGetSymbolAddress((void**)&vth, g_vth);
    cudaGetSymbolAddress((void**)&vtl, g_vtl);
    cudaGetSymbolAddress((void**)&ah,  g_ah);
    cudaGetSymbolAddress((void**)&al,  g_al);
    cudaGetSymbolAddress((void**)&bh,  g_bh);
    cudaGetSymbolAddress((void**)&bl,  g_bl);

    cudaFuncSetAttribute(gemm_mma, cudaFuncAttributeMaxDynamicSharedMemorySize,
                         GEMM_SMEM);
    cudaFuncSetAttribute(attn_mma, cudaFuncAttributeMaxDynamicSharedMemorySize,
                         ATTN_SMEM);

    // ---- GEMM 1: qkv = hidden @ w_pack ----
    {
        int n4 = BSc * HIDc / 4;
        split_a_kernel<<<(n4 + 255) / 256, 256>>>(hidden, ah, al, n4);
        split_bt_kernel<<<dim3(QKVF / 32, HIDc / 32), dim3(32, 8)>>>(w_pack, bh, bl, HIDc, QKVF);
        dim3 g1(QKVF / 128, BSc / 128);
        gemm_mma<<<g1, 256, GEMM_SMEM>>>(ah, al, bh, bl, qkv, BSc, QKVF, HIDc);
    }

    // ---- elementwise prep (emit split bf16 operands) ----
    rope_q_kernel<<<(BSc * Hc * 64) / 256, 256>>>(qkv, positions, qh, ql);
    smooth_rope_k_kernel<<<(BSc * KVc * 64) / 256, 256>>>(qkv, positions, conv_k, kh, kl);
    smooth_v_t_kernel<<<dim3(Sc / 32, Dc / 32, Bc * KVc), dim3(32, 8)>>>(qkv, conv_v, vth, vtl);

    // prep GEMM2 weights early (independent of attention)
    split_bt_kernel<<<dim3(HIDc / 32, HIDc / 32), dim3(32, 8)>>>(w_o, bh, bl, HIDc, HIDc);

    // ---- register-resident windowed attention; writes split A for GEMM2 ----
    attn_mma<<<dim3(Sc / 128, Hc, Bc), 256, ATTN_SMEM>>>(qh, ql, kh, kl, vth, vtl, ah, al);

    // ---- GEMM 2: out = attn @ w_o ----
    {
        dim3 g2(HIDc / 128, BSc / 128);
        gemm_mma<<<g2, 256, GEMM_SMEM>>>(ah, al, bh, bl, out, BSc, HIDc, HIDc);
    }
}

// round 6
// speedup vs baseline: 2.9016x; 1.0459x over previous
#include <cuda_runtime.h>
#include <cuda_bf16.h>
#include <math.h>
#include <stdint.h>

// ---------------------------------------------------------------------------
// Problem constants
// ---------------------------------------------------------------------------
#define Bc    2
#define Sc    2048
#define HIDc  4096
#define Hc    32
#define KVc   8
#define Dc    128
#define Wc    512
#define BSc   (Bc * Sc)              // 4096
#define QKVF  ((Hc + 2 * KVc) * Dc)  // 6144

// ---------------------------------------------------------------------------
// Scratch (static device globals -- no allocation allowed)
// ---------------------------------------------------------------------------
__device__ float g_qkv[(size_t)BSc * QKVF];

__device__ __nv_bfloat16 g_qh[(size_t)BSc * Hc * Dc];
__device__ __nv_bfloat16 g_ql[(size_t)BSc * Hc * Dc];
__device__ __nv_bfloat16 g_kh[(size_t)BSc * KVc * Dc];
__device__ __nv_bfloat16 g_kl[(size_t)BSc * KVc * Dc];
__device__ __nv_bfloat16 g_vth[(size_t)Bc * KVc * Dc * Sc]; // V^T [b][kv][d][s]
__device__ __nv_bfloat16 g_vtl[(size_t)Bc * KVc * Dc * Sc];

__device__ __nv_bfloat16 g_ah[(size_t)BSc * HIDc];
__device__ __nv_bfloat16 g_al[(size_t)BSc * HIDc];
__device__ __nv_bfloat16 g_bh[(size_t)QKVF * HIDc];
__device__ __nv_bfloat16 g_bl[(size_t)QKVF * HIDc];

// ---------------------------------------------------------------------------
// Helpers
// ---------------------------------------------------------------------------
__device__ __forceinline__ uint32_t smem_u32(const void* p) {
    uint32_t a;
    asm("{ .reg .u64 t; cvta.to.shared.u64 t, %1; cvt.u32.u64 %0, t; }"
        : "=r"(a) : "l"(p));
    return a;
}
__device__ __forceinline__ void cp16(uint32_t smem, const void* gmem) {
    asm volatile("cp.async.cg.shared.global [%0], [%1], 16;"
                 :: "r"(smem), "l"(gmem));
}
#define CP_COMMIT() asm volatile("cp.async.commit_group;" ::: "memory")
#define CP_WAIT0()  asm volatile("cp.async.wait_group 0;" ::: "memory")

__device__ __forceinline__ uint32_t lds32(uint32_t addr) {
    uint32_t v;
    asm("ld.shared.b32 %0, [%1];" : "=r"(v) : "r"(addr));
    return v;
}

// bf16 HMMA m16n8k16
__device__ __forceinline__ void mma16816(float* d, const uint32_t* a,
                                         const uint32_t* b) {
    asm volatile(
        "mma.sync.aligned.m16n8k16.row.col.f32.bf16.bf16.f32 "
        "{%0,%1,%2,%3}, {%4,%5,%6,%7}, {%8,%9}, {%0,%1,%2,%3};"
        : "+f"(d[0]), "+f"(d[1]), "+f"(d[2]), "+f"(d[3])
        : "r"(a[0]), "r"(a[1]), "r"(a[2]), "r"(a[3]),
          "r"(b[0]), "r"(b[1]));
}

__device__ __forceinline__ uint32_t pack_hi2(float x, float y) {
    __nv_bfloat162 h(__float2bfloat16(x), __float2bfloat16(y));
    return *(uint32_t*)&h;
}
__device__ __forceinline__ uint32_t pack_lo2(float x, float y) {
    float hx = __bfloat162float(__float2bfloat16(x));
    float hy = __bfloat162float(__float2bfloat16(y));
    __nv_bfloat162 l(__float2bfloat16(x - hx), __float2bfloat16(y - hy));
    return *(uint32_t*)&l;
}

// ---------------------------------------------------------------------------
// Split-precision HMMA GEMM.  Now 2 CTAs/SM (reg-capped) for latency hiding.
// ---------------------------------------------------------------------------
#define GBK   32
#define SROW  40
#define MATB  (128 * SROW * 2)
#define STAGEB (4 * MATB)
#define GEMM_SMEM (2 * STAGEB)

__global__ __launch_bounds__(256, 2)
void gemm_mma(const __nv_bfloat16* __restrict__ Ah,
              const __nv_bfloat16* __restrict__ Al,
              const __nv_bfloat16* __restrict__ Bh,
              const __nv_bfloat16* __restrict__ Bl,
              float* __restrict__ C, int M, int N, int K)
{
    extern __shared__ char sm[];
    const uint32_t sb = smem_u32(sm);
    const int tid  = threadIdx.x;
    const int wid  = tid >> 5;
    const int lane = tid & 31;
    const int wm = wid & 3;
    const int wn = wid >> 2;
    const int g  = lane >> 2;
    const int tg = lane & 3;

    const int m0 = blockIdx.y * 128;
    const int n0 = blockIdx.x * 128;

    auto load_stage = [&](int k0, int st) {
        const uint32_t base = sb + st * STAGEB;
#pragma unroll
        for (int mat = 0; mat < 4; mat++) {
            const __nv_bfloat16* src =
                (mat == 0) ? Ah : (mat == 1) ? Al : (mat == 2) ? Bh : Bl;
            const int row0 = (mat < 2) ? m0 : n0;
#pragma unroll
            for (int hh = 0; hh < 2; hh++) {
                int unit = tid + hh * 256;
                int r = unit >> 2, u = unit & 3;
                const void* gp = src + (size_t)(row0 + r) * K + k0 + u * 8;
                cp16(base + mat * MATB + r * (SROW * 2) + u * 16, gp);
            }
        }
    };

    float acc[2][8][4];
#pragma unroll
    for (int mt = 0; mt < 2; mt++)
#pragma unroll
        for (int nt = 0; nt < 8; nt++)
#pragma unroll
            for (int j = 0; j < 4; j++) acc[mt][nt][j] = 0.f;

    const int NIT = K / GBK;
    load_stage(0, 0);
    CP_COMMIT();

    for (int it = 0; it < NIT; it++) {
        CP_WAIT0();
        __syncthreads();
        const int st = it & 1;
        if (it + 1 < NIT) {
            load_stage((it + 1) * GBK, st ^ 1);
            CP_COMMIT();
        }

        const uint32_t ahb = sb + st * STAGEB;
        const uint32_t alb = ahb + MATB;
        const uint32_t bhb = ahb + 2 * MATB;
        const uint32_t blb = ahb + 3 * MATB;

#pragma unroll
        for (int ks = 0; ks < 2; ks++) {
            const int c0 = ks * 16 + tg * 2;
            uint32_t ah[2][4], al[2][4];
#pragma unroll
            for (int mt = 0; mt < 2; mt++) {
                const int r0 = wm * 32 + mt * 16 + g;
                const uint32_t o00 = (uint32_t)((r0 * SROW + c0) * 2);
                const uint32_t o10 = (uint32_t)(((r0 + 8) * SROW + c0) * 2);
                ah[mt][0] = lds32(ahb + o00);
                ah[mt][1] = lds32(ahb + o10);
                ah[mt][2] = lds32(ahb + o00 + 16);
                ah[mt][3] = lds32(ahb + o10 + 16);
                al[mt][0] = lds32(alb + o00);
                al[mt][1] = lds32(alb + o10);
                al[mt][2] = lds32(alb + o00 + 16);
                al[mt][3] = lds32(alb + o10 + 16);
            }
#pragma unroll
            for (int nt = 0; nt < 8; nt++) {
                const int r0 = wn * 64 + nt * 8 + g;
                const uint32_t bo = (uint32_t)((r0 * SROW + c0) * 2);
                uint32_t bh2[2], bl2[2];
                bh2[0] = lds32(bhb + bo);
                bh2[1] = lds32(bhb + bo + 16);
                bl2[0] = lds32(blb + bo);
                bl2[1] = lds32(blb + bo + 16);
#pragma unroll
                for (int mt = 0; mt < 2; mt++) {
                    mma16816(acc[mt][nt], ah[mt], bh2);
                    mma16816(acc[mt][nt], ah[mt], bl2);
                    mma16816(acc[mt][nt], al[mt], bh2);
                }
            }
        }
    }

#pragma unroll
    for (int mt = 0; mt < 2; mt++) {
        const int r0 = m0 + wm * 32 + mt * 16 + g;
#pragma unroll
        for (int nt = 0; nt < 8; nt++) {
            const int cc = n0 + wn * 64 + nt * 8 + tg * 2;
            float2 w0 = make_float2(acc[mt][nt][0], acc[mt][nt][1]);
            float2 w1 = make_float2(acc[mt][nt][2], acc[mt][nt][3]);
            *(float2*)(C + (size_t)r0 * N + cc)       = w0;
            *(float2*)(C + (size_t)(r0 + 8) * N + cc) = w1;
        }
    }
}

// ---------------------------------------------------------------------------
// Split fp32 -> (hi, lo) bf16 (A operand prep for GEMM1)
// ---------------------------------------------------------------------------
__global__ void split_a_kernel(const float* __restrict__ X,
                               __nv_bfloat16* __restrict__ Xh,
                               __nv_bfloat16* __restrict__ Xl, int n4)
{
    int i = blockIdx.x * blockDim.x + threadIdx.x;
    if (i >= n4) return;
    float4 v = ((const float4*)X)[i];
    ((uint32_t*)Xh)[i * 2 + 0] = pack_hi2(v.x, v.y);
    ((uint32_t*)Xh)[i * 2 + 1] = pack_hi2(v.z, v.w);
    ((uint32_t*)Xl)[i * 2 + 0] = pack_lo2(v.x, v.y);
    ((uint32_t*)Xl)[i * 2 + 1] = pack_lo2(v.z, v.w);
}

// ---------------------------------------------------------------------------
// Split + transpose: B fp32 [K,N] -> BhT/BlT bf16 [N,K]
// ---------------------------------------------------------------------------
__global__ void split_bt_kernel(const float* __restrict__ B,
                                __nv_bfloat16* __restrict__ BhT,
                                __nv_bfloat16* __restrict__ BlT, int K, int N)
{
    __shared__ float th[32][33];
    __shared__ float tl[32][33];
    const int tx = threadIdx.x, ty = threadIdx.y;
    const int n0 = blockIdx.x * 32, k0 = blockIdx.y * 32;
#pragma unroll
    for (int i = 0; i < 4; i++) {
        int k = ty + i * 8;
        float v = B[(size_t)(k0 + k) * N + n0 + tx];
        float hi = __bfloat162float(__float2bfloat16(v));
        th[k][tx] = hi;
        tl[k][tx] = v - hi;
    }
    __syncthreads();
#pragma unroll
    for (int i = 0; i < 4; i++) {
        int n = ty + i * 8;
        BhT[(size_t)(n0 + n) * K + k0 + tx] = __float2bfloat16(th[tx][n]);
        BlT[(size_t)(n0 + n) * K + k0 + tx] = __float2bfloat16(tl[tx][n]);
    }
}

// ---------------------------------------------------------------------------
// RoPE for Q -> split bf16
// ---------------------------------------------------------------------------
__global__ void rope_q_kernel(const float* __restrict__ qkv,
                              const int* __restrict__ positions,
                              __nv_bfloat16* __restrict__ Qh,
                              __nv_bfloat16* __restrict__ Ql)
{
    int idx = blockIdx.x * blockDim.x + threadIdx.x;
    int i  = idx & 63;
    int h  = (idx >> 6) & 31;
    int bs = idx >> 11;
    if (bs >= BSc) return;

    const float* src = qkv + (size_t)bs * QKVF + h * Dc;
    float x1 = src[i], x2 = src[i + 64];
    float pos = (float)positions[bs];
    float inv = 1.0f / powf(10000.0f, (float)i * (1.0f / 64.0f));
    float ang = pos * inv;
    float sn, cs;
    sincosf(ang, &sn, &cs);
    float y1 = x1 * cs - x2 * sn;
    float y2 = x2 * cs + x1 * sn;

    size_t o = (size_t)bs * (Hc * Dc) + h * Dc;
    __nv_bfloat16 h1 = __float2bfloat16(y1);
    __nv_bfloat16 h2 = __float2bfloat16(y2);
    Qh[o + i]      = h1;
    Qh[o + i + 64] = h2;
    Ql[o + i]      = __float2bfloat16(y1 - __bfloat162float(h1));
    Ql[o + i + 64] = __float2bfloat16(y2 - __bfloat162float(h2));
}

// ---------------------------------------------------------------------------
// Smooth conv + RoPE for K -> split bf16
// ---------------------------------------------------------------------------
__global__ void smooth_rope_k_kernel(const float* __restrict__ qkv,
                                     const int* __restrict__ positions,
                                     const float* __restrict__ conv_k,
                                     __nv_bfloat16* __restrict__ Kh,
                                     __nv_bfloat16* __restrict__ Kl)
{
    int idx = blockIdx.x * blockDim.x + threadIdx.x;
    int i  = idx & 63;
    int kv = (idx >> 6) & 7;
    int bs = idx >> 9;
    if (bs >= BSc) return;
    int s = bs & (Sc - 1);

    const float* src = qkv + (size_t)bs * QKVF + Hc * Dc + kv * Dc;
    float c1 = src[i], c2 = src[i + 64];
    float p1 = 0.f, p2 = 0.f;
    if (s > 0) {
        const float* ps = src - QKVF;
        p1 = ps[i]; p2 = ps[i + 64];
    }
    float f0 = conv_k[kv], f1 = conv_k[KVc + kv];
    float x1 = c1 * f1 + p1 * f0;
    float x2 = c2 * f1 + p2 * f0;

    float pos = (float)positions[bs];
    float inv = 1.0f / powf(10000.0f, (float)i * (1.0f / 64.0f));
    float ang = pos * inv;
    float sn, cs;
    sincosf(ang, &sn, &cs);
    float y1 = x1 * cs - x2 * sn;
    float y2 = x2 * cs + x1 * sn;

    size_t o = ((size_t)bs * KVc + kv) * Dc;
    __nv_bfloat16 h1 = __float2bfloat16(y1);
    __nv_bfloat16 h2 = __float2bfloat16(y2);
    Kh[o + i]      = h1;
    Kh[o + i + 64] = h2;
    Kl[o + i]      = __float2bfloat16(y1 - __bfloat162float(h1));
    Kl[o + i + 64] = __float2bfloat16(y2 - __bfloat162float(h2));
}

// ---------------------------------------------------------------------------
// Smooth conv for V + transpose -> split bf16 Vt [b][kv][d][s]
// ---------------------------------------------------------------------------
__global__ void smooth_v_t_kernel(const float* __restrict__ qkv,
                                  const float* __restrict__ conv_v,
                                  __nv_bfloat16* __restrict__ Vth,
                                  __nv_bfloat16* __restrict__ Vtl)
{
    __shared__ float t[32][33];
    const int tx = threadIdx.x, ty = threadIdx.y;
    const int s0 = blockIdx.x * 32;
    const int d0 = blockIdx.y * 32;
    const int b  = blockIdx.z >> 3;
    const int kv = blockIdx.z & 7;

    const float f0 = conv_v[kv], f1 = conv_v[KVc + kv];
    const size_t voff = (size_t)(Hc + KVc) * Dc + kv * Dc + d0;

#pragma unroll
    for (int i = 0; i < 4; i++) {
        int sl = ty + i * 8;
        int s = s0 + sl;
        const float* src = qkv + (size_t)(b * Sc + s) * QKVF + voff;
        float cur = src[tx];
        float prv = (s > 0) ? src[tx - QKVF] : 0.f;
        t[sl][tx] = cur * f1 + prv * f0;
    }
    __syncthreads();
#pragma unroll
    for (int i = 0; i < 4; i++) {
        int dl = ty + i * 8;
        float v = t[tx][dl];
        __nv_bfloat16 hi = __float2bfloat16(v);
        size_t o = (((size_t)(b * KVc + kv)) * Dc + d0 + dl) * Sc + s0 + tx;
        Vth[o] = hi;
        Vtl[o] = __float2bfloat16(v - __bfloat162float(hi));
    }
}

// ---------------------------------------------------------------------------
// Register-resident windowed flash attention on HMMA.
// Q fragments preloaded into registers (reused across all k-tiles).
// ---------------------------------------------------------------------------
#define RQK  272                 // Q/K smem row stride bytes (128 bf16 + pad)
#define RPV  144                 // Vt smem row stride bytes  (64 bf16 + pad)

#define A_QH   0
#define A_QL   (A_QH + 128 * RQK)
#define A_ST0  (A_QL + 128 * RQK)
#define KV_STAGE (2 * 64 * RQK + 2 * 128 * RPV)
#define ST_KH  0
#define ST_KL  (64 * RQK)
#define ST_VH  (2 * 64 * RQK)
#define ST_VL  (2 * 64 * RQK + 128 * RPV)
#define ATTN_SMEM (A_ST0 + 2 * KV_STAGE)            // 212992

__global__ __launch_bounds__(256)
void attn_mma(const __nv_bfloat16* __restrict__ Qh, const __nv_bfloat16* __restrict__ Ql,
              const __nv_bfloat16* __restrict__ Kh, const __nv_bfloat16* __restrict__ Kl,
              const __nv_bfloat16* __restrict__ Vth, const __nv_bfloat16* __restrict__ Vtl,
              __nv_bfloat16* __restrict__ Oh, __nv_bfloat16* __restrict__ Ol)
{
    extern __shared__ char sm[];
    const uint32_t sb = smem_u32(sm);

    const int tid  = threadIdx.x;
    const int w    = tid >> 5;
    const int lane = tid & 31;
    const int g  = lane >> 2;
    const int tg = lane & 3;

    const int qt = blockIdx.x, h = blockIdx.y, b = blockIdx.z;
    const int q0 = qt * 128;
    const int kvh = h >> 2;
    const float scale = 0.08838834764831845f;

    // ---- load Q tile (128 rows x 128 bf16, hi/lo) via cp.async ----
    {
        const size_t qbase = ((size_t)(b * Sc + q0) * Hc + h) * Dc;
#pragma unroll
        for (int hh = 0; hh < 8; hh++) {
            int idx = tid + hh * 256;
            int r = idx >> 4, u = idx & 15;
            const size_t go = qbase + (size_t)r * (Hc * Dc) + u * 8;
            cp16(sb + A_QH + r * RQK + u * 16, Qh + go);
            cp16(sb + A_QL + r * RQK + u * 16, Ql + go);
        }
    }

    const size_t kbase = ((size_t)b * Sc * KVc + kvh) * Dc;
    const size_t vbase = ((size_t)(b * KVc + kvh)) * Dc * Sc;
    auto load_kv = [&](int kt, int st) {
        const int k0 = kt * 64;
        const uint32_t stb = sb + A_ST0 + st * KV_STAGE;
#pragma unroll
        for (int hh = 0; hh < 4; hh++) {
            int idx = tid + hh * 256;
            int r = idx >> 4, u = idx & 15;
            const size_t go = kbase + (size_t)(k0 + r) * (KVc * Dc) + u * 8;
            cp16(stb + ST_KH + r * RQK + u * 16, Kh + go);
            cp16(stb + ST_KL + r * RQK + u * 16, Kl + go);
        }
#pragma unroll
        for (int hh = 0; hh < 4; hh++) {
            int idx = tid + hh * 256;
            int d = idx >> 3, u = idx & 7;
            const size_t go = vbase + (size_t)d * Sc + k0 + u * 8;
            cp16(stb + ST_VH + d * RPV + u * 16, Vth + go);
            cp16(stb + ST_VL + d * RPV + u * 16, Vtl + go);
        }
    };

    float m0 = -1e30f, m1 = -1e30f, l0 = 0.f, l1 = 0.f;
    float oacc[16][4];
#pragma unroll
    for (int nt = 0; nt < 16; nt++)
#pragma unroll
        for (int j = 0; j < 4; j++) oacc[nt][j] = 0.f;

    const int qw_lo = q0 + w * 16;
    const int qw_hi = qw_lo + 15;
    const int qi0 = qw_lo + g;
    const int qi1 = qi0 + 8;

    int kt_lo = 2 * qt - 8; if (kt_lo < 0) kt_lo = 0;
    const int kt_hi = 2 * qt + 1;

    load_kv(kt_lo, 0);
    CP_COMMIT();

    // Q fragments, preloaded once after the first wait
    uint32_t qfh[8][4], qfl[8][4];

    for (int kt = kt_lo; kt <= kt_hi; kt++) {
        const int st = (kt - kt_lo) & 1;
        const int k0 = kt * 64;
        CP_WAIT0();
        __syncthreads();

        if (kt == kt_lo) {
            // one-time Q fragment preload from smem into registers
#pragma unroll
            for (int ks = 0; ks < 8; ks++) {
                const uint32_t o0 = (uint32_t)((w * 16 + g) * RQK + ks * 32 + tg * 4);
                qfh[ks][0] = lds32(sb + A_QH + o0);
                qfh[ks][1] = lds32(sb + A_QH + o0 + 8 * RQK);
                qfh[ks][2] = lds32(sb + A_QH + o0 + 16);
                qfh[ks][3] = lds32(sb + A_QH + o0 + 8 * RQK + 16);
                qfl[ks][0] = lds32(sb + A_QL + o0);
                qfl[ks][1] = lds32(sb + A_QL + o0 + 8 * RQK);
                qfl[ks][2] = lds32(sb + A_QL + o0 + 16);
                qfl[ks][3] = lds32(sb + A_QL + o0 + 8 * RQK + 16);
            }
        }

        if (kt < kt_hi) {
            load_kv(kt + 1, st ^ 1);
            CP_COMMIT();
        }

        if (k0 > qw_hi) continue;
        if (k0 + 575 <= qw_lo) continue;

        const uint32_t stb = sb + A_ST0 + st * KV_STAGE;
        const uint32_t khb = stb + ST_KH;
        const uint32_t klb = stb + ST_KL;
        const uint32_t vhb = stb + ST_VH;
        const uint32_t vlb = stb + ST_VL;

        // ---- scores ----
        float sacc[8][4];
#pragma unroll
        for (int nt = 0; nt < 8; nt++)
#pragma unroll
            for (int j = 0; j < 4; j++) sacc[nt][j] = 0.f;

#pragma unroll
        for (int ks = 0; ks < 8; ks++) {
#pragma unroll
            for (int nt = 0; nt < 8; nt++) {
                const uint32_t bo = (uint32_t)((nt * 8 + g) * RQK + ks * 32 + tg * 4);
                uint32_t bh2[2], bl2[2];
                bh2[0] = lds32(khb + bo);
                bh2[1] = lds32(khb + bo + 16);
                bl2[0] = lds32(klb + bo);
                bl2[1] = lds32(klb + bo + 16);
                mma16816(sacc[nt], qfh[ks], bh2);
                mma16816(sacc[nt], qfh[ks], bl2);
                mma16816(sacc[nt], qfl[ks], bh2);
            }
        }

        // ---- scale + mask ----
        const bool fully_valid = (k0 + 63 <= qw_lo) && (k0 >= qw_hi - (Wc - 1));
        if (fully_valid) {
#pragma unroll
            for (int nt = 0; nt < 8; nt++)
#pragma unroll
                for (int j = 0; j < 4; j++) sacc[nt][j] *= scale;
        } else {
#pragma unroll
            for (int nt = 0; nt < 8; nt++) {
                const int ki0 = k0 + nt * 8 + tg * 2, ki1 = ki0 + 1;
                bool m00 = (ki0 <= qi0) && (qi0 - ki0 < Wc);
                bool m01 = (ki1 <= qi0) && (qi0 - ki1 < Wc);
                bool m10 = (ki0 <= qi1) && (qi1 - ki0 < Wc);
                bool m11 = (ki1 <= qi1) && (qi1 - ki1 < Wc);
                sacc[nt][0] = m00 ? sacc[nt][0] * scale : -1e30f;
                sacc[nt][1] = m01 ? sacc[nt][1] * scale : -1e30f;
                sacc[nt][2] = m10 ? sacc[nt][2] * scale : -1e30f;
                sacc[nt][3] = m11 ? sacc[nt][3] * scale : -1e30f;
            }
        }

        // ---- row max via shfl ----
        float mx0 = -1e30f, mx1 = -1e30f;
#pragma unroll
        for (int nt = 0; nt < 8; nt++) {
            mx0 = fmaxf(mx0, fmaxf(sacc[nt][0], sacc[nt][1]));
            mx1 = fmaxf(mx1, fmaxf(sacc[nt][2], sacc[nt][3]));
        }
        mx0 = fmaxf(mx0, __shfl_xor_sync(0xffffffffu, mx0, 1));
        mx0 = fmaxf(mx0, __shfl_xor_sync(0xffffffffu, mx0, 2));
        mx1 = fmaxf(mx1, __shfl_xor_sync(0xffffffffu, mx1, 1));
        mx1 = fmaxf(mx1, __shfl_xor_sync(0xffffffffu, mx1, 2));

        const float mn0 = fmaxf(m0, mx0);
        const float mn1 = fmaxf(m1, mx1);
        const float f0 = __expf(m0 - mn0);
        const float f1 = __expf(m1 - mn1);
        m0 = mn0; m1 = mn1;

        // ---- exp + sums ----
        float s0 = 0.f, s1 = 0.f;
#pragma unroll
        for (int nt = 0; nt < 8; nt++) {
            float p0 = (sacc[nt][0] > -1e29f) ? __expf(sacc[nt][0] - mn0) : 0.f;
            float p1 = (sacc[nt][1] > -1e29f) ? __expf(sacc[nt][1] - mn0) : 0.f;
            float p2 = (sacc[nt][2] > -1e29f) ? __expf(sacc[nt][2] - mn1) : 0.f;
            float p3 = (sacc[nt][3] > -1e29f) ? __expf(sacc[nt][3] - mn1) : 0.f;
            sacc[nt][0] = p0; sacc[nt][1] = p1; sacc[nt][2] = p2; sacc[nt][3] = p3;
            s0 += p0 + p1; s1 += p2 + p3;
        }
        s0 += __shfl_xor_sync(0xffffffffu, s0, 1);
        s0 += __shfl_xor_sync(0xffffffffu, s0, 2);
        s1 += __shfl_xor_sync(0xffffffffu, s1, 1);
        s1 += __shfl_xor_sync(0xffffffffu, s1, 2);
        l0 = l0 * f0 + s0;
        l1 = l1 * f1 + s1;

#pragma unroll
        for (int nt = 0; nt < 16; nt++) {
            oacc[nt][0] *= f0; oacc[nt][1] *= f0;
            oacc[nt][2] *= f1; oacc[nt][3] *= f1;
        }

        // ---- PV ----
#pragma unroll
        for (int ks = 0; ks < 4; ks++) {
            uint32_t aph[4], apl[4];
            aph[0] = pack_hi2(sacc[2 * ks][0],     sacc[2 * ks][1]);
            aph[1] = pack_hi2(sacc[2 * ks][2],     sacc[2 * ks][3]);
            aph[2] = pack_hi2(sacc[2 * ks + 1][0], sacc[2 * ks + 1][1]);
            aph[3] = pack_hi2(sacc[2 * ks + 1][2], sacc[2 * ks + 1][3]);
            apl[0] = pack_lo2(sacc[2 * ks][0],     sacc[2 * ks][1]);
            apl[1] = pack_lo2(sacc[2 * ks][2],     sacc[2 * ks][3]);
            apl[2] = pack_lo2(sacc[2 * ks + 1][0], sacc[2 * ks + 1][1]);
            apl[3] = pack_lo2(sacc[2 * ks + 1][2], sacc[2 * ks + 1][3]);
#pragma unroll
            for (int nt = 0; nt < 16; nt++) {
                const uint32_t bo = (uint32_t)((nt * 8 + g) * RPV + ks * 32 + tg * 4);
                uint32_t bv[2], bw[2];
                bv[0] = lds32(vhb + bo);
                bv[1] = lds32(vhb + bo + 16);
                bw[0] = lds32(vlb + bo);
                bw[1] = lds32(vlb + bo + 16);
                mma16816(oacc[nt], aph, bv);
                mma16816(oacc[nt], aph, bw);
                mma16816(oacc[nt], apl, bv);
            }
        }
    }

    // ---- epilogue ----
    {
        const float linv0 = 1.0f / l0;
        const float linv1 = 1.0f / l1;
        const size_t tok0 = (size_t)(b * Sc + qw_lo + g);
        const size_t tok1 = tok0 + 8;
#pragma unroll
        for (int nt = 0; nt < 16; nt++) {
            const int col = h * Dc + nt * 8 + tg * 2;
            float v00 = oacc[nt][0] * linv0, v01 = oacc[nt][1] * linv0;
            float v10 = oacc[nt][2] * linv1, v11 = oacc[nt][3] * linv1;
            ((uint32_t*)Oh)[(tok0 * HIDc + col) >> 1] = pack_hi2(v00, v01);
            ((uint32_t*)Ol)[(tok0 * HIDc + col) >> 1] = pack_lo2(v00, v01);
            ((uint32_t*)Oh)[(tok1 * HIDc + col) >> 1] = pack_hi2(v10, v11);
            ((uint32_t*)Ol)[(tok1 * HIDc + col) >> 1] = pack_lo2(v10, v11);
        }
    }
}

// ---------------------------------------------------------------------------
// Launch
// ---------------------------------------------------------------------------
extern "C" void kernel_launch(void* const* d_in, const int* in_sizes, int n_in,
                              void* d_out, int out_size)
{
    const float* hidden    = (const float*)d_in[0];
    const int*   positions = (const int*)d_in[1];
    const float* w_pack    = (const float*)d_in[2];
    const float* w_o       = (const float*)d_in[3];
    const float* conv_k    = (const float*)d_in[4];
    const float* conv_v    = (const float*)d_in[5];
    float* out = (float*)d_out;

    float* qkv;
    __nv_bfloat16 *qh, *ql, *kh, *kl, *vth, *vtl, *ah, *al, *bh, *bl;
    cudaGetSymbolAddress((void**)&qkv, g_qkv);
    cudaGetSymbolAddress((void**)&qh,  g_qh);
    cudaGetSymbolAddress((void**)&ql,  g_ql);
    cudaGetSymbolAddress((void**)&kh,  g_kh);
    cudaGetSymbolAddress((void**)&kl,  g_kl);
    cudaGetSymbolAddress((void**)&vth, g_vth);
    cudaGetSymbolAddress((void**)&vtl, g_vtl);
    cudaGetSymbolAddress((void**)&ah,  g_ah);
    cudaGetSymbolAddress((void**)&al,  g_al);
    cudaGetSymbolAddress((void**)&bh,  g_bh);
    cudaGetSymbolAddress((void**)&bl,  g_bl);

    cudaFuncSetAttribute(gemm_mma, cudaFuncAttributeMaxDynamicSharedMemorySize,
                         GEMM_SMEM);
    cudaFuncSetAttribute(attn_mma, cudaFuncAttributeMaxDynamicSharedMemorySize,
                         ATTN_SMEM);

    // ---- GEMM 1: qkv = hidden @ w_pack ----
    {
        int n4 = BSc * HIDc / 4;
        split_a_kernel<<<(n4 + 255) / 256, 256>>>(hidden, ah, al, n4);
        split_bt_kernel<<<dim3(QKVF / 32, HIDc / 32), dim3(32, 8)>>>(w_pack, bh, bl, HIDc, QKVF);
        dim3 g1(QKVF / 128, BSc / 128);
        gemm_mma<<<g1, 256, GEMM_SMEM>>>(ah, al, bh, bl, qkv, BSc, QKVF, HIDc);
    }

    // ---- elementwise prep (emit split bf16 operands) ----
    rope_q_kernel<<<(BSc * Hc * 64) / 256, 256>>>(qkv, positions, qh, ql);
    smooth_rope_k_kernel<<<(BSc * KVc * 64) / 256, 256>>>(qkv, positions, conv_k, kh, kl);
    smooth_v_t_kernel<<<dim3(Sc / 32, Dc / 32, Bc * KVc), dim3(32, 8)>>>(qkv, conv_v, vth, vtl);

    // prep GEMM2 weights early (independent of attention)
    split_bt_kernel<<<dim3(HIDc / 32, HIDc / 32), dim3(32, 8)>>>(w_o, bh, bl, HIDc, HIDc);

    // ---- register-resident windowed attention; writes split A for GEMM2 ----
    attn_mma<<<dim3(Sc / 128, Hc, Bc), 256, ATTN_SMEM>>>(qh, ql, kh, kl, vth, vtl, ah, al);

    // ---- GEMM 2: out = attn @ w_o ----
    {
        dim3 g2(HIDc / 128, BSc / 128);
        gemm_mma<<<g2, 256, GEMM_SMEM>>>(ah, al, bh, bl, out, BSc, HIDc, HIDc);
    }
}

// round 7
// speedup vs baseline: 3.1143x; 1.0733x over previous
#include <cuda_runtime.h>
#include <cuda_bf16.h>
#include <math.h>
#include <stdint.h>

// ---------------------------------------------------------------------------
// Problem constants
// ---------------------------------------------------------------------------
#define Bc    2
#define Sc    2048
#define HIDc  4096
#define Hc    32
#define KVc   8
#define Dc    128
#define Wc    512
#define BSc   (Bc * Sc)              // 4096
#define QKVF  ((Hc + 2 * KVc) * Dc)  // 6144

// ---------------------------------------------------------------------------
// Scratch (static device globals -- no allocation allowed)
// ---------------------------------------------------------------------------
__device__ float g_qkv[(size_t)BSc * QKVF];

__device__ __nv_bfloat16 g_qh[(size_t)BSc * Hc * Dc];
__device__ __nv_bfloat16 g_ql[(size_t)BSc * Hc * Dc];
__device__ __nv_bfloat16 g_kh[(size_t)BSc * KVc * Dc];
__device__ __nv_bfloat16 g_kl[(size_t)BSc * KVc * Dc];
__device__ __nv_bfloat16 g_vth[(size_t)Bc * KVc * Dc * Sc]; // V^T [b][kv][d][s]
__device__ __nv_bfloat16 g_vtl[(size_t)Bc * KVc * Dc * Sc];

__device__ __nv_bfloat16 g_ah[(size_t)BSc * HIDc];
__device__ __nv_bfloat16 g_al[(size_t)BSc * HIDc];
__device__ __nv_bfloat16 g_bh[(size_t)QKVF * HIDc];
__device__ __nv_bfloat16 g_bl[(size_t)QKVF * HIDc];

// ---------------------------------------------------------------------------
// Helpers
// ---------------------------------------------------------------------------
__device__ __forceinline__ uint32_t smem_u32(const void* p) {
    uint32_t a;
    asm("{ .reg .u64 t; cvta.to.shared.u64 t, %1; cvt.u32.u64 %0, t; }"
        : "=r"(a) : "l"(p));
    return a;
}
__device__ __forceinline__ void cp16(uint32_t smem, const void* gmem) {
    asm volatile("cp.async.cg.shared.global [%0], [%1], 16;"
                 :: "r"(smem), "l"(gmem));
}
#define CP_COMMIT() asm volatile("cp.async.commit_group;" ::: "memory")
#define CP_WAIT0()  asm volatile("cp.async.wait_group 0;" ::: "memory")

__device__ __forceinline__ uint32_t lds32(uint32_t addr) {
    uint32_t v;
    asm("ld.shared.b32 %0, [%1];" : "=r"(v) : "r"(addr));
    return v;
}
// ldmatrix x4: 4 8x8 bf16 matrices, lane groups of 8 give row addresses
__device__ __forceinline__ void ldsm_x4(uint32_t* r, uint32_t addr) {
    asm volatile("ldmatrix.sync.aligned.m8n8.x4.shared.b16 {%0,%1,%2,%3}, [%4];"
                 : "=r"(r[0]), "=r"(r[1]), "=r"(r[2]), "=r"(r[3]) : "r"(addr));
}

// bf16 HMMA m16n8k16
__device__ __forceinline__ void mma16816(float* d, const uint32_t* a,
                                         const uint32_t* b) {
    asm volatile(
        "mma.sync.aligned.m16n8k16.row.col.f32.bf16.bf16.f32 "
        "{%0,%1,%2,%3}, {%4,%5,%6,%7}, {%8,%9}, {%0,%1,%2,%3};"
        : "+f"(d[0]), "+f"(d[1]), "+f"(d[2]), "+f"(d[3])
        : "r"(a[0]), "r"(a[1]), "r"(a[2]), "r"(a[3]),
          "r"(b[0]), "r"(b[1]));
}

__device__ __forceinline__ uint32_t pack_hi2(float x, float y) {
    __nv_bfloat162 h(__float2bfloat16(x), __float2bfloat16(y));
    return *(uint32_t*)&h;
}
__device__ __forceinline__ uint32_t pack_lo2(float x, float y) {
    float hx = __bfloat162float(__float2bfloat16(x));
    float hy = __bfloat162float(__float2bfloat16(y));
    __nv_bfloat162 l(__float2bfloat16(x - hx), __float2bfloat16(y - hy));
    return *(uint32_t*)&l;
}

// ---------------------------------------------------------------------------
// Split-precision HMMA GEMM.  2 CTAs/SM; ldmatrix fragment loads.
// ---------------------------------------------------------------------------
#define GBK   32
#define SROW  40
#define MATB  (128 * SROW * 2)
#define STAGEB (4 * MATB)
#define GEMM_SMEM (2 * STAGEB)

__global__ __launch_bounds__(256, 2)
void gemm_mma(const __nv_bfloat16* __restrict__ Ah,
              const __nv_bfloat16* __restrict__ Al,
              const __nv_bfloat16* __restrict__ Bh,
              const __nv_bfloat16* __restrict__ Bl,
              float* __restrict__ C, int M, int N, int K)
{
    extern __shared__ char sm[];
    const uint32_t sb = smem_u32(sm);
    const int tid  = threadIdx.x;
    const int wid  = tid >> 5;
    const int lane = tid & 31;
    const int wm = wid & 3;
    const int wn = wid >> 2;
    const int g  = lane >> 2;
    const int tg = lane & 3;

    const int m0 = blockIdx.y * 128;
    const int n0 = blockIdx.x * 128;

    // ldmatrix per-lane address components
    // A (m16k16, x4): mats = {r0-7 k0-7, r8-15 k0-7, r0-7 k8-15, r8-15 k8-15}
    const uint32_t amrow = (lane & 7) + ((lane >> 3) & 1) * 8;
    const uint32_t acol  = (uint32_t)(lane >> 4) * 16;
    // B pair (two n8k16 fragments, x4): mats = {n0-7 k0-7, n0-7 k8-15, n8-15 k0-7, n8-15 k8-15}
    const uint32_t bmrow = (lane & 7) + (uint32_t)(lane >> 4) * 8;
    const uint32_t bcol  = ((lane >> 3) & 1) * 16;

    auto load_stage = [&](int k0, int st) {
        const uint32_t base = sb + st * STAGEB;
#pragma unroll
        for (int mat = 0; mat < 4; mat++) {
            const __nv_bfloat16* src =
                (mat == 0) ? Ah : (mat == 1) ? Al : (mat == 2) ? Bh : Bl;
            const int row0 = (mat < 2) ? m0 : n0;
#pragma unroll
            for (int hh = 0; hh < 2; hh++) {
                int unit = tid + hh * 256;
                int r = unit >> 2, u = unit & 3;
                const void* gp = src + (size_t)(row0 + r) * K + k0 + u * 8;
                cp16(base + mat * MATB + r * (SROW * 2) + u * 16, gp);
            }
        }
    };

    float acc[2][8][4];
#pragma unroll
    for (int mt = 0; mt < 2; mt++)
#pragma unroll
        for (int nt = 0; nt < 8; nt++)
#pragma unroll
            for (int j = 0; j < 4; j++) acc[mt][nt][j] = 0.f;

    const int NIT = K / GBK;
    load_stage(0, 0);
    CP_COMMIT();

    for (int it = 0; it < NIT; it++) {
        CP_WAIT0();
        __syncthreads();
        const int st = it & 1;
        if (it + 1 < NIT) {
            load_stage((it + 1) * GBK, st ^ 1);
            CP_COMMIT();
        }

        const uint32_t ahb = sb + st * STAGEB;
        const uint32_t bhb = ahb + 2 * MATB;

#pragma unroll
        for (int ks = 0; ks < 2; ks++) {
            uint32_t ah[2][4], al[2][4];
#pragma unroll
            for (int mt = 0; mt < 2; mt++) {
                const uint32_t ar = ahb +
                    (uint32_t)((wm * 32 + mt * 16 + amrow) * (SROW * 2)) +
                    (uint32_t)(ks * 32) + acol;
                ldsm_x4(ah[mt], ar);
                ldsm_x4(al[mt], ar + MATB);
            }
#pragma unroll
            for (int ntp = 0; ntp < 4; ntp++) {
                const uint32_t br = bhb +
                    (uint32_t)((wn * 64 + ntp * 16 + bmrow) * (SROW * 2)) +
                    (uint32_t)(ks * 32) + bcol;
                uint32_t bh4[4], bl4[4];
                ldsm_x4(bh4, br);
                ldsm_x4(bl4, br + MATB);
#pragma unroll
                for (int mt = 0; mt < 2; mt++) {
                    mma16816(acc[mt][2 * ntp],     ah[mt], &bh4[0]);
                    mma16816(acc[mt][2 * ntp],     ah[mt], &bl4[0]);
                    mma16816(acc[mt][2 * ntp],     al[mt], &bh4[0]);
                    mma16816(acc[mt][2 * ntp + 1], ah[mt], &bh4[2]);
                    mma16816(acc[mt][2 * ntp + 1], ah[mt], &bl4[2]);
                    mma16816(acc[mt][2 * ntp + 1], al[mt], &bh4[2]);
                }
            }
        }
    }

#pragma unroll
    for (int mt = 0; mt < 2; mt++) {
        const int r0 = m0 + wm * 32 + mt * 16 + g;
#pragma unroll
        for (int nt = 0; nt < 8; nt++) {
            const int cc = n0 + wn * 64 + nt * 8 + tg * 2;
            float2 w0 = make_float2(acc[mt][nt][0], acc[mt][nt][1]);
            float2 w1 = make_float2(acc[mt][nt][2], acc[mt][nt][3]);
            *(float2*)(C + (size_t)r0 * N + cc)       = w0;
            *(float2*)(C + (size_t)(r0 + 8) * N + cc) = w1;
        }
    }
}

// ---------------------------------------------------------------------------
// Split fp32 -> (hi, lo) bf16 (A operand prep for GEMM1)
// ---------------------------------------------------------------------------
__global__ void split_a_kernel(const float* __restrict__ X,
                               __nv_bfloat16* __restrict__ Xh,
                               __nv_bfloat16* __restrict__ Xl, int n4)
{
    int i = blockIdx.x * blockDim.x + threadIdx.x;
    if (i >= n4) return;
    float4 v = ((const float4*)X)[i];
    ((uint32_t*)Xh)[i * 2 + 0] = pack_hi2(v.x, v.y);
    ((uint32_t*)Xh)[i * 2 + 1] = pack_hi2(v.z, v.w);
    ((uint32_t*)Xl)[i * 2 + 0] = pack_lo2(v.x, v.y);
    ((uint32_t*)Xl)[i * 2 + 1] = pack_lo2(v.z, v.w);
}

// ---------------------------------------------------------------------------
// Split + transpose: B fp32 [K,N] -> BhT/BlT bf16 [N,K]
// ---------------------------------------------------------------------------
__global__ void split_bt_kernel(const float* __restrict__ B,
                                __nv_bfloat16* __restrict__ BhT,
                                __nv_bfloat16* __restrict__ BlT, int K, int N)
{
    __shared__ float th[32][33];
    __shared__ float tl[32][33];
    const int tx = threadIdx.x, ty = threadIdx.y;
    const int n0 = blockIdx.x * 32, k0 = blockIdx.y * 32;
#pragma unroll
    for (int i = 0; i < 4; i++) {
        int k = ty + i * 8;
        float v = B[(size_t)(k0 + k) * N + n0 + tx];
        float hi = __bfloat162float(__float2bfloat16(v));
        th[k][tx] = hi;
        tl[k][tx] = v - hi;
    }
    __syncthreads();
#pragma unroll
    for (int i = 0; i < 4; i++) {
        int n = ty + i * 8;
        BhT[(size_t)(n0 + n) * K + k0 + tx] = __float2bfloat16(th[tx][n]);
        BlT[(size_t)(n0 + n) * K + k0 + tx] = __float2bfloat16(tl[tx][n]);
    }
}

// ---------------------------------------------------------------------------
// RoPE for Q -> split bf16
// ---------------------------------------------------------------------------
__global__ void rope_q_kernel(const float* __restrict__ qkv,
                              const int* __restrict__ positions,
                              __nv_bfloat16* __restrict__ Qh,
                              __nv_bfloat16* __restrict__ Ql)
{
    int idx = blockIdx.x * blockDim.x + threadIdx.x;
    int i  = idx & 63;
    int h  = (idx >> 6) & 31;
    int bs = idx >> 11;
    if (bs >= BSc) return;

    const float* src = qkv + (size_t)bs * QKVF + h * Dc;
    float x1 = src[i], x2 = src[i + 64];
    float pos = (float)positions[bs];
    float inv = 1.0f / powf(10000.0f, (float)i * (1.0f / 64.0f));
    float ang = pos * inv;
    float sn, cs;
    sincosf(ang, &sn, &cs);
    float y1 = x1 * cs - x2 * sn;
    float y2 = x2 * cs + x1 * sn;

    size_t o = (size_t)bs * (Hc * Dc) + h * Dc;
    __nv_bfloat16 h1 = __float2bfloat16(y1);
    __nv_bfloat16 h2 = __float2bfloat16(y2);
    Qh[o + i]      = h1;
    Qh[o + i + 64] = h2;
    Ql[o + i]      = __float2bfloat16(y1 - __bfloat162float(h1));
    Ql[o + i + 64] = __float2bfloat16(y2 - __bfloat162float(h2));
}

// ---------------------------------------------------------------------------
// Smooth conv + RoPE for K -> split bf16
// ---------------------------------------------------------------------------
__global__ void smooth_rope_k_kernel(const float* __restrict__ qkv,
                                     const int* __restrict__ positions,
                                     const float* __restrict__ conv_k,
                                     __nv_bfloat16* __restrict__ Kh,
                                     __nv_bfloat16* __restrict__ Kl)
{
    int idx = blockIdx.x * blockDim.x + threadIdx.x;
    int i  = idx & 63;
    int kv = (idx >> 6) & 7;
    int bs = idx >> 9;
    if (bs >= BSc) return;
    int s = bs & (Sc - 1);

    const float* src = qkv + (size_t)bs * QKVF + Hc * Dc + kv * Dc;
    float c1 = src[i], c2 = src[i + 64];
    float p1 = 0.f, p2 = 0.f;
    if (s > 0) {
        const float* ps = src - QKVF;
        p1 = ps[i]; p2 = ps[i + 64];
    }
    float f0 = conv_k[kv], f1 = conv_k[KVc + kv];
    float x1 = c1 * f1 + p1 * f0;
    float x2 = c2 * f1 + p2 * f0;

    float pos = (float)positions[bs];
    float inv = 1.0f / powf(10000.0f, (float)i * (1.0f / 64.0f));
    float ang = pos * inv;
    float sn, cs;
    sincosf(ang, &sn, &cs);
    float y1 = x1 * cs - x2 * sn;
    float y2 = x2 * cs + x1 * sn;

    size_t o = ((size_t)bs * KVc + kv) * Dc;
    __nv_bfloat16 h1 = __float2bfloat16(y1);
    __nv_bfloat16 h2 = __float2bfloat16(y2);
    Kh[o + i]      = h1;
    Kh[o + i + 64] = h2;
    Kl[o + i]      = __float2bfloat16(y1 - __bfloat162float(h1));
    Kl[o + i + 64] = __float2bfloat16(y2 - __bfloat162float(h2));
}

// ---------------------------------------------------------------------------
// Smooth conv for V + transpose -> split bf16 Vt [b][kv][d][s]
// ---------------------------------------------------------------------------
__global__ void smooth_v_t_kernel(const float* __restrict__ qkv,
                                  const float* __restrict__ conv_v,
                                  __nv_bfloat16* __restrict__ Vth,
                                  __nv_bfloat16* __restrict__ Vtl)
{
    __shared__ float t[32][33];
    const int tx = threadIdx.x, ty = threadIdx.y;
    const int s0 = blockIdx.x * 32;
    const int d0 = blockIdx.y * 32;
    const int b  = blockIdx.z >> 3;
    const int kv = blockIdx.z & 7;

    const float f0 = conv_v[kv], f1 = conv_v[KVc + kv];
    const size_t voff = (size_t)(Hc + KVc) * Dc + kv * Dc + d0;

#pragma unroll
    for (int i = 0; i < 4; i++) {
        int sl = ty + i * 8;
        int s = s0 + sl;
        const float* src = qkv + (size_t)(b * Sc + s) * QKVF + voff;
        float cur = src[tx];
        float prv = (s > 0) ? src[tx - QKVF] : 0.f;
        t[sl][tx] = cur * f1 + prv * f0;
    }
    __syncthreads();
#pragma unroll
    for (int i = 0; i < 4; i++) {
        int dl = ty + i * 8;
        float v = t[tx][dl];
        __nv_bfloat16 hi = __float2bfloat16(v);
        size_t o = (((size_t)(b * KVc + kv)) * Dc + d0 + dl) * Sc + s0 + tx;
        Vth[o] = hi;
        Vtl[o] = __float2bfloat16(v - __bfloat162float(hi));
    }
}

// ---------------------------------------------------------------------------
// Register-resident windowed flash attention on HMMA, ldmatrix loads.
// ---------------------------------------------------------------------------
#define RQK  272                 // Q/K smem row stride bytes (128 bf16 + pad)
#define RPV  144                 // Vt smem row stride bytes  (64 bf16 + pad)

#define A_QH   0
#define A_QL   (A_QH + 128 * RQK)
#define A_ST0  (A_QL + 128 * RQK)
#define KV_STAGE (2 * 64 * RQK + 2 * 128 * RPV)
#define ST_KH  0
#define ST_KL  (64 * RQK)
#define ST_VH  (2 * 64 * RQK)
#define ST_VL  (2 * 64 * RQK + 128 * RPV)
#define ATTN_SMEM (A_ST0 + 2 * KV_STAGE)            // 212992

__global__ __launch_bounds__(256)
void attn_mma(const __nv_bfloat16* __restrict__ Qh, const __nv_bfloat16* __restrict__ Ql,
              const __nv_bfloat16* __restrict__ Kh, const __nv_bfloat16* __restrict__ Kl,
              const __nv_bfloat16* __restrict__ Vth, const __nv_bfloat16* __restrict__ Vtl,
              __nv_bfloat16* __restrict__ Oh, __nv_bfloat16* __restrict__ Ol)
{
    extern __shared__ char sm[];
    const uint32_t sb = smem_u32(sm);

    const int tid  = threadIdx.x;
    const int w    = tid >> 5;
    const int lane = tid & 31;
    const int g  = lane >> 2;
    const int tg = lane & 3;

    const int qt = blockIdx.x, h = blockIdx.y, b = blockIdx.z;
    const int q0 = qt * 128;
    const int kvh = h >> 2;
    const float scale = 0.08838834764831845f;

    // ldmatrix lane address components (B-pair x4 pattern)
    const uint32_t bmrow = (lane & 7) + (uint32_t)(lane >> 4) * 8;
    const uint32_t bcol  = ((lane >> 3) & 1) * 16;

    // ---- load Q tile (128 rows x 128 bf16, hi/lo) via cp.async ----
    {
        const size_t qbase = ((size_t)(b * Sc + q0) * Hc + h) * Dc;
#pragma unroll
        for (int hh = 0; hh < 8; hh++) {
            int idx = tid + hh * 256;
            int r = idx >> 4, u = idx & 15;
            const size_t go = qbase + (size_t)r * (Hc * Dc) + u * 8;
            cp16(sb + A_QH + r * RQK + u * 16, Qh + go);
            cp16(sb + A_QL + r * RQK + u * 16, Ql + go);
        }
    }

    const size_t kbase = ((size_t)b * Sc * KVc + kvh) * Dc;
    const size_t vbase = ((size_t)(b * KVc + kvh)) * Dc * Sc;
    auto load_kv = [&](int kt, int st) {
        const int k0 = kt * 64;
        const uint32_t stb = sb + A_ST0 + st * KV_STAGE;
#pragma unroll
        for (int hh = 0; hh < 4; hh++) {
            int idx = tid + hh * 256;
            int r = idx >> 4, u = idx & 15;
            const size_t go = kbase + (size_t)(k0 + r) * (KVc * Dc) + u * 8;
            cp16(stb + ST_KH + r * RQK + u * 16, Kh + go);
            cp16(stb + ST_KL + r * RQK + u * 16, Kl + go);
        }
#pragma unroll
        for (int hh = 0; hh < 4; hh++) {
            int idx = tid + hh * 256;
            int d = idx >> 3, u = idx & 7;
            const size_t go = vbase + (size_t)d * Sc + k0 + u * 8;
            cp16(stb + ST_VH + d * RPV + u * 16, Vth + go);
            cp16(stb + ST_VL + d * RPV + u * 16, Vtl + go);
        }
    };

    float m0 = -1e30f, m1 = -1e30f, l0 = 0.f, l1 = 0.f;
    float oacc[16][4];
#pragma unroll
    for (int nt = 0; nt < 16; nt++)
#pragma unroll
        for (int j = 0; j < 4; j++) oacc[nt][j] = 0.f;

    const int qw_lo = q0 + w * 16;
    const int qw_hi = qw_lo + 15;
    const int qi0 = qw_lo + g;
    const int qi1 = qi0 + 8;

    int kt_lo = 2 * qt - 8; if (kt_lo < 0) kt_lo = 0;
    const int kt_hi = 2 * qt + 1;

    load_kv(kt_lo, 0);
    CP_COMMIT();

    uint32_t qfh[8][4], qfl[8][4];

    for (int kt = kt_lo; kt <= kt_hi; kt++) {
        const int st = (kt - kt_lo) & 1;
        const int k0 = kt * 64;
        CP_WAIT0();
        __syncthreads();

        if (kt == kt_lo) {
            // one-time Q fragment preload (A-layout x4 ldmatrix)
            const uint32_t amrow = (lane & 7) + ((lane >> 3) & 1) * 8;
            const uint32_t acol  = (uint32_t)(lane >> 4) * 16;
#pragma unroll
            for (int ks = 0; ks < 8; ks++) {
                const uint32_t ar = (uint32_t)((w * 16 + amrow) * RQK) +
                                    (uint32_t)(ks * 32) + acol;
                ldsm_x4(qfh[ks], sb + A_QH + ar);
                ldsm_x4(qfl[ks], sb + A_QL + ar);
            }
        }

        if (kt < kt_hi) {
            load_kv(kt + 1, st ^ 1);
            CP_COMMIT();
        }

        if (k0 > qw_hi) continue;
        if (k0 + 575 <= qw_lo) continue;

        const uint32_t stb = sb + A_ST0 + st * KV_STAGE;
        const uint32_t khb = stb + ST_KH;
        const uint32_t vhb = stb + ST_VH;

        // ---- scores ----
        float sacc[8][4];
#pragma unroll
        for (int nt = 0; nt < 8; nt++)
#pragma unroll
            for (int j = 0; j < 4; j++) sacc[nt][j] = 0.f;

#pragma unroll
        for (int ks = 0; ks < 8; ks++) {
#pragma unroll
            for (int ntp = 0; ntp < 4; ntp++) {
                const uint32_t br = khb + (uint32_t)((ntp * 16 + bmrow) * RQK) +
                                    (uint32_t)(ks * 32) + bcol;
                uint32_t kh4[4], kl4[4];
                ldsm_x4(kh4, br);
                ldsm_x4(kl4, br + 64 * RQK);
                mma16816(sacc[2 * ntp],     qfh[ks], &kh4[0]);
                mma16816(sacc[2 * ntp],     qfh[ks], &kl4[0]);
                mma16816(sacc[2 * ntp],     qfl[ks], &kh4[0]);
                mma16816(sacc[2 * ntp + 1], qfh[ks], &kh4[2]);
                mma16816(sacc[2 * ntp + 1], qfh[ks], &kl4[2]);
                mma16816(sacc[2 * ntp + 1], qfl[ks], &kh4[2]);
            }
        }

        // ---- scale + mask ----
        const bool fully_valid = (k0 + 63 <= qw_lo) && (k0 >= qw_hi - (Wc - 1));
        if (fully_valid) {
#pragma unroll
            for (int nt = 0; nt < 8; nt++)
#pragma unroll
                for (int j = 0; j < 4; j++) sacc[nt][j] *= scale;
        } else {
#pragma unroll
            for (int nt = 0; nt < 8; nt++) {
                const int ki0 = k0 + nt * 8 + tg * 2, ki1 = ki0 + 1;
                bool m00 = (ki0 <= qi0) && (qi0 - ki0 < Wc);
                bool m01 = (ki1 <= qi0) && (qi0 - ki1 < Wc);
                bool m10 = (ki0 <= qi1) && (qi1 - ki0 < Wc);
                bool m11 = (ki1 <= qi1) && (qi1 - ki1 < Wc);
                sacc[nt][0] = m00 ? sacc[nt][0] * scale : -1e30f;
                sacc[nt][1] = m01 ? sacc[nt][1] * scale : -1e30f;
                sacc[nt][2] = m10 ? sacc[nt][2] * scale : -1e30f;
                sacc[nt][3] = m11 ? sacc[nt][3] * scale : -1e30f;
            }
        }

        // ---- row max via shfl ----
        float mx0 = -1e30f, mx1 = -1e30f;
#pragma unroll
        for (int nt = 0; nt < 8; nt++) {
            mx0 = fmaxf(mx0, fmaxf(sacc[nt][0], sacc[nt][1]));
            mx1 = fmaxf(mx1, fmaxf(sacc[nt][2], sacc[nt][3]));
        }
        mx0 = fmaxf(mx0, __shfl_xor_sync(0xffffffffu, mx0, 1));
        mx0 = fmaxf(mx0, __shfl_xor_sync(0xffffffffu, mx0, 2));
        mx1 = fmaxf(mx1, __shfl_xor_sync(0xffffffffu, mx1, 1));
        mx1 = fmaxf(mx1, __shfl_xor_sync(0xffffffffu, mx1, 2));

        const float mn0 = fmaxf(m0, mx0);
        const float mn1 = fmaxf(m1, mx1);
        const float f0 = __expf(m0 - mn0);
        const float f1 = __expf(m1 - mn1);
        m0 = mn0; m1 = mn1;

        // ---- exp + sums ----
        float s0 = 0.f, s1 = 0.f;
#pragma unroll
        for (int nt = 0; nt < 8; nt++) {
            float p0 = (sacc[nt][0] > -1e29f) ? __expf(sacc[nt][0] - mn0) : 0.f;
            float p1 = (sacc[nt][1] > -1e29f) ? __expf(sacc[nt][1] - mn0) : 0.f;
            float p2 = (sacc[nt][2] > -1e29f) ? __expf(sacc[nt][2] - mn1) : 0.f;
            float p3 = (sacc[nt][3] > -1e29f) ? __expf(sacc[nt][3] - mn1) : 0.f;
            sacc[nt][0] = p0; sacc[nt][1] = p1; sacc[nt][2] = p2; sacc[nt][3] = p3;
            s0 += p0 + p1; s1 += p2 + p3;
        }
        s0 += __shfl_xor_sync(0xffffffffu, s0, 1);
        s0 += __shfl_xor_sync(0xffffffffu, s0, 2);
        s1 += __shfl_xor_sync(0xffffffffu, s1, 1);
        s1 += __shfl_xor_sync(0xffffffffu, s1, 2);
        l0 = l0 * f0 + s0;
        l1 = l1 * f1 + s1;

#pragma unroll
        for (int nt = 0; nt < 16; nt++) {
            oacc[nt][0] *= f0; oacc[nt][1] *= f0;
            oacc[nt][2] *= f1; oacc[nt][3] *= f1;
        }

        // ---- PV ----
#pragma unroll
        for (int ks = 0; ks < 4; ks++) {
            uint32_t aph[4], apl[4];
            aph[0] = pack_hi2(sacc[2 * ks][0],     sacc[2 * ks][1]);
            aph[1] = pack_hi2(sacc[2 * ks][2],     sacc[2 * ks][3]);
            aph[2] = pack_hi2(sacc[2 * ks + 1][0], sacc[2 * ks + 1][1]);
            aph[3] = pack_hi2(sacc[2 * ks + 1][2], sacc[2 * ks + 1][3]);
            apl[0] = pack_lo2(sacc[2 * ks][0],     sacc[2 * ks][1]);
            apl[1] = pack_lo2(sacc[2 * ks][2],     sacc[2 * ks][3]);
            apl[2] = pack_lo2(sacc[2 * ks + 1][0], sacc[2 * ks + 1][1]);
            apl[3] = pack_lo2(sacc[2 * ks + 1][2], sacc[2 * ks + 1][3]);
#pragma unroll
            for (int ntp = 0; ntp < 8; ntp++) {
                const uint32_t br = vhb + (uint32_t)((ntp * 16 + bmrow) * RPV) +
                                    (uint32_t)(ks * 32) + bcol;
                uint32_t vh4[4], vl4[4];
                ldsm_x4(vh4, br);
                ldsm_x4(vl4, br + 128 * RPV);
                mma16816(oacc[2 * ntp],     aph, &vh4[0]);
                mma16816(oacc[2 * ntp],     aph, &vl4[0]);
                mma16816(oacc[2 * ntp],     apl, &vh4[0]);
                mma16816(oacc[2 * ntp + 1], aph, &vh4[2]);
                mma16816(oacc[2 * ntp + 1], aph, &vl4[2]);
                mma16816(oacc[2 * ntp + 1], apl, &vh4[2]);
            }
        }
    }

    // ---- epilogue ----
    {
        const float linv0 = 1.0f / l0;
        const float linv1 = 1.0f / l1;
        const size_t tok0 = (size_t)(b * Sc + qw_lo + g);
        const size_t tok1 = tok0 + 8;
#pragma unroll
        for (int nt = 0; nt < 16; nt++) {
            const int col = h * Dc + nt * 8 + tg * 2;
            float v00 = oacc[nt][0] * linv0, v01 = oacc[nt][1] * linv0;
            float v10 = oacc[nt][2] * linv1, v11 = oacc[nt][3] * linv1;
            ((uint32_t*)Oh)[(tok0 * HIDc + col) >> 1] = pack_hi2(v00, v01);
            ((uint32_t*)Ol)[(tok0 * HIDc + col) >> 1] = pack_lo2(v00, v01);
            ((uint32_t*)Oh)[(tok1 * HIDc + col) >> 1] = pack_hi2(v10, v11);
            ((uint32_t*)Ol)[(tok1 * HIDc + col) >> 1] = pack_lo2(v10, v11);
        }
    }
}

// ---------------------------------------------------------------------------
// Launch
// ---------------------------------------------------------------------------
extern "C" void kernel_launch(void* const* d_in, const int* in_sizes, int n_in,
                              void* d_out, int out_size)
{
    const float* hidden    = (const float*)d_in[0];
    const int*   positions = (const int*)d_in[1];
    const float* w_pack    = (const float*)d_in[2];
    const float* w_o       = (const float*)d_in[3];
    const float* conv_k    = (const float*)d_in[4];
    const float* conv_v    = (const float*)d_in[5];
    float* out = (float*)d_out;

    float* qkv;
    __nv_bfloat16 *qh, *ql, *kh, *kl, *vth, *vtl, *ah, *al, *bh, *bl;
    cudaGetSymbolAddress((void**)&qkv, g_qkv);
    cudaGetSymbolAddress((void**)&qh,  g_qh);
    cudaGetSymbolAddress((void**)&ql,  g_ql);
    cudaGetSymbolAddress((void**)&kh,  g_kh);
    cudaGetSymbolAddress((void**)&kl,  g_kl);
    cudaGetSymbolAddress((void**)&vth, g_vth);
    cudaGetSymbolAddress((void**)&vtl, g_vtl);
    cudaGetSymbolAddress((void**)&ah,  g_ah);
    cudaGetSymbolAddress((void**)&al,  g_al);
    cudaGetSymbolAddress((void**)&bh,  g_bh);
    cudaGetSymbolAddress((void**)&bl,  g_bl);

    cudaFuncSetAttribute(gemm_mma, cudaFuncAttributeMaxDynamicSharedMemorySize,
                         GEMM_SMEM);
    cudaFuncSetAttribute(attn_mma, cudaFuncAttributeMaxDynamicSharedMemorySize,
                         ATTN_SMEM);

    // ---- GEMM 1: qkv = hidden @ w_pack ----
    {
        int n4 = BSc * HIDc / 4;
        split_a_kernel<<<(n4 + 255) / 256, 256>>>(hidden, ah, al, n4);
        split_bt_kernel<<<dim3(QKVF / 32, HIDc / 32), dim3(32, 8)>>>(w_pack, bh, bl, HIDc, QKVF);
        dim3 g1(QKVF / 128, BSc / 128);
        gemm_mma<<<g1, 256, GEMM_SMEM>>>(ah, al, bh, bl, qkv, BSc, QKVF, HIDc);
    }

    // ---- elementwise prep (emit split bf16 operands) ----
    rope_q_kernel<<<(BSc * Hc * 64) / 256, 256>>>(qkv, positions, qh, ql);
    smooth_rope_k_kernel<<<(BSc * KVc * 64) / 256, 256>>>(qkv, positions, conv_k, kh, kl);
    smooth_v_t_kernel<<<dim3(Sc / 32, Dc / 32, Bc * KVc), dim3(32, 8)>>>(qkv, conv_v, vth, vtl);

    // prep GEMM2 weights early (independent of attention)
    split_bt_kernel<<<dim3(HIDc / 32, HIDc / 32), dim3(32, 8)>>>(w_o, bh, bl, HIDc, HIDc);

    // ---- register-resident windowed attention; writes split A for GEMM2 ----
    attn_mma<<<dim3(Sc / 128, Hc, Bc), 256, ATTN_SMEM>>>(qh, ql, kh, kl, vth, vtl, ah, al);

    // ---- GEMM 2: out = attn @ w_o ----
    {
        dim3 g2(HIDc / 128, BSc / 128);
        gemm_mma<<<g2, 256, GEMM_SMEM>>>(ah, al, bh, bl, out, BSc, HIDc, HIDc);
    }
}

// round 8
// speedup vs baseline: 4.3214x; 1.3876x over previous
#include <cuda_runtime.h>
#include <cuda_fp16.h>
#include <math.h>
#include <stdint.h>

// ---------------------------------------------------------------------------
// Problem constants
// ---------------------------------------------------------------------------
#define Bc    2
#define Sc    2048
#define HIDc  4096
#define Hc    32
#define KVc   8
#define Dc    128
#define Wc    512
#define BSc   (Bc * Sc)              // 4096
#define QKVF  ((Hc + 2 * KVc) * Dc)  // 6144

// global operand scale 2^10 (keeps fp16 residuals out of subnormal range)
#define SCF      1024.0f
#define INV_SC2  (1.0f / (SCF * SCF))

// ---------------------------------------------------------------------------
// Scratch (static device globals -- no allocation allowed)
// ---------------------------------------------------------------------------
__device__ float g_qkv[(size_t)BSc * QKVF];

__device__ __half g_qh[(size_t)BSc * Hc * Dc];          // roped Q hi (scaled)
__device__ __half g_ql[(size_t)BSc * Hc * Dc];          // roped Q lo
__device__ __half g_kh[(size_t)BSc * KVc * Dc];         // smoothed+roped K hi
__device__ __half g_vth[(size_t)Bc * KVc * Dc * Sc];    // V^T hi [b][kv][d][s]

__device__ __half g_ah[(size_t)BSc * HIDc];             // GEMM A hi [M,K]
__device__ __half g_al[(size_t)BSc * HIDc];             // GEMM A lo
__device__ __half g_bh[(size_t)QKVF * HIDc];            // GEMM B^T hi [N,K]

// ---------------------------------------------------------------------------
// Helpers
// ---------------------------------------------------------------------------
__device__ __forceinline__ uint32_t smem_u32(const void* p) {
    uint32_t a;
    asm("{ .reg .u64 t; cvta.to.shared.u64 t, %1; cvt.u32.u64 %0, t; }"
        : "=r"(a) : "l"(p));
    return a;
}
__device__ __forceinline__ void cp16(uint32_t smem, const void* gmem) {
    asm volatile("cp.async.cg.shared.global [%0], [%1], 16;"
                 :: "r"(smem), "l"(gmem));
}
#define CP_COMMIT() asm volatile("cp.async.commit_group;" ::: "memory")
#define CP_WAIT0()  asm volatile("cp.async.wait_group 0;" ::: "memory")

__device__ __forceinline__ void ldsm_x4(uint32_t* r, uint32_t addr) {
    asm volatile("ldmatrix.sync.aligned.m8n8.x4.shared.b16 {%0,%1,%2,%3}, [%4];"
                 : "=r"(r[0]), "=r"(r[1]), "=r"(r[2]), "=r"(r[3]) : "r"(addr));
}

// fp16 HMMA m16n8k16, fp32 accumulate
__device__ __forceinline__ void mma16816(float* d, const uint32_t* a,
                                         const uint32_t* b) {
    asm volatile(
        "mma.sync.aligned.m16n8k16.row.col.f32.f16.f16.f32 "
        "{%0,%1,%2,%3}, {%4,%5,%6,%7}, {%8,%9}, {%0,%1,%2,%3};"
        : "+f"(d[0]), "+f"(d[1]), "+f"(d[2]), "+f"(d[3])
        : "r"(a[0]), "r"(a[1]), "r"(a[2]), "r"(a[3]),
          "r"(b[0]), "r"(b[1]));
}

// pack two pre-scaled floats to fp16 hi / residual-lo pairs
__device__ __forceinline__ uint32_t packh_hi2(float x, float y) {
    __half2 h(__float2half_rn(x), __float2half_rn(y));
    return *(uint32_t*)&h;
}
__device__ __forceinline__ uint32_t packh_lo2(float x, float y) {
    float hx = __half2float(__float2half_rn(x));
    float hy = __half2float(__float2half_rn(y));
    __half2 l(__float2half_rn(x - hx), __float2half_rn(y - hy));
    return *(uint32_t*)&l;
}

// ---------------------------------------------------------------------------
// 2-term fp16 HMMA GEMM:  C[M,N] = (Ah+Al)[M,K] * Bh[K,N] / SC^2
// Ah/Al fp16 scaled [M,K]; BhT fp16 scaled [N,K]. C fp32 row-major.
// 2 CTAs/SM, ldmatrix fragment loads, cp.async double buffer.
// ---------------------------------------------------------------------------
#define GBK   32
#define SROW  40
#define MATB  (128 * SROW * 2)              // 10240 B
#define STAGEB (3 * MATB)                   // 30720 B (Ah, Al, Bh)
#define GEMM_SMEM (2 * STAGEB)              // 61440 B

__global__ __launch_bounds__(256, 2)
void gemm_mma(const __half* __restrict__ Ah,
              const __half* __restrict__ Al,
              const __half* __restrict__ Bh,
              float* __restrict__ C, int M, int N, int K)
{
    extern __shared__ char sm[];
    const uint32_t sb = smem_u32(sm);
    const int tid  = threadIdx.x;
    const int wid  = tid >> 5;
    const int lane = tid & 31;
    const int wm = wid & 3;
    const int wn = wid >> 2;
    const int g  = lane >> 2;
    const int tg = lane & 3;

    const int m0 = blockIdx.y * 128;
    const int n0 = blockIdx.x * 128;

    const uint32_t amrow = (lane & 7) + ((lane >> 3) & 1) * 8;
    const uint32_t acol  = (uint32_t)(lane >> 4) * 16;
    const uint32_t bmrow = (lane & 7) + (uint32_t)(lane >> 4) * 8;
    const uint32_t bcol  = ((lane >> 3) & 1) * 16;

    auto load_stage = [&](int k0, int st) {
        const uint32_t base = sb + st * STAGEB;
#pragma unroll
        for (int mat = 0; mat < 3; mat++) {
            const __half* src = (mat == 0) ? Ah : (mat == 1) ? Al : Bh;
            const int row0 = (mat < 2) ? m0 : n0;
#pragma unroll
            for (int hh = 0; hh < 2; hh++) {
                int unit = tid + hh * 256;
                int r = unit >> 2, u = unit & 3;
                const void* gp = src + (size_t)(row0 + r) * K + k0 + u * 8;
                cp16(base + mat * MATB + r * (SROW * 2) + u * 16, gp);
            }
        }
    };

    float acc[2][8][4];
#pragma unroll
    for (int mt = 0; mt < 2; mt++)
#pragma unroll
        for (int nt = 0; nt < 8; nt++)
#pragma unroll
            for (int j = 0; j < 4; j++) acc[mt][nt][j] = 0.f;

    const int NIT = K / GBK;
    load_stage(0, 0);
    CP_COMMIT();

    for (int it = 0; it < NIT; it++) {
        CP_WAIT0();
        __syncthreads();
        const int st = it & 1;
        if (it + 1 < NIT) {
            load_stage((it + 1) * GBK, st ^ 1);
            CP_COMMIT();
        }

        const uint32_t ahb = sb + st * STAGEB;
        const uint32_t bhb = ahb + 2 * MATB;

#pragma unroll
        for (int ks = 0; ks < 2; ks++) {
            uint32_t ah[2][4], al[2][4];
#pragma unroll
            for (int mt = 0; mt < 2; mt++) {
                const uint32_t ar = ahb +
                    (uint32_t)((wm * 32 + mt * 16 + amrow) * (SROW * 2)) +
                    (uint32_t)(ks * 32) + acol;
                ldsm_x4(ah[mt], ar);
                ldsm_x4(al[mt], ar + MATB);
            }
#pragma unroll
            for (int ntp = 0; ntp < 4; ntp++) {
                const uint32_t br = bhb +
                    (uint32_t)((wn * 64 + ntp * 16 + bmrow) * (SROW * 2)) +
                    (uint32_t)(ks * 32) + bcol;
                uint32_t bh4[4];
                ldsm_x4(bh4, br);
#pragma unroll
                for (int mt = 0; mt < 2; mt++) {
                    mma16816(acc[mt][2 * ntp],     ah[mt], &bh4[0]);
                    mma16816(acc[mt][2 * ntp],     al[mt], &bh4[0]);
                    mma16816(acc[mt][2 * ntp + 1], ah[mt], &bh4[2]);
                    mma16816(acc[mt][2 * ntp + 1], al[mt], &bh4[2]);
                }
            }
        }
    }

#pragma unroll
    for (int mt = 0; mt < 2; mt++) {
        const int r0 = m0 + wm * 32 + mt * 16 + g;
#pragma unroll
        for (int nt = 0; nt < 8; nt++) {
            const int cc = n0 + wn * 64 + nt * 8 + tg * 2;
            float2 w0 = make_float2(acc[mt][nt][0] * INV_SC2,
                                    acc[mt][nt][1] * INV_SC2);
            float2 w1 = make_float2(acc[mt][nt][2] * INV_SC2,
                                    acc[mt][nt][3] * INV_SC2);
            *(float2*)(C + (size_t)r0 * N + cc)       = w0;
            *(float2*)(C + (size_t)(r0 + 8) * N + cc) = w1;
        }
    }
}

// ---------------------------------------------------------------------------
// Split fp32 -> scaled fp16 (hi, lo)  (A operand prep for GEMM1)
// ---------------------------------------------------------------------------
__global__ void split_a_kernel(const float* __restrict__ X,
                               __half* __restrict__ Xh,
                               __half* __restrict__ Xl, int n4)
{
    int i = blockIdx.x * blockDim.x + threadIdx.x;
    if (i >= n4) return;
    float4 v = ((const float4*)X)[i];
    v.x *= SCF; v.y *= SCF; v.z *= SCF; v.w *= SCF;
    ((uint32_t*)Xh)[i * 2 + 0] = packh_hi2(v.x, v.y);
    ((uint32_t*)Xh)[i * 2 + 1] = packh_hi2(v.z, v.w);
    ((uint32_t*)Xl)[i * 2 + 0] = packh_lo2(v.x, v.y);
    ((uint32_t*)Xl)[i * 2 + 1] = packh_lo2(v.z, v.w);
}

// ---------------------------------------------------------------------------
// Transpose + scale: B fp32 [K,N] -> BhT fp16 scaled [N,K] (hi only)
// ---------------------------------------------------------------------------
__global__ void split_bt_kernel(const float* __restrict__ B,
                                __half* __restrict__ BhT, int K, int N)
{
    __shared__ float t[32][33];
    const int tx = threadIdx.x, ty = threadIdx.y;
    const int n0 = blockIdx.x * 32, k0 = blockIdx.y * 32;
#pragma unroll
    for (int i = 0; i < 4; i++) {
        int k = ty + i * 8;
        t[k][tx] = B[(size_t)(k0 + k) * N + n0 + tx] * SCF;
    }
    __syncthreads();
#pragma unroll
    for (int i = 0; i < 4; i++) {
        int n = ty + i * 8;
        BhT[(size_t)(n0 + n) * K + k0 + tx] = __float2half_rn(t[tx][n]);
    }
}

// ---------------------------------------------------------------------------
// RoPE for Q -> scaled fp16 hi/lo
// ---------------------------------------------------------------------------
__global__ void rope_q_kernel(const float* __restrict__ qkv,
                              const int* __restrict__ positions,
                              __half* __restrict__ Qh,
                              __half* __restrict__ Ql)
{
    int idx = blockIdx.x * blockDim.x + threadIdx.x;
    int i  = idx & 63;
    int h  = (idx >> 6) & 31;
    int bs = idx >> 11;
    if (bs >= BSc) return;

    const float* src = qkv + (size_t)bs * QKVF + h * Dc;
    float x1 = src[i], x2 = src[i + 64];
    float pos = (float)positions[bs];
    float inv = 1.0f / powf(10000.0f, (float)i * (1.0f / 64.0f));
    float ang = pos * inv;
    float sn, cs;
    sincosf(ang, &sn, &cs);
    float y1 = (x1 * cs - x2 * sn) * SCF;
    float y2 = (x2 * cs + x1 * sn) * SCF;

    size_t o = (size_t)bs * (Hc * Dc) + h * Dc;
    __half h1 = __float2half_rn(y1);
    __half h2 = __float2half_rn(y2);
    Qh[o + i]      = h1;
    Qh[o + i + 64] = h2;
    Ql[o + i]      = __float2half_rn(y1 - __half2float(h1));
    Ql[o + i + 64] = __float2half_rn(y2 - __half2float(h2));
}

// ---------------------------------------------------------------------------
// Smooth conv + RoPE for K -> scaled fp16 hi only
// ---------------------------------------------------------------------------
__global__ void smooth_rope_k_kernel(const float* __restrict__ qkv,
                                     const int* __restrict__ positions,
                                     const float* __restrict__ conv_k,
                                     __half* __restrict__ Kh)
{
    int idx = blockIdx.x * blockDim.x + threadIdx.x;
    int i  = idx & 63;
    int kv = (idx >> 6) & 7;
    int bs = idx >> 9;
    if (bs >= BSc) return;
    int s = bs & (Sc - 1);

    const float* src = qkv + (size_t)bs * QKVF + Hc * Dc + kv * Dc;
    float c1 = src[i], c2 = src[i + 64];
    float p1 = 0.f, p2 = 0.f;
    if (s > 0) {
        const float* ps = src - QKVF;
        p1 = ps[i]; p2 = ps[i + 64];
    }
    float f0 = conv_k[kv], f1 = conv_k[KVc + kv];
    float x1 = c1 * f1 + p1 * f0;
    float x2 = c2 * f1 + p2 * f0;

    float pos = (float)positions[bs];
    float inv = 1.0f / powf(10000.0f, (float)i * (1.0f / 64.0f));
    float ang = pos * inv;
    float sn, cs;
    sincosf(ang, &sn, &cs);

    size_t o = ((size_t)bs * KVc + kv) * Dc;
    Kh[o + i]      = __float2half_rn((x1 * cs - x2 * sn) * SCF);
    Kh[o + i + 64] = __float2half_rn((x2 * cs + x1 * sn) * SCF);
}

// ---------------------------------------------------------------------------
// Smooth conv for V + transpose -> scaled fp16 Vt hi [b][kv][d][s]
// ---------------------------------------------------------------------------
__global__ void smooth_v_t_kernel(const float* __restrict__ qkv,
                                  const float* __restrict__ conv_v,
                                  __half* __restrict__ Vth)
{
    __shared__ float t[32][33];
    const int tx = threadIdx.x, ty = threadIdx.y;
    const int s0 = blockIdx.x * 32;
    const int d0 = blockIdx.y * 32;
    const int b  = blockIdx.z >> 3;
    const int kv = blockIdx.z & 7;

    const float f0 = conv_v[kv], f1 = conv_v[KVc + kv];
    const size_t voff = (size_t)(Hc + KVc) * Dc + kv * Dc + d0;

#pragma unroll
    for (int i = 0; i < 4; i++) {
        int sl = ty + i * 8;
        int s = s0 + sl;
        const float* src = qkv + (size_t)(b * Sc + s) * QKVF + voff;
        float cur = src[tx];
        float prv = (s > 0) ? src[tx - QKVF] : 0.f;
        t[sl][tx] = (cur * f1 + prv * f0) * SCF;
    }
    __syncthreads();
#pragma unroll
    for (int i = 0; i < 4; i++) {
        int dl = ty + i * 8;
        size_t o = (((size_t)(b * KVc + kv)) * Dc + d0 + dl) * Sc + s0 + tx;
        Vth[o] = __float2half_rn(t[tx][dl]);
    }
}

// ---------------------------------------------------------------------------
// Register-resident windowed flash attention, fp16 2-term split.
// ---------------------------------------------------------------------------
#define RQK  272
#define RPV  144

#define A_QH   0
#define A_QL   (A_QH + 128 * RQK)
#define A_ST0  (A_QL + 128 * RQK)                   // 69632
#define KV_STAGE (64 * RQK + 128 * RPV)             // 35840
#define ST_KH  0
#define ST_VH  (64 * RQK)
#define ATTN_SMEM (A_ST0 + 2 * KV_STAGE)            // 141312

__global__ __launch_bounds__(256)
void attn_mma(const __half* __restrict__ Qh, const __half* __restrict__ Ql,
              const __half* __restrict__ Kh, const __half* __restrict__ Vth,
              __half* __restrict__ Oh, __half* __restrict__ Ol)
{
    extern __shared__ char sm[];
    const uint32_t sb = smem_u32(sm);

    const int tid  = threadIdx.x;
    const int w    = tid >> 5;
    const int lane = tid & 31;
    const int g  = lane >> 2;
    const int tg = lane & 3;

    const int qt = blockIdx.x, h = blockIdx.y, b = blockIdx.z;
    const int q0 = qt * 128;
    const int kvh = h >> 2;
    const float scale_eff = 0.08838834764831845f * INV_SC2;

    const uint32_t bmrow = (lane & 7) + (uint32_t)(lane >> 4) * 8;
    const uint32_t bcol  = ((lane >> 3) & 1) * 16;

    // ---- load Q tile (hi/lo) via cp.async ----
    {
        const size_t qbase = ((size_t)(b * Sc + q0) * Hc + h) * Dc;
#pragma unroll
        for (int hh = 0; hh < 8; hh++) {
            int idx = tid + hh * 256;
            int r = idx >> 4, u = idx & 15;
            const size_t go = qbase + (size_t)r * (Hc * Dc) + u * 8;
            cp16(sb + A_QH + r * RQK + u * 16, Qh + go);
            cp16(sb + A_QL + r * RQK + u * 16, Ql + go);
        }
    }

    const size_t kbase = ((size_t)b * Sc * KVc + kvh) * Dc;
    const size_t vbase = ((size_t)(b * KVc + kvh)) * Dc * Sc;
    auto load_kv = [&](int kt, int st) {
        const int k0 = kt * 64;
        const uint32_t stb = sb + A_ST0 + st * KV_STAGE;
#pragma unroll
        for (int hh = 0; hh < 4; hh++) {
            int idx = tid + hh * 256;
            int r = idx >> 4, u = idx & 15;
            const size_t go = kbase + (size_t)(k0 + r) * (KVc * Dc) + u * 8;
            cp16(stb + ST_KH + r * RQK + u * 16, Kh + go);
        }
#pragma unroll
        for (int hh = 0; hh < 4; hh++) {
            int idx = tid + hh * 256;
            int d = idx >> 3, u = idx & 7;
            const size_t go = vbase + (size_t)d * Sc + k0 + u * 8;
            cp16(stb + ST_VH + d * RPV + u * 16, Vth + go);
        }
    };

    float m0 = -1e30f, m1 = -1e30f, l0 = 0.f, l1 = 0.f;
    float oacc[16][4];
#pragma unroll
    for (int nt = 0; nt < 16; nt++)
#pragma unroll
        for (int j = 0; j < 4; j++) oacc[nt][j] = 0.f;

    const int qw_lo = q0 + w * 16;
    const int qw_hi = qw_lo + 15;
    const int qi0 = qw_lo + g;
    const int qi1 = qi0 + 8;

    int kt_lo = 2 * qt - 8; if (kt_lo < 0) kt_lo = 0;
    const int kt_hi = 2 * qt + 1;

    load_kv(kt_lo, 0);
    CP_COMMIT();

    uint32_t qfh[8][4], qfl[8][4];

    for (int kt = kt_lo; kt <= kt_hi; kt++) {
        const int st = (kt - kt_lo) & 1;
        const int k0 = kt * 64;
        CP_WAIT0();
        __syncthreads();

        if (kt == kt_lo) {
            const uint32_t amrow = (lane & 7) + ((lane >> 3) & 1) * 8;
            const uint32_t acol  = (uint32_t)(lane >> 4) * 16;
#pragma unroll
            for (int ks = 0; ks < 8; ks++) {
                const uint32_t ar = (uint32_t)((w * 16 + amrow) * RQK) +
                                    (uint32_t)(ks * 32) + acol;
                ldsm_x4(qfh[ks], sb + A_QH + ar);
                ldsm_x4(qfl[ks], sb + A_QL + ar);
            }
        }

        if (kt < kt_hi) {
            load_kv(kt + 1, st ^ 1);
            CP_COMMIT();
        }

        if (k0 > qw_hi) continue;
        if (k0 + 575 <= qw_lo) continue;

        const uint32_t stb = sb + A_ST0 + st * KV_STAGE;
        const uint32_t khb = stb + ST_KH;
        const uint32_t vhb = stb + ST_VH;

        // ---- scores: 2-term fp16 (Q residual kept, K residual dropped) ----
        float sacc[8][4];
#pragma unroll
        for (int nt = 0; nt < 8; nt++)
#pragma unroll
            for (int j = 0; j < 4; j++) sacc[nt][j] = 0.f;

#pragma unroll
        for (int ks = 0; ks < 8; ks++) {
#pragma unroll
            for (int ntp = 0; ntp < 4; ntp++) {
                const uint32_t br = khb + (uint32_t)((ntp * 16 + bmrow) * RQK) +
                                    (uint32_t)(ks * 32) + bcol;
                uint32_t kh4[4];
                ldsm_x4(kh4, br);
                mma16816(sacc[2 * ntp],     qfh[ks], &kh4[0]);
                mma16816(sacc[2 * ntp],     qfl[ks], &kh4[0]);
                mma16816(sacc[2 * ntp + 1], qfh[ks], &kh4[2]);
                mma16816(sacc[2 * ntp + 1], qfl[ks], &kh4[2]);
            }
        }

        // ---- scale + mask ----
        const bool fully_valid = (k0 + 63 <= qw_lo) && (k0 >= qw_hi - (Wc - 1));
        if (fully_valid) {
#pragma unroll
            for (int nt = 0; nt < 8; nt++)
#pragma unroll
                for (int j = 0; j < 4; j++) sacc[nt][j] *= scale_eff;
        } else {
#pragma unroll
            for (int nt = 0; nt < 8; nt++) {
                const int ki0 = k0 + nt * 8 + tg * 2, ki1 = ki0 + 1;
                bool m00 = (ki0 <= qi0) && (qi0 - ki0 < Wc);
                bool m01 = (ki1 <= qi0) && (qi0 - ki1 < Wc);
                bool m10 = (ki0 <= qi1) && (qi1 - ki0 < Wc);
                bool m11 = (ki1 <= qi1) && (qi1 - ki1 < Wc);
                sacc[nt][0] = m00 ? sacc[nt][0] * scale_eff : -1e30f;
                sacc[nt][1] = m01 ? sacc[nt][1] * scale_eff : -1e30f;
                sacc[nt][2] = m10 ? sacc[nt][2] * scale_eff : -1e30f;
                sacc[nt][3] = m11 ? sacc[nt][3] * scale_eff : -1e30f;
            }
        }

        // ---- row max via shfl ----
        float mx0 = -1e30f, mx1 = -1e30f;
#pragma unroll
        for (int nt = 0; nt < 8; nt++) {
            mx0 = fmaxf(mx0, fmaxf(sacc[nt][0], sacc[nt][1]));
            mx1 = fmaxf(mx1, fmaxf(sacc[nt][2], sacc[nt][3]));
        }
        mx0 = fmaxf(mx0, __shfl_xor_sync(0xffffffffu, mx0, 1));
        mx0 = fmaxf(mx0, __shfl_xor_sync(0xffffffffu, mx0, 2));
        mx1 = fmaxf(mx1, __shfl_xor_sync(0xffffffffu, mx1, 1));
        mx1 = fmaxf(mx1, __shfl_xor_sync(0xffffffffu, mx1, 2));

        const float mn0 = fmaxf(m0, mx0);
        const float mn1 = fmaxf(m1, mx1);
        const float f0 = __expf(m0 - mn0);
        const float f1 = __expf(m1 - mn1);
        m0 = mn0; m1 = mn1;

        // ---- exp + sums ----
        float s0 = 0.f, s1 = 0.f;
#pragma unroll
        for (int nt = 0; nt < 8; nt++) {
            float p0 = (sacc[nt][0] > -1e29f) ? __expf(sacc[nt][0] - mn0) : 0.f;
            float p1 = (sacc[nt][1] > -1e29f) ? __expf(sacc[nt][1] - mn0) : 0.f;
            float p2 = (sacc[nt][2] > -1e29f) ? __expf(sacc[nt][2] - mn1) : 0.f;
            float p3 = (sacc[nt][3] > -1e29f) ? __expf(sacc[nt][3] - mn1) : 0.f;
            sacc[nt][0] = p0; sacc[nt][1] = p1; sacc[nt][2] = p2; sacc[nt][3] = p3;
            s0 += p0 + p1; s1 += p2 + p3;
        }
        s0 += __shfl_xor_sync(0xffffffffu, s0, 1);
        s0 += __shfl_xor_sync(0xffffffffu, s0, 2);
        s1 += __shfl_xor_sync(0xffffffffu, s1, 1);
        s1 += __shfl_xor_sync(0xffffffffu, s1, 2);
        l0 = l0 * f0 + s0;
        l1 = l1 * f1 + s1;

#pragma unroll
        for (int nt = 0; nt < 16; nt++) {
            oacc[nt][0] *= f0; oacc[nt][1] *= f0;
            oacc[nt][2] *= f1; oacc[nt][3] *= f1;
        }

        // ---- PV: P split to scaled fp16 hi/lo in registers, V hi only ----
#pragma unroll
        for (int ks = 0; ks < 4; ks++) {
            uint32_t aph[4], apl[4];
            float c00 = sacc[2 * ks][0] * SCF,     c01 = sacc[2 * ks][1] * SCF;
            float c02 = sacc[2 * ks][2] * SCF,     c03 = sacc[2 * ks][3] * SCF;
            float c10 = sacc[2 * ks + 1][0] * SCF, c11 = sacc[2 * ks + 1][1] * SCF;
            float c12 = sacc[2 * ks + 1][2] * SCF, c13 = sacc[2 * ks + 1][3] * SCF;
            aph[0] = packh_hi2(c00, c01);
            aph[1] = packh_hi2(c02, c03);
            aph[2] = packh_hi2(c10, c11);
            aph[3] = packh_hi2(c12, c13);
            apl[0] = packh_lo2(c00, c01);
            apl[1] = packh_lo2(c02, c03);
            apl[2] = packh_lo2(c10, c11);
            apl[3] = packh_lo2(c12, c13);
#pragma unroll
            for (int ntp = 0; ntp < 8; ntp++) {
                const uint32_t br = vhb + (uint32_t)((ntp * 16 + bmrow) * RPV) +
                                    (uint32_t)(ks * 32) + bcol;
                uint32_t vh4[4];
                ldsm_x4(vh4, br);
                mma16816(oacc[2 * ntp],     aph, &vh4[0]);
                mma16816(oacc[2 * ntp],     apl, &vh4[0]);
                mma16816(oacc[2 * ntp + 1], aph, &vh4[2]);
                mma16816(oacc[2 * ntp + 1], apl, &vh4[2]);
            }
        }
    }

    // ---- epilogue: normalize, rescale to fp16 operand for GEMM2 ----
    {
        // oacc carries SC^2 (P*SC x V*SC); operand needs value*SC -> /SC
        const float linv0 = (1.0f / l0) * (1.0f / SCF);
        const float linv1 = (1.0f / l1) * (1.0f / SCF);
        const size_t tok0 = (size_t)(b * Sc + qw_lo + g);
        const size_t tok1 = tok0 + 8;
#pragma unroll
        for (int nt = 0; nt < 16; nt++) {
            const int col = h * Dc + nt * 8 + tg * 2;
            float v00 = oacc[nt][0] * linv0, v01 = oacc[nt][1] * linv0;
            float v10 = oacc[nt][2] * linv1, v11 = oacc[nt][3] * linv1;
            ((uint32_t*)Oh)[(tok0 * HIDc + col) >> 1] = packh_hi2(v00, v01);
            ((uint32_t*)Ol)[(tok0 * HIDc + col) >> 1] = packh_lo2(v00, v01);
            ((uint32_t*)Oh)[(tok1 * HIDc + col) >> 1] = packh_hi2(v10, v11);
            ((uint32_t*)Ol)[(tok1 * HIDc + col) >> 1] = packh_lo2(v10, v11);
        }
    }
}

// ---------------------------------------------------------------------------
// Launch
// ---------------------------------------------------------------------------
extern "C" void kernel_launch(void* const* d_in, const int* in_sizes, int n_in,
                              void* d_out, int out_size)
{
    const float* hidden    = (const float*)d_in[0];
    const int*   positions = (const int*)d_in[1];
    const float* w_pack    = (const float*)d_in[2];
    const float* w_o       = (const float*)d_in[3];
    const float* conv_k    = (const float*)d_in[4];
    const float* conv_v    = (const float*)d_in[5];
    float* out = (float*)d_out;

    float* qkv;
    __half *qh, *ql, *kh, *vth, *ah, *al, *bh;
    cudaGetSymbolAddress((void**)&qkv, g_qkv);
    cudaGetSymbolAddress((void**)&qh,  g_qh);
    cudaGetSymbolAddress((void**)&ql,  g_ql);
    cudaGetSymbolAddress((void**)&kh,  g_kh);
    cudaGetSymbolAddress((void**)&vth, g_vth);
    cudaGetSymbolAddress((void**)&ah,  g_ah);
    cudaGetSymbolAddress((void**)&al,  g_al);
    cudaGetSymbolAddress((void**)&bh,  g_bh);

    cudaFuncSetAttribute(gemm_mma, cudaFuncAttributeMaxDynamicSharedMemorySize,
                         GEMM_SMEM);
    cudaFuncSetAttribute(attn_mma, cudaFuncAttributeMaxDynamicSharedMemorySize,
                         ATTN_SMEM);

    // ---- GEMM 1: qkv = hidden @ w_pack ----
    {
        int n4 = BSc * HIDc / 4;
        split_a_kernel<<<(n4 + 255) / 256, 256>>>(hidden, ah, al, n4);
        split_bt_kernel<<<dim3(QKVF / 32, HIDc / 32), dim3(32, 8)>>>(w_pack, bh, HIDc, QKVF);
        dim3 g1(QKVF / 128, BSc / 128);
        gemm_mma<<<g1, 256, GEMM_SMEM>>>(ah, al, bh, qkv, BSc, QKVF, HIDc);
    }

    // ---- elementwise prep (emit scaled fp16 operands) ----
    rope_q_kernel<<<(BSc * Hc * 64) / 256, 256>>>(qkv, positions, qh, ql);
    smooth_rope_k_kernel<<<(BSc * KVc * 64) / 256, 256>>>(qkv, positions, conv_k, kh);
    smooth_v_t_kernel<<<dim3(Sc / 32, Dc / 32, Bc * KVc), dim3(32, 8)>>>(qkv, conv_v, vth);

    // prep GEMM2 weights (hi only)
    split_bt_kernel<<<dim3(HIDc / 32, HIDc / 32), dim3(32, 8)>>>(w_o, bh, HIDc, HIDc);

    // ---- windowed attention; writes scaled fp16 A for GEMM2 ----
    attn_mma<<<dim3(Sc / 128, Hc, Bc), 256, ATTN_SMEM>>>(qh, ql, kh, vth, ah, al);

    // ---- GEMM 2: out = attn @ w_o ----
    {
        dim3 g2(HIDc / 128, BSc / 128);
        gemm_mma<<<g2, 256, GEMM_SMEM>>>(ah, al, bh, out, BSc, HIDc, HIDc);
    }
}